// round 8
// baseline (speedup 1.0000x reference)
#include <cuda_runtime.h>
#include <math.h>

#define BB 32
#define SS 512
#define HH 768
#define MC 128
#define EPSF 1e-8f
#define TK 16

// ---------------- scratch (static device memory; no allocs) ----------------
__device__ int   g_kidx[BB*MC];
__device__ int   g_vidx[BB*MC];
__device__ float g_kbox[BB*MC*4];
__device__ float g_vbox[BB*MC*4];
__device__ float g_u[BB*MC*HH];
__device__ float g_biaf8[8][BB*MC*MC];
__device__ float g_Wc2[HH*HH];   // Wbil @ Wv^T
__device__ float g_M[HH*HH];     // Wk @ Wc2
__device__ float g_s1[HH];       // bk @ Wbil
__device__ float g_r[HH];        // Wbil @ bv
__device__ float g_q[HH];        // Wv @ s1
__device__ float g_p[HH];        // Wk @ r
__device__ float g_c[1];         // s1 . bv
__device__ float g_rowk[BB*MC];
__device__ float g_rowv[BB*MC];
__device__ float g_W2f[64*16];
__device__ float g_b2f[16];

// -------- 1+2) conf (inline) + exact top-128 of 512 via bitonic sort ------
__global__ void topk_kernel(const float* __restrict__ logits,
                            const int* __restrict__ mask,
                            const float* __restrict__ bboxes,
                            float* __restrict__ out) {
    int b = blockIdx.x;
    int which = blockIdx.y;   // 0 = key, 1 = val
    __shared__ float sc[512];
    __shared__ int   si[512];
    int tid = threadIdx.x;

    {   // inline confidence
        int t = b * SS + tid;
        float l0 = logits[3*t+0], l1 = logits[3*t+1], l2 = logits[3*t+2];
        int pred = 0; float best = l0;
        if (l1 > best) { pred = 1; best = l1; }
        if (l2 > best) { pred = 2; best = l2; }
        float e0 = expf(l0 - best), e1 = expf(l1 - best), e2 = expf(l2 - best);
        float inv = 1.0f / (e0 + e1 + e2);
        bool valid = (mask[t] == 1);
        float conf;
        if (which == 0) conf = (pred == 1 && valid) ? e1 * inv : -INFINITY;
        else            conf = (pred == 2 && valid) ? e2 * inv : -INFINITY;
        sc[tid] = conf; si[tid] = tid;
    }

    for (int k = 2; k <= 512; k <<= 1) {
        for (int j = k >> 1; j > 0; j >>= 1) {
            __syncthreads();
            int ixj = tid ^ j;
            if (ixj > tid) {
                float c1 = sc[tid], c2 = sc[ixj];
                int   i1 = si[tid], i2 = si[ixj];
                bool b2 = (c2 > c1) || (c2 == c1 && i2 < i1);
                bool doswap = ((tid & k) == 0) ? b2 : !b2;
                if (doswap) {
                    sc[tid] = c2; si[tid] = i2;
                    sc[ixj] = c1; si[ixj] = i1;
                }
            }
        }
    }
    __syncthreads();

    if (tid < MC) {
        int   idx = si[tid];
        float cf  = sc[tid];
        int*   gi = (which == 0) ? g_kidx : g_vidx;
        float* gb = (which == 0) ? g_kbox : g_vbox;
        gi[b * MC + tid] = idx;
        const float* src = bboxes + ((long long)b * SS + idx) * 4;
        float* dst = gb + (b * MC + tid) * 4;
        dst[0] = src[0]; dst[1] = src[1]; dst[2] = src[2]; dst[3] = src[3];
        long long base = (long long)BB * MC * MC;            // 524288
        float vf = (cf != -INFINITY) ? 1.0f : 0.0f;
        out[base + (long long)which * (BB * MC) + b * MC + tid] = vf;
        out[base + 2LL * (BB * MC) + (long long)which * (BB * MC) + b * MC + tid] = (float)idx;
    }
}

// ---------------- setupA: s1 = bk @ Wbil ; r = Wbil @ bv -------------------
__global__ void setupA(const float* __restrict__ bk,
                       const float* __restrict__ Wbil,
                       const float* __restrict__ bv) {
    int bx = blockIdx.x, tid = threadIdx.x;
    if (bx < 3) {
        int j = bx * 256 + tid;
        float s = 0.f;
        for (int h = 0; h < HH; h++) s = fmaf(bk[h], Wbil[h * HH + j], s);
        g_s1[j] = s;
    } else {
        int row = (bx - 3) * 8 + (tid >> 5);
        int lane = tid & 31;
        const float* rp = Wbil + (long long)row * HH;
        float s = 0.f;
        #pragma unroll 4
        for (int cdx = lane; cdx < HH; cdx += 32) s = fmaf(rp[cdx], bv[cdx], s);
        #pragma unroll
        for (int o = 16; o; o >>= 1) s += __shfl_xor_sync(0xffffffffu, s, o);
        if (lane == 0) g_r[row] = s;
    }
}

// -------- setupB: q = Wv@s1 ; p = Wk@r ; c = s1.bv ; MLP fold --------------
__global__ void setupB(const float* __restrict__ Wv, const float* __restrict__ Wk,
                       const float* __restrict__ bv,
                       const float* __restrict__ Ws2, const float* __restrict__ bs2,
                       const float* __restrict__ Wf1, const float* __restrict__ bf1) {
    int bx = blockIdx.x, tid = threadIdx.x;
    if (bx < 192) {
        const float* A   = (bx < 96) ? Wv : Wk;
        const float* x   = (bx < 96) ? g_s1 : g_r;
        float* outv      = (bx < 96) ? g_q : g_p;
        int row = ((bx < 96) ? bx : bx - 96) * 8 + (tid >> 5);
        int lane = tid & 31;
        const float* rp = A + (long long)row * HH;
        float s = 0.f;
        #pragma unroll 4
        for (int cdx = lane; cdx < HH; cdx += 32) s = fmaf(rp[cdx], x[cdx], s);
        #pragma unroll
        for (int o = 16; o; o >>= 1) s += __shfl_xor_sync(0xffffffffu, s, o);
        if (lane == 0) outv[row] = s;
    } else {
        #pragma unroll
        for (int e = 0; e < 4; e++) {
            int o = tid * 4 + e;
            if (o < 1024) {
                int u = o >> 4, t = o & 15;
                float s = 0.f;
                #pragma unroll
                for (int s2 = 0; s2 < 32; s2++)
                    s = fmaf(Ws2[u * 32 + s2], Wf1[(s2 + 1) * 16 + t], s);
                g_W2f[o] = s;
            }
        }
        if (tid < 16) {
            float s = bf1[tid];
            #pragma unroll
            for (int s2 = 0; s2 < 32; s2++)
                s = fmaf(bs2[s2], Wf1[(s2 + 1) * 16 + tid], s);
            g_b2f[tid] = s;
        }
        __shared__ float red[256];
        float s = 0.f;
        for (int g = tid; g < HH; g += 256) s = fmaf(g_s1[g], bv[g], s);
        red[tid] = s; __syncthreads();
        for (int o = 128; o; o >>= 1) { if (tid < o) red[tid] += red[tid + o]; __syncthreads(); }
        if (tid == 0) g_c[0] = red[0];
    }
}

// ------ NT split-K x8 atomic: Wc2 = Wbil @ Wv^T (8x8, 256 thr) ------------
__global__ __launch_bounds__(256)
void nt_atomic(const float* __restrict__ A, const float* __restrict__ B,
               float* __restrict__ C) {
    __shared__ __align__(16) float As[2][TK][132];
    __shared__ __align__(16) float Bs[2][TK][132];
    const int nslabs = 6;
    int tid = threadIdx.x;
    int tx = tid & 15, ty = tid >> 4;
    int m0 = blockIdx.y * 128, n0 = blockIdx.x * 128;
    int kbase = blockIdx.z * nslabs * TK;
    int ar0 = tid >> 2, ak = (tid & 3) * 4, ar1 = ar0 + 64;

    float4 a0v, a1v, b0v, b1v;
#define LOAD(K0) do { \
        a0v = *(const float4*)(A + (long long)(m0 + ar0) * HH + (K0) + ak); \
        a1v = *(const float4*)(A + (long long)(m0 + ar1) * HH + (K0) + ak); \
        b0v = *(const float4*)(B + (long long)(n0 + ar0) * HH + (K0) + ak); \
        b1v = *(const float4*)(B + (long long)(n0 + ar1) * HH + (K0) + ak); \
    } while (0)
#define STORE(BUF) do { \
        As[BUF][ak+0][ar0] = a0v.x; As[BUF][ak+1][ar0] = a0v.y; \
        As[BUF][ak+2][ar0] = a0v.z; As[BUF][ak+3][ar0] = a0v.w; \
        As[BUF][ak+0][ar1] = a1v.x; As[BUF][ak+1][ar1] = a1v.y; \
        As[BUF][ak+2][ar1] = a1v.z; As[BUF][ak+3][ar1] = a1v.w; \
        Bs[BUF][ak+0][ar0] = b0v.x; Bs[BUF][ak+1][ar0] = b0v.y; \
        Bs[BUF][ak+2][ar0] = b0v.z; Bs[BUF][ak+3][ar0] = b0v.w; \
        Bs[BUF][ak+0][ar1] = b1v.x; Bs[BUF][ak+1][ar1] = b1v.y; \
        Bs[BUF][ak+2][ar1] = b1v.z; Bs[BUF][ak+3][ar1] = b1v.w; \
    } while (0)

    float acc[8][8];
    #pragma unroll
    for (int i = 0; i < 8; i++)
        #pragma unroll
        for (int j = 0; j < 8; j++) acc[i][j] = 0.f;

    LOAD(kbase); STORE(0); __syncthreads();
    for (int kt = 0; kt < nslabs; kt++) {
        int cur = kt & 1;
        if (kt + 1 < nslabs) LOAD(kbase + (kt + 1) * TK);
        #pragma unroll
        for (int kk = 0; kk < TK; kk++) {
            float a[8], b[8];
            *(float4*)(a)     = *(const float4*)&As[cur][kk][ty * 8];
            *(float4*)(a + 4) = *(const float4*)&As[cur][kk][ty * 8 + 4];
            *(float4*)(b)     = *(const float4*)&Bs[cur][kk][tx * 8];
            *(float4*)(b + 4) = *(const float4*)&Bs[cur][kk][tx * 8 + 4];
            #pragma unroll
            for (int i = 0; i < 8; i++)
                #pragma unroll
                for (int j = 0; j < 8; j++)
                    acc[i][j] = fmaf(a[i], b[j], acc[i][j]);
        }
        if (kt + 1 < nslabs) { STORE(cur ^ 1); __syncthreads(); }
    }
    #pragma unroll
    for (int i = 0; i < 8; i++)
        #pragma unroll
        for (int j = 0; j < 8; j++)
            atomicAdd(&C[(long long)(m0 + ty * 8 + i) * HH + n0 + tx * 8 + j], acc[i][j]);
#undef LOAD
#undef STORE
}

// ------ NN split-K x8 atomic: M = Wk @ Wc2 (8x8, 256 thr) ------------------
__global__ __launch_bounds__(256)
void nn_atomic(const float* __restrict__ A, const float* __restrict__ B,
               float* __restrict__ C) {
    __shared__ __align__(16) float As[2][TK][132];
    __shared__ __align__(16) float Bs[2][TK][128];
    const int nslabs = 6;
    int tid = threadIdx.x;
    int tx = tid & 15, ty = tid >> 4;
    int m0 = blockIdx.y * 128, c0 = blockIdx.x * 128;
    int kbase = blockIdx.z * nslabs * TK;
    int ar0 = tid >> 2, ak = (tid & 3) * 4, ar1 = ar0 + 64;
    int bk0 = tid >> 5, bcc = (tid & 31) * 4, bk1 = bk0 + 8;

    float4 a0v, a1v, b0v, b1v;
#define LOAD(K0) do { \
        a0v = *(const float4*)(A + (long long)(m0 + ar0) * HH + (K0) + ak); \
        a1v = *(const float4*)(A + (long long)(m0 + ar1) * HH + (K0) + ak); \
        b0v = *(const float4*)(B + (long long)((K0) + bk0) * HH + c0 + bcc); \
        b1v = *(const float4*)(B + (long long)((K0) + bk1) * HH + c0 + bcc); \
    } while (0)
#define STORE(BUF) do { \
        As[BUF][ak+0][ar0] = a0v.x; As[BUF][ak+1][ar0] = a0v.y; \
        As[BUF][ak+2][ar0] = a0v.z; As[BUF][ak+3][ar0] = a0v.w; \
        As[BUF][ak+0][ar1] = a1v.x; As[BUF][ak+1][ar1] = a1v.y; \
        As[BUF][ak+2][ar1] = a1v.z; As[BUF][ak+3][ar1] = a1v.w; \
        *(float4*)&Bs[BUF][bk0][bcc] = b0v; \
        *(float4*)&Bs[BUF][bk1][bcc] = b1v; \
    } while (0)

    float acc[8][8];
    #pragma unroll
    for (int i = 0; i < 8; i++)
        #pragma unroll
        for (int j = 0; j < 8; j++) acc[i][j] = 0.f;

    LOAD(kbase); STORE(0); __syncthreads();
    for (int kt = 0; kt < nslabs; kt++) {
        int cur = kt & 1;
        if (kt + 1 < nslabs) LOAD(kbase + (kt + 1) * TK);
        #pragma unroll
        for (int kk = 0; kk < TK; kk++) {
            float a[8], b[8];
            *(float4*)(a)     = *(const float4*)&As[cur][kk][ty * 8];
            *(float4*)(a + 4) = *(const float4*)&As[cur][kk][ty * 8 + 4];
            *(float4*)(b)     = *(const float4*)&Bs[cur][kk][tx * 8];
            *(float4*)(b + 4) = *(const float4*)&Bs[cur][kk][tx * 8 + 4];
            #pragma unroll
            for (int i = 0; i < 8; i++)
                #pragma unroll
                for (int j = 0; j < 8; j++)
                    acc[i][j] = fmaf(a[i], b[j], acc[i][j]);
        }
        if (kt + 1 < nslabs) { STORE(cur ^ 1); __syncthreads(); }
    }
    #pragma unroll
    for (int i = 0; i < 8; i++)
        #pragma unroll
        for (int j = 0; j < 8; j++)
            atomicAdd(&C[(long long)(m0 + ty * 8 + i) * HH + c0 + tx * 8 + j], acc[i][j]);
#undef LOAD
#undef STORE
}

// --------- u = Gk(seq) @ M : 64x128 tile, 4x8/thread, 384 blocks -----------
__global__ __launch_bounds__(256)
void u_gemm(const float* __restrict__ A, const float* __restrict__ Bm) {
    __shared__ __align__(16) float As[2][TK][68];
    __shared__ __align__(16) float Bs[2][TK][128];
    __shared__ long long rowbase[64];

    int tid = threadIdx.x;
    int tx = tid & 15, ty = tid >> 4;
    int m0 = blockIdx.y * 64, c0 = blockIdx.x * 128;

    if (tid < 64) {
        int m = m0 + tid;
        rowbase[tid] = ((long long)(m >> 7) * SS + g_kidx[m]) * HH;
    }
    __syncthreads();

    int ar = tid >> 2, ak = (tid & 3) * 4;       // 64 rows x 16 k
    int bk0 = tid >> 5, bcc = (tid & 31) * 4, bk1 = bk0 + 8;
    long long ra = rowbase[ar];

    float4 av, b0v, b1v;
#define LOAD(K0) do { \
        av  = *(const float4*)(A + ra + (K0) + ak); \
        b0v = *(const float4*)(Bm + (long long)((K0) + bk0) * HH + c0 + bcc); \
        b1v = *(const float4*)(Bm + (long long)((K0) + bk1) * HH + c0 + bcc); \
    } while (0)
#define STORE(BUF) do { \
        As[BUF][ak+0][ar] = av.x; As[BUF][ak+1][ar] = av.y; \
        As[BUF][ak+2][ar] = av.z; As[BUF][ak+3][ar] = av.w; \
        *(float4*)&Bs[BUF][bk0][bcc] = b0v; \
        *(float4*)&Bs[BUF][bk1][bcc] = b1v; \
    } while (0)

    float acc[4][8];
    #pragma unroll
    for (int i = 0; i < 4; i++)
        #pragma unroll
        for (int j = 0; j < 8; j++) acc[i][j] = 0.0f;

    LOAD(0); STORE(0); __syncthreads();

    const int NT = HH / TK;   // 48
    for (int kt = 0; kt < NT; kt++) {
        int cur = kt & 1;
        if (kt + 1 < NT) LOAD((kt + 1) * TK);
        #pragma unroll
        for (int kk = 0; kk < TK; kk++) {
            float a[4], b[8];
            *(float4*)a       = *(const float4*)&As[cur][kk][ty * 4];
            *(float4*)b       = *(const float4*)&Bs[cur][kk][tx * 8];
            *(float4*)(b + 4) = *(const float4*)&Bs[cur][kk][tx * 8 + 4];
            #pragma unroll
            for (int i = 0; i < 4; i++)
                #pragma unroll
                for (int j = 0; j < 8; j++)
                    acc[i][j] = fmaf(a[i], b[j], acc[i][j]);
        }
        if (kt + 1 < NT) { STORE(cur ^ 1); __syncthreads(); }
    }

    #pragma unroll
    for (int i = 0; i < 4; i++) {
        long long r = m0 + ty * 4 + i;
        *(float4*)&g_u[r * HH + c0 + tx * 8]     = *(float4*)&acc[i][0];
        *(float4*)&g_u[r * HH + c0 + tx * 8 + 4] = *(float4*)&acc[i][4];
    }
#undef LOAD
#undef STORE
}

// -------- rowk = Gk.p ; rowv = Gv.q + c  (warp per row) --------------------
__global__ void growdot_kernel(const float* __restrict__ seq) {
    int r = blockIdx.x * 8 + (threadIdx.x >> 5);
    int lane = threadIdx.x & 31;
    int which = blockIdx.y;
    const int* gidx = which ? g_vidx : g_kidx;
    const float* vec = which ? g_q : g_p;
    const float* row = seq + ((long long)(r >> 7) * SS + gidx[r]) * HH;
    float s = 0.f;
    #pragma unroll 4
    for (int cdx = lane; cdx < HH; cdx += 32) s = fmaf(row[cdx], vec[cdx], s);
    #pragma unroll
    for (int o = 16; o; o >>= 1) s += __shfl_xor_sync(0xffffffffu, s, o);
    if (lane == 0) {
        if (which) g_rowv[r] = s + g_c[0];
        else       g_rowk[r] = s;
    }
}

// -- biaffine: biaf8[s][b,i,j] = u[b,i,ks].Gv_seq[b,j,ks] (8 splits, 8x8) ---
__global__ __launch_bounds__(256)
void biaf_splitk(const float* __restrict__ seq) {
    __shared__ __align__(16) float As[2][TK][132];
    __shared__ __align__(16) float Bs[2][TK][132];
    __shared__ long long vrowbase[128];
    const int nslabs = 6;
    int b = blockIdx.y;
    int split = blockIdx.x;
    int kbase = split * nslabs * TK;
    int tid = threadIdx.x;
    int tx = tid & 15, ty = tid >> 4;

    const float* A = g_u + (long long)b * MC * HH;

    if (tid < 128)
        vrowbase[tid] = ((long long)b * SS + g_vidx[b * MC + tid]) * HH;
    __syncthreads();

    int ar0 = tid >> 2, ak = (tid & 3) * 4, ar1 = ar0 + 64;
    long long vb0 = vrowbase[ar0];
    long long vb1 = vrowbase[ar1];

    float4 a0v, a1v, b0v, b1v;
#define LOAD(K0) do { \
        a0v = *(const float4*)(A + (long long)ar0 * HH + (K0) + ak); \
        a1v = *(const float4*)(A + (long long)ar1 * HH + (K0) + ak); \
        b0v = *(const float4*)(seq + vb0 + (K0) + ak); \
        b1v = *(const float4*)(seq + vb1 + (K0) + ak); \
    } while (0)
#define STORE(BUF) do { \
        As[BUF][ak+0][ar0] = a0v.x; As[BUF][ak+1][ar0] = a0v.y; \
        As[BUF][ak+2][ar0] = a0v.z; As[BUF][ak+3][ar0] = a0v.w; \
        As[BUF][ak+0][ar1] = a1v.x; As[BUF][ak+1][ar1] = a1v.y; \
        As[BUF][ak+2][ar1] = a1v.z; As[BUF][ak+3][ar1] = a1v.w; \
        Bs[BUF][ak+0][ar0] = b0v.x; Bs[BUF][ak+1][ar0] = b0v.y; \
        Bs[BUF][ak+2][ar0] = b0v.z; Bs[BUF][ak+3][ar0] = b0v.w; \
        Bs[BUF][ak+0][ar1] = b1v.x; Bs[BUF][ak+1][ar1] = b1v.y; \
        Bs[BUF][ak+2][ar1] = b1v.z; Bs[BUF][ak+3][ar1] = b1v.w; \
    } while (0)

    float acc[8][8];
    #pragma unroll
    for (int i = 0; i < 8; i++)
        #pragma unroll
        for (int j = 0; j < 8; j++) acc[i][j] = 0.f;

    LOAD(kbase); STORE(0); __syncthreads();
    for (int kt = 0; kt < nslabs; kt++) {
        int cur = kt & 1;
        if (kt + 1 < nslabs) LOAD(kbase + (kt + 1) * TK);
        #pragma unroll
        for (int kk = 0; kk < TK; kk++) {
            float a[8], bb[8];
            *(float4*)(a)      = *(const float4*)&As[cur][kk][ty * 8];
            *(float4*)(a + 4)  = *(const float4*)&As[cur][kk][ty * 8 + 4];
            *(float4*)(bb)     = *(const float4*)&Bs[cur][kk][tx * 8];
            *(float4*)(bb + 4) = *(const float4*)&Bs[cur][kk][tx * 8 + 4];
            #pragma unroll
            for (int i = 0; i < 8; i++)
                #pragma unroll
                for (int j = 0; j < 8; j++)
                    acc[i][j] = fmaf(a[i], bb[j], acc[i][j]);
        }
        if (kt + 1 < nslabs) { STORE(cur ^ 1); __syncthreads(); }
    }

    float* dst = g_biaf8[split] + (long long)b * (MC * MC);
    #pragma unroll
    for (int i = 0; i < 8; i++) {
        int r = ty * 8 + i;
        *(float4*)&dst[r * MC + tx * 8]     = *(float4*)&acc[i][0];
        *(float4*)&dst[r * MC + tx * 8 + 4] = *(float4*)&acc[i][4];
    }
#undef LOAD
#undef STORE
}

// ------- spatial features + folded MLP, 2 key rows per 256-thr block ------
__global__ __launch_bounds__(256)
void pair_kernel(float* __restrict__ out,
                 const float* __restrict__ Ws1, const float* __restrict__ bs1,
                 const float* __restrict__ Wf1,
                 const float* __restrict__ Wf2, const float* __restrict__ bf2,
                 const float* __restrict__ bbilp) {
    __shared__ float sW1[8 * 64], sb1[64];
    __shared__ float sW2f[64 * 16], sb2f[16];
    __shared__ float sF0[16], sF2[16];
    __shared__ float sbf2, sbil;
    __shared__ float kb[2][4];
    __shared__ float srowk[2];

    int b = blockIdx.y;
    int j = threadIdx.x;
    int ty = j >> 7;            // key row within block
    int jj = j & 127;           // value index
    int i = blockIdx.x * 2 + ty;

    for (int t = j; t < 512;  t += 256) sW1[t] = Ws1[t];
    for (int t = j; t < 1024; t += 256) sW2f[t] = g_W2f[t];
    if (j < 64) sb1[j] = bs1[j];
    if (j < 16) { sb2f[j] = g_b2f[j]; sF0[j] = Wf1[j]; sF2[j] = Wf2[j]; }
    if (j == 0) { sbf2 = bf2[0]; sbil = bbilp[0]; }
    if (j < 2)  srowk[j] = g_rowk[b * MC + blockIdx.x * 2 + j];
    if (j < 8)  kb[j >> 2][j & 3] =
        g_kbox[(b * MC + blockIdx.x * 2 + (j >> 2)) * 4 + (j & 3)];
    __syncthreads();

    float vx1 = g_vbox[(b * MC + jj) * 4 + 0];
    float vy1 = g_vbox[(b * MC + jj) * 4 + 1];
    float vx2 = g_vbox[(b * MC + jj) * 4 + 2];
    float vy2 = g_vbox[(b * MC + jj) * 4 + 3];
    float kx1 = kb[ty][0], ky1 = kb[ty][1], kx2 = kb[ty][2], ky2 = kb[ty][3];

    float kcx = (kx1 + kx2) * 0.5f, kcy = (ky1 + ky2) * 0.5f;
    float vcx = (vx1 + vx2) * 0.5f, vcy = (vy1 + vy2) * 0.5f;
    float dx = vcx - kcx, dy = vcy - kcy;
    float dist  = sqrtf(dx * dx + dy * dy + EPSF);
    float angle = atan2f(dy, dx);
    float kh = ky2 - ky1, kw = kx2 - kx1;
    float vh = vy2 - vy1, vw = vx2 - vx1;
    float h_ov = fmaxf(fminf(ky2, vy2) - fmaxf(ky1, vy1), 0.0f);
    float h_align = h_ov / (fminf(kh, vh) + EPSF);
    float v_ov = fmaxf(fminf(kx2, vx2) - fmaxf(kx1, vx1), 0.0f);
    float v_align = v_ov / (fminf(kw, vw) + EPSF);
    float area_ratio   = (vh * vw) / (kh * kw + EPSF);
    float aspect_ratio = (vw / (vh + EPSF)) / (kw / (kh + EPSF));

    float sf[8] = { dx, dy, dist, angle, h_align, v_align, area_ratio, aspect_ratio };

    long long bidx = (long long)b * (MC * MC) + i * MC + jj;
    float biafv = srowk[ty] + g_rowv[b * MC + jj] + sbil;
    #pragma unroll
    for (int s = 0; s < 8; s++) biafv += g_biaf8[s][bidx];

    float f1[16];
    #pragma unroll
    for (int t = 0; t < 16; t++) f1[t] = fmaf(biafv, sF0[t], sb2f[t]);

    for (int u = 0; u < 64; u++) {
        float h = sb1[u];
        #pragma unroll
        for (int f = 0; f < 8; f++) h = fmaf(sf[f], sW1[f * 64 + u], h);
        h = fmaxf(h, 0.0f);
        #pragma unroll
        for (int t = 0; t < 16; t++) f1[t] = fmaf(h, sW2f[u * 16 + t], f1[t]);
    }

    float score = sbf2;
    #pragma unroll
    for (int t = 0; t < 16; t++) score = fmaf(fmaxf(f1[t], 0.0f), sF2[t], score);

    out[bidx] = score;
}

// ---------------- launch ----------------
extern "C" void kernel_launch(void* const* d_in, const int* in_sizes, int n_in,
                              void* d_out, int out_size) {
    (void)in_sizes; (void)n_in; (void)out_size;
    const float* seq    = (const float*)d_in[0];
    const float* logits = (const float*)d_in[1];
    const float* bboxes = (const float*)d_in[2];
    const int*   mask   = (const int*)  d_in[3];
    const float* Wk  = (const float*)d_in[4];
    const float* bk  = (const float*)d_in[5];
    const float* Wv  = (const float*)d_in[6];
    const float* bv  = (const float*)d_in[7];
    const float* Wbil= (const float*)d_in[8];
    const float* bbil= (const float*)d_in[9];
    const float* Ws1 = (const float*)d_in[10];
    const float* bs1 = (const float*)d_in[11];
    const float* Ws2 = (const float*)d_in[12];
    const float* bs2 = (const float*)d_in[13];
    const float* Wf1 = (const float*)d_in[14];
    const float* bf1 = (const float*)d_in[15];
    const float* Wf2 = (const float*)d_in[16];
    const float* bf2 = (const float*)d_in[17];
    float* out = (float*)d_out;

    float *pWc2, *pM;
    cudaGetSymbolAddress((void**)&pWc2, g_Wc2);
    cudaGetSymbolAddress((void**)&pM,   g_M);

    cudaMemsetAsync(pWc2, 0, (size_t)HH * HH * sizeof(float));
    cudaMemsetAsync(pM,   0, (size_t)HH * HH * sizeof(float));

    topk_kernel<<<dim3(BB, 2), 512>>>(logits, mask, bboxes, out);
    setupA<<<99, 256>>>(bk, Wbil, bv);
    setupB<<<193, 256>>>(Wv, Wk, bv, Ws2, bs2, Wf1, bf1);

    // Wc2 = Wbil @ Wv^T  (split-K x8, 288 blocks, 256 threads)
    nt_atomic<<<dim3(HH / 128, HH / 128, 8), 256>>>(Wbil, Wv, pWc2);
    // M = Wk @ Wc2
    nn_atomic<<<dim3(HH / 128, HH / 128, 8), 256>>>(Wk, pWc2, pM);

    // u = Gk(seq) @ M   (64x128 tiles, 384 blocks)
    u_gemm<<<dim3(HH / 128, (BB * MC) / 64), 256>>>(seq, pM);

    // rowk = Gk.p ; rowv = Gv.q + c
    growdot_kernel<<<dim3((BB * MC) / 8, 2), 256>>>(seq);

    // biaffine term1: 8 split buffers (256 blocks, 256 threads)
    biaf_splitk<<<dim3(8, BB), 256>>>(seq);

    pair_kernel<<<dim3(MC / 2, BB), 256>>>(out, Ws1, bs1, Wf1, Wf2, bf2, bbil);
}

// round 9
// speedup vs baseline: 1.0404x; 1.0404x over previous
#include <cuda_runtime.h>
#include <math.h>

#define BB 32
#define SS 512
#define HH 768
#define MC 128
#define EPSF 1e-8f
#define TK 16

// ---------------- scratch (static device memory; no allocs) ----------------
__device__ int   g_kidx[BB*MC];
__device__ int   g_vidx[BB*MC];
__device__ float g_kbox[BB*MC*4];
__device__ float g_vbox[BB*MC*4];
__device__ float g_u[BB*MC*HH];
__device__ float g_biaf4[4][BB*MC*MC];
__device__ float g_Wc2[HH*HH];   // Wbil @ Wv^T
__device__ float g_M[HH*HH];     // Wk @ Wc2
__device__ float g_s1[HH];       // bk @ Wbil
__device__ float g_r[HH];        // Wbil @ bv
__device__ float g_q[HH];        // Wv @ s1
__device__ float g_p[HH];        // Wk @ r
__device__ float g_c[1];         // s1 . bv
__device__ float g_rowk[BB*MC];
__device__ float g_rowv[BB*MC];
__device__ float g_W2f[64*16];
__device__ float g_b2f[16];

// -------- 1+2) conf (inline) + exact top-128 of 512 via bitonic sort ------
__global__ void topk_kernel(const float* __restrict__ logits,
                            const int* __restrict__ mask,
                            const float* __restrict__ bboxes,
                            float* __restrict__ out) {
    int b = blockIdx.x;
    int which = blockIdx.y;   // 0 = key, 1 = val
    __shared__ float sc[512];
    __shared__ int   si[512];
    int tid = threadIdx.x;

    {   // inline confidence
        int t = b * SS + tid;
        float l0 = logits[3*t+0], l1 = logits[3*t+1], l2 = logits[3*t+2];
        int pred = 0; float best = l0;
        if (l1 > best) { pred = 1; best = l1; }
        if (l2 > best) { pred = 2; best = l2; }
        float e0 = expf(l0 - best), e1 = expf(l1 - best), e2 = expf(l2 - best);
        float inv = 1.0f / (e0 + e1 + e2);
        bool valid = (mask[t] == 1);
        float conf;
        if (which == 0) conf = (pred == 1 && valid) ? e1 * inv : -INFINITY;
        else            conf = (pred == 2 && valid) ? e2 * inv : -INFINITY;
        sc[tid] = conf; si[tid] = tid;
    }

    for (int k = 2; k <= 512; k <<= 1) {
        for (int j = k >> 1; j > 0; j >>= 1) {
            __syncthreads();
            int ixj = tid ^ j;
            if (ixj > tid) {
                float c1 = sc[tid], c2 = sc[ixj];
                int   i1 = si[tid], i2 = si[ixj];
                bool b2 = (c2 > c1) || (c2 == c1 && i2 < i1);
                bool doswap = ((tid & k) == 0) ? b2 : !b2;
                if (doswap) {
                    sc[tid] = c2; si[tid] = i2;
                    sc[ixj] = c1; si[ixj] = i1;
                }
            }
        }
    }
    __syncthreads();

    if (tid < MC) {
        int   idx = si[tid];
        float cf  = sc[tid];
        int*   gi = (which == 0) ? g_kidx : g_vidx;
        float* gb = (which == 0) ? g_kbox : g_vbox;
        gi[b * MC + tid] = idx;
        const float* src = bboxes + ((long long)b * SS + idx) * 4;
        float* dst = gb + (b * MC + tid) * 4;
        dst[0] = src[0]; dst[1] = src[1]; dst[2] = src[2]; dst[3] = src[3];
        long long base = (long long)BB * MC * MC;            // 524288
        float vf = (cf != -INFINITY) ? 1.0f : 0.0f;
        out[base + (long long)which * (BB * MC) + b * MC + tid] = vf;
        out[base + 2LL * (BB * MC) + (long long)which * (BB * MC) + b * MC + tid] = (float)idx;
    }
}

// ---------------- setupA: s1 = bk @ Wbil ; r = Wbil @ bv -------------------
__global__ void setupA(const float* __restrict__ bk,
                       const float* __restrict__ Wbil,
                       const float* __restrict__ bv) {
    int bx = blockIdx.x, tid = threadIdx.x;
    if (bx < 3) {                 // s1: column dots, thread per output
        int j = bx * 256 + tid;
        float s = 0.f;
        for (int h = 0; h < HH; h++) s = fmaf(bk[h], Wbil[h * HH + j], s);
        g_s1[j] = s;
    } else {                      // r: row dots, warp per row
        int row = (bx - 3) * 8 + (tid >> 5);
        int lane = tid & 31;
        const float* rp = Wbil + (long long)row * HH;
        float s = 0.f;
        #pragma unroll 4
        for (int cdx = lane; cdx < HH; cdx += 32) s = fmaf(rp[cdx], bv[cdx], s);
        #pragma unroll
        for (int o = 16; o; o >>= 1) s += __shfl_xor_sync(0xffffffffu, s, o);
        if (lane == 0) g_r[row] = s;
    }
}

// -------- setupB: q = Wv@s1 ; p = Wk@r ; c = s1.bv ; MLP fold --------------
__global__ void setupB(const float* __restrict__ Wv, const float* __restrict__ Wk,
                       const float* __restrict__ bv,
                       const float* __restrict__ Ws2, const float* __restrict__ bs2,
                       const float* __restrict__ Wf1, const float* __restrict__ bf1) {
    int bx = blockIdx.x, tid = threadIdx.x;
    if (bx < 192) {               // warp-per-row dots
        const float* A   = (bx < 96) ? Wv : Wk;
        const float* x   = (bx < 96) ? g_s1 : g_r;
        float* outv      = (bx < 96) ? g_q : g_p;
        int row = ((bx < 96) ? bx : bx - 96) * 8 + (tid >> 5);
        int lane = tid & 31;
        const float* rp = A + (long long)row * HH;
        float s = 0.f;
        #pragma unroll 4
        for (int cdx = lane; cdx < HH; cdx += 32) s = fmaf(rp[cdx], x[cdx], s);
        #pragma unroll
        for (int o = 16; o; o >>= 1) s += __shfl_xor_sync(0xffffffffu, s, o);
        if (lane == 0) outv[row] = s;
    } else {                      // fold + c
        #pragma unroll
        for (int e = 0; e < 4; e++) {
            int o = tid * 4 + e;
            if (o < 1024) {
                int u = o >> 4, t = o & 15;
                float s = 0.f;
                #pragma unroll
                for (int s2 = 0; s2 < 32; s2++)
                    s = fmaf(Ws2[u * 32 + s2], Wf1[(s2 + 1) * 16 + t], s);
                g_W2f[o] = s;
            }
        }
        if (tid < 16) {
            float s = bf1[tid];
            #pragma unroll
            for (int s2 = 0; s2 < 32; s2++)
                s = fmaf(bs2[s2], Wf1[(s2 + 1) * 16 + tid], s);
            g_b2f[tid] = s;
        }
        __shared__ float red[256];
        float s = 0.f;
        for (int g = tid; g < HH; g += 256) s = fmaf(g_s1[g], bv[g], s);
        red[tid] = s; __syncthreads();
        for (int o = 128; o; o >>= 1) { if (tid < o) red[tid] += red[tid + o]; __syncthreads(); }
        if (tid == 0) g_c[0] = red[0];
    }
}

// ---------------- NT split-K x8 atomic: Wc2 = Wbil @ Wv^T ------------------
__global__ __launch_bounds__(512)
void nt_atomic(const float* __restrict__ A, const float* __restrict__ B,
               float* __restrict__ C) {
    __shared__ __align__(16) float As[2][TK][132];
    __shared__ __align__(16) float Bs[2][TK][132];
    const int nslabs = 6;
    int tid = threadIdx.x;
    int tx = tid & 15, ty = tid >> 4;
    int m0 = blockIdx.y * 128, n0 = blockIdx.x * 128;
    int kbase = blockIdx.z * nslabs * TK;
    int ar = tid >> 2, ak = (tid & 3) * 4;

    float4 av, bv4;
#define LOAD(K0) do { \
        av  = *(const float4*)(A + (long long)(m0 + ar) * HH + (K0) + ak); \
        bv4 = *(const float4*)(B + (long long)(n0 + ar) * HH + (K0) + ak); \
    } while (0)
#define STORE(BUF) do { \
        As[BUF][ak+0][ar] = av.x; As[BUF][ak+1][ar] = av.y; \
        As[BUF][ak+2][ar] = av.z; As[BUF][ak+3][ar] = av.w; \
        Bs[BUF][ak+0][ar] = bv4.x; Bs[BUF][ak+1][ar] = bv4.y; \
        Bs[BUF][ak+2][ar] = bv4.z; Bs[BUF][ak+3][ar] = bv4.w; \
    } while (0)

    float acc[4][8];
    #pragma unroll
    for (int i = 0; i < 4; i++)
        #pragma unroll
        for (int j = 0; j < 8; j++) acc[i][j] = 0.f;

    LOAD(kbase); STORE(0); __syncthreads();
    for (int kt = 0; kt < nslabs; kt++) {
        int cur = kt & 1;
        if (kt + 1 < nslabs) LOAD(kbase + (kt + 1) * TK);
        #pragma unroll
        for (int kk = 0; kk < TK; kk++) {
            float a[4], b[8];
            *(float4*)a       = *(const float4*)&As[cur][kk][ty * 4];
            *(float4*)b       = *(const float4*)&Bs[cur][kk][tx * 8];
            *(float4*)(b + 4) = *(const float4*)&Bs[cur][kk][tx * 8 + 4];
            #pragma unroll
            for (int i = 0; i < 4; i++)
                #pragma unroll
                for (int j = 0; j < 8; j++)
                    acc[i][j] = fmaf(a[i], b[j], acc[i][j]);
        }
        if (kt + 1 < nslabs) { STORE(cur ^ 1); __syncthreads(); }
    }
    #pragma unroll
    for (int i = 0; i < 4; i++)
        #pragma unroll
        for (int j = 0; j < 8; j++)
            atomicAdd(&C[(long long)(m0 + ty * 4 + i) * HH + n0 + tx * 8 + j], acc[i][j]);
#undef LOAD
#undef STORE
}

// ---------------- NN split-K x8 atomic: M = Wk @ Wc2 -----------------------
__global__ __launch_bounds__(512)
void nn_atomic(const float* __restrict__ A, const float* __restrict__ B,
               float* __restrict__ C) {
    __shared__ __align__(16) float As[2][TK][132];
    __shared__ __align__(16) float Bs[2][TK][128];
    const int nslabs = 6;
    int tid = threadIdx.x;
    int tx = tid & 15, ty = tid >> 4;
    int m0 = blockIdx.y * 128, c0 = blockIdx.x * 128;
    int kbase = blockIdx.z * nslabs * TK;
    int ar = tid >> 2, ak = (tid & 3) * 4;
    int bkr = tid >> 5, bcc = (tid & 31) * 4;

    float4 av, bv4;
#define LOAD(K0) do { \
        av  = *(const float4*)(A + (long long)(m0 + ar) * HH + (K0) + ak); \
        bv4 = *(const float4*)(B + (long long)((K0) + bkr) * HH + c0 + bcc); \
    } while (0)
#define STORE(BUF) do { \
        As[BUF][ak+0][ar] = av.x; As[BUF][ak+1][ar] = av.y; \
        As[BUF][ak+2][ar] = av.z; As[BUF][ak+3][ar] = av.w; \
        *(float4*)&Bs[BUF][bkr][bcc] = bv4; \
    } while (0)

    float acc[4][8];
    #pragma unroll
    for (int i = 0; i < 4; i++)
        #pragma unroll
        for (int j = 0; j < 8; j++) acc[i][j] = 0.f;

    LOAD(kbase); STORE(0); __syncthreads();
    for (int kt = 0; kt < nslabs; kt++) {
        int cur = kt & 1;
        if (kt + 1 < nslabs) LOAD(kbase + (kt + 1) * TK);
        #pragma unroll
        for (int kk = 0; kk < TK; kk++) {
            float a[4], b[8];
            *(float4*)a       = *(const float4*)&As[cur][kk][ty * 4];
            *(float4*)b       = *(const float4*)&Bs[cur][kk][tx * 8];
            *(float4*)(b + 4) = *(const float4*)&Bs[cur][kk][tx * 8 + 4];
            #pragma unroll
            for (int i = 0; i < 4; i++)
                #pragma unroll
                for (int j = 0; j < 8; j++)
                    acc[i][j] = fmaf(a[i], b[j], acc[i][j]);
        }
        if (kt + 1 < nslabs) { STORE(cur ^ 1); __syncthreads(); }
    }
    #pragma unroll
    for (int i = 0; i < 4; i++)
        #pragma unroll
        for (int j = 0; j < 8; j++)
            atomicAdd(&C[(long long)(m0 + ty * 4 + i) * HH + c0 + tx * 8 + j], acc[i][j]);
#undef LOAD
#undef STORE
}

// --------- u = Gk(seq) @ M : full-K gathered NN, 128x128 tile, 8x8 --------
__global__ __launch_bounds__(256)
void u_gemm(const float* __restrict__ A, const float* __restrict__ Bm) {
    __shared__ __align__(16) float As[2][TK][132];
    __shared__ __align__(16) float Bs[2][TK][128];
    __shared__ long long rowbase[128];

    int tid = threadIdx.x;
    int tx = tid & 15, ty = tid >> 4;
    int m0 = blockIdx.y * 128, c0 = blockIdx.x * 128;

    if (tid < 128) {
        int m = m0 + tid;
        rowbase[tid] = ((long long)(m >> 7) * SS + g_kidx[m]) * HH;
    }
    __syncthreads();

    int ar0 = tid >> 2, ak0 = (tid & 3) * 4, ar1 = ar0 + 64;
    int bk0 = tid >> 5, bc0 = (tid & 31) * 4, bk1 = bk0 + 8;
    long long ra0 = rowbase[ar0];
    long long ra1 = rowbase[ar1];

    float4 a0v, a1v, b0v, b1v;
#define LOAD_REGS(K0) do { \
        a0v = *(const float4*)(A + ra0 + (K0) + ak0); \
        a1v = *(const float4*)(A + ra1 + (K0) + ak0); \
        b0v = *(const float4*)(Bm + (long long)((K0) + bk0) * HH + c0 + bc0); \
        b1v = *(const float4*)(Bm + (long long)((K0) + bk1) * HH + c0 + bc0); \
    } while (0)
#define STORE_SMEM(BUF) do { \
        As[BUF][ak0+0][ar0] = a0v.x; As[BUF][ak0+1][ar0] = a0v.y; \
        As[BUF][ak0+2][ar0] = a0v.z; As[BUF][ak0+3][ar0] = a0v.w; \
        As[BUF][ak0+0][ar1] = a1v.x; As[BUF][ak0+1][ar1] = a1v.y; \
        As[BUF][ak0+2][ar1] = a1v.z; As[BUF][ak0+3][ar1] = a1v.w; \
        *(float4*)&Bs[BUF][bk0][bc0] = b0v; \
        *(float4*)&Bs[BUF][bk1][bc0] = b1v; \
    } while (0)

    float acc[8][8];
    #pragma unroll
    for (int i = 0; i < 8; i++)
        #pragma unroll
        for (int j = 0; j < 8; j++) acc[i][j] = 0.0f;

    LOAD_REGS(0);
    STORE_SMEM(0);
    __syncthreads();

    const int NT = HH / TK;   // 48
    for (int kt = 0; kt < NT; kt++) {
        int cur = kt & 1;
        if (kt + 1 < NT) LOAD_REGS((kt + 1) * TK);
        #pragma unroll
        for (int kk = 0; kk < TK; kk++) {
            float a[8], b[8];
            *(float4*)(a)     = *(const float4*)&As[cur][kk][ty * 8];
            *(float4*)(a + 4) = *(const float4*)&As[cur][kk][ty * 8 + 4];
            *(float4*)(b)     = *(const float4*)&Bs[cur][kk][tx * 8];
            *(float4*)(b + 4) = *(const float4*)&Bs[cur][kk][tx * 8 + 4];
            #pragma unroll
            for (int i = 0; i < 8; i++)
                #pragma unroll
                for (int j = 0; j < 8; j++)
                    acc[i][j] = fmaf(a[i], b[j], acc[i][j]);
        }
        if (kt + 1 < NT) { STORE_SMEM(cur ^ 1); __syncthreads(); }
    }

    #pragma unroll
    for (int i = 0; i < 8; i++) {
        long long r = m0 + ty * 8 + i;
        *(float4*)&g_u[r * HH + c0 + tx * 8]     = *(float4*)&acc[i][0];
        *(float4*)&g_u[r * HH + c0 + tx * 8 + 4] = *(float4*)&acc[i][4];
    }
#undef LOAD_REGS
#undef STORE_SMEM
}

// -------- rowk = Gk.p ; rowv = Gv.q + c  (warp per row) --------------------
__global__ void growdot_kernel(const float* __restrict__ seq) {
    int r = blockIdx.x * 8 + (threadIdx.x >> 5);
    int lane = threadIdx.x & 31;
    int which = blockIdx.y;
    const int* gidx = which ? g_vidx : g_kidx;
    const float* vec = which ? g_q : g_p;
    const float* row = seq + ((long long)(r >> 7) * SS + gidx[r]) * HH;
    float s = 0.f;
    #pragma unroll 4
    for (int cdx = lane; cdx < HH; cdx += 32) s = fmaf(row[cdx], vec[cdx], s);
    #pragma unroll
    for (int o = 16; o; o >>= 1) s += __shfl_xor_sync(0xffffffffu, s, o);
    if (lane == 0) {
        if (which) g_rowv[r] = s + g_c[0];
        else       g_rowk[r] = s;
    }
}

// ----- biaffine: biaf4[s][b,i,j] = u[b,i,ks] . Gv_seq[b,j,ks] (4 splits) ---
__global__ __launch_bounds__(512)
void biaf_splitk(const float* __restrict__ seq) {
    __shared__ __align__(16) float As[2][TK][132];
    __shared__ __align__(16) float Bs[2][TK][132];
    __shared__ long long vrowbase[128];
    const int nslabs = 12;
    int b = blockIdx.y;
    int split = blockIdx.x;
    int kbase = split * nslabs * TK;
    int tid = threadIdx.x;
    int tx = tid & 15, ty = tid >> 4;

    const float* A = g_u + (long long)b * MC * HH;

    if (tid < 128)
        vrowbase[tid] = ((long long)b * SS + g_vidx[b * MC + tid]) * HH;
    __syncthreads();

    int ar = tid >> 2, ak = (tid & 3) * 4;
    long long vb = vrowbase[ar];

    float4 av, bv4;
#define LOAD(K0) do { \
        av  = *(const float4*)(A + (long long)ar * HH + (K0) + ak); \
        bv4 = *(const float4*)(seq + vb + (K0) + ak); \
    } while (0)
#define STORE(BUF) do { \
        As[BUF][ak+0][ar] = av.x; As[BUF][ak+1][ar] = av.y; \
        As[BUF][ak+2][ar] = av.z; As[BUF][ak+3][ar] = av.w; \
        Bs[BUF][ak+0][ar] = bv4.x; Bs[BUF][ak+1][ar] = bv4.y; \
        Bs[BUF][ak+2][ar] = bv4.z; Bs[BUF][ak+3][ar] = bv4.w; \
    } while (0)

    float acc[4][8];
    #pragma unroll
    for (int i = 0; i < 4; i++)
        #pragma unroll
        for (int j = 0; j < 8; j++) acc[i][j] = 0.f;

    LOAD(kbase); STORE(0); __syncthreads();
    for (int kt = 0; kt < nslabs; kt++) {
        int cur = kt & 1;
        if (kt + 1 < nslabs) LOAD(kbase + (kt + 1) * TK);
        #pragma unroll
        for (int kk = 0; kk < TK; kk++) {
            float a[4], bb[8];
            *(float4*)a        = *(const float4*)&As[cur][kk][ty * 4];
            *(float4*)bb       = *(const float4*)&Bs[cur][kk][tx * 8];
            *(float4*)(bb + 4) = *(const float4*)&Bs[cur][kk][tx * 8 + 4];
            #pragma unroll
            for (int i = 0; i < 4; i++)
                #pragma unroll
                for (int j = 0; j < 8; j++)
                    acc[i][j] = fmaf(a[i], bb[j], acc[i][j]);
        }
        if (kt + 1 < nslabs) { STORE(cur ^ 1); __syncthreads(); }
    }

    float* dst = g_biaf4[split] + (long long)b * (MC * MC);
    #pragma unroll
    for (int i = 0; i < 4; i++) {
        int r = ty * 4 + i;
        *(float4*)&dst[r * MC + tx * 8]     = *(float4*)&acc[i][0];
        *(float4*)&dst[r * MC + tx * 8 + 4] = *(float4*)&acc[i][4];
    }
#undef LOAD
#undef STORE
}

// ---------------- spatial features + folded MLP + final scores ------------
__global__ __launch_bounds__(128)
void pair_kernel(float* __restrict__ out,
                 const float* __restrict__ Ws1, const float* __restrict__ bs1,
                 const float* __restrict__ Wf1,
                 const float* __restrict__ Wf2, const float* __restrict__ bf2,
                 const float* __restrict__ bbilp) {
    __shared__ float sW1[8 * 64], sb1[64];
    __shared__ float sW2f[64 * 16], sb2f[16];
    __shared__ float sF0[16], sF2[16];
    __shared__ float sbf2, sbil, srowk;
    __shared__ float kb[4];

    int i = blockIdx.x;
    int b = blockIdx.y;
    int j = threadIdx.x;

    for (int t = j; t < 512;  t += 128) sW1[t] = Ws1[t];
    for (int t = j; t < 1024; t += 128) sW2f[t] = g_W2f[t];
    if (j < 64) sb1[j] = bs1[j];
    if (j < 16) { sb2f[j] = g_b2f[j]; sF0[j] = Wf1[j]; sF2[j] = Wf2[j]; }
    if (j == 0) { sbf2 = bf2[0]; sbil = bbilp[0]; srowk = g_rowk[b * MC + i]; }
    if (j < 4)  kb[j] = g_kbox[(b * MC + i) * 4 + j];
    __syncthreads();

    float vx1 = g_vbox[(b * MC + j) * 4 + 0];
    float vy1 = g_vbox[(b * MC + j) * 4 + 1];
    float vx2 = g_vbox[(b * MC + j) * 4 + 2];
    float vy2 = g_vbox[(b * MC + j) * 4 + 3];
    float kx1 = kb[0], ky1 = kb[1], kx2 = kb[2], ky2 = kb[3];

    float kcx = (kx1 + kx2) * 0.5f, kcy = (ky1 + ky2) * 0.5f;
    float vcx = (vx1 + vx2) * 0.5f, vcy = (vy1 + vy2) * 0.5f;
    float dx = vcx - kcx, dy = vcy - kcy;
    float dist  = sqrtf(dx * dx + dy * dy + EPSF);
    float angle = atan2f(dy, dx);
    float kh = ky2 - ky1, kw = kx2 - kx1;
    float vh = vy2 - vy1, vw = vx2 - vx1;
    float h_ov = fmaxf(fminf(ky2, vy2) - fmaxf(ky1, vy1), 0.0f);
    float h_align = h_ov / (fminf(kh, vh) + EPSF);
    float v_ov = fmaxf(fminf(kx2, vx2) - fmaxf(kx1, vx1), 0.0f);
    float v_align = v_ov / (fminf(kw, vw) + EPSF);
    float area_ratio   = (vh * vw) / (kh * kw + EPSF);
    float aspect_ratio = (vw / (vh + EPSF)) / (kw / (kh + EPSF));

    float sf[8] = { dx, dy, dist, angle, h_align, v_align, area_ratio, aspect_ratio };

    long long bidx = (long long)b * (MC * MC) + i * MC + j;
    float biafv = g_biaf4[0][bidx] + g_biaf4[1][bidx]
                + g_biaf4[2][bidx] + g_biaf4[3][bidx]
                + srowk + g_rowv[b * MC + j] + sbil;

    float f1[16];
    #pragma unroll
    for (int t = 0; t < 16; t++) f1[t] = fmaf(biafv, sF0[t], sb2f[t]);

    for (int u = 0; u < 64; u++) {
        float h = sb1[u];
        #pragma unroll
        for (int f = 0; f < 8; f++) h = fmaf(sf[f], sW1[f * 64 + u], h);
        h = fmaxf(h, 0.0f);
        #pragma unroll
        for (int t = 0; t < 16; t++) f1[t] = fmaf(h, sW2f[u * 16 + t], f1[t]);
    }

    float score = sbf2;
    #pragma unroll
    for (int t = 0; t < 16; t++) score = fmaf(fmaxf(f1[t], 0.0f), sF2[t], score);

    out[bidx] = score;
}

// ---------------- launch ----------------
extern "C" void kernel_launch(void* const* d_in, const int* in_sizes, int n_in,
                              void* d_out, int out_size) {
    (void)in_sizes; (void)n_in; (void)out_size;
    const float* seq    = (const float*)d_in[0];
    const float* logits = (const float*)d_in[1];
    const float* bboxes = (const float*)d_in[2];
    const int*   mask   = (const int*)  d_in[3];
    const float* Wk  = (const float*)d_in[4];
    const float* bk  = (const float*)d_in[5];
    const float* Wv  = (const float*)d_in[6];
    const float* bv  = (const float*)d_in[7];
    const float* Wbil= (const float*)d_in[8];
    const float* bbil= (const float*)d_in[9];
    const float* Ws1 = (const float*)d_in[10];
    const float* bs1 = (const float*)d_in[11];
    const float* Ws2 = (const float*)d_in[12];
    const float* bs2 = (const float*)d_in[13];
    const float* Wf1 = (const float*)d_in[14];
    const float* bf1 = (const float*)d_in[15];
    const float* Wf2 = (const float*)d_in[16];
    const float* bf2 = (const float*)d_in[17];
    float* out = (float*)d_out;

    float *pWc2, *pM;
    cudaGetSymbolAddress((void**)&pWc2, g_Wc2);
    cudaGetSymbolAddress((void**)&pM,   g_M);

    cudaMemsetAsync(pWc2, 0, (size_t)HH * HH * sizeof(float));
    cudaMemsetAsync(pM,   0, (size_t)HH * HH * sizeof(float));

    topk_kernel<<<dim3(BB, 2), 512>>>(logits, mask, bboxes, out);
    setupA<<<99, 256>>>(bk, Wbil, bv);
    setupB<<<193, 256>>>(Wv, Wk, bv, Ws2, bs2, Wf1, bf1);

    // Wc2 = Wbil @ Wv^T  (split-K x8, 288 blocks, 512 threads)
    nt_atomic<<<dim3(HH / 128, HH / 128, 8), 512>>>(Wbil, Wv, pWc2);
    // M = Wk @ Wc2       (split-K x8)
    nn_atomic<<<dim3(HH / 128, HH / 128, 8), 512>>>(Wk, pWc2, pM);

    // u = Gk(seq) @ M   (full K, 192 blocks)
    u_gemm<<<dim3(HH / 128, (BB * MC) / 128), 256>>>(seq, pM);

    // rowk = Gk.p ; rowv = Gv.q + c
    growdot_kernel<<<dim3((BB * MC) / 8, 2), 256>>>(seq);

    // biaffine term1: 4 split buffers
    biaf_splitk<<<dim3(4, BB), 512>>>(seq);

    pair_kernel<<<dim3(MC, BB), 128>>>(out, Ws1, bs1, Wf1, Wf2, bf2, bbil);
}

// round 10
// speedup vs baseline: 1.2130x; 1.1659x over previous
#include <cuda_runtime.h>
#include <math.h>

#define BB 32
#define SS 512
#define HH 768
#define MC 128
#define EPSF 1e-8f
#define TK 16

// ---------------- scratch (static device memory; no allocs) ----------------
__device__ int   g_kidx[BB*MC];
__device__ int   g_vidx[BB*MC];
__device__ float g_kbox[BB*MC*4];
__device__ float g_vbox[BB*MC*4];
__device__ float g_u[BB*MC*HH];
__device__ float g_biaf4[4][BB*MC*MC];
__device__ float g_Wc2[HH*HH];   // Wbil @ Wv^T
__device__ float g_M[HH*HH];     // Wk @ Wc2
__device__ float g_s1[HH];       // bk @ Wbil
__device__ float g_r[HH];        // Wbil @ bv
__device__ float g_q[HH];        // Wv @ s1
__device__ float g_p[HH];        // Wk @ r
__device__ float g_c[1];         // s1 . bv
__device__ float g_rowk[BB*MC];
__device__ float g_rowv[BB*MC];
__device__ float g_W2f[64*16];
__device__ float g_b2f[16];

// -------- 1+2) conf (inline) + exact top-128 of 512 via bitonic sort ------
__global__ void topk_kernel(const float* __restrict__ logits,
                            const int* __restrict__ mask,
                            const float* __restrict__ bboxes,
                            float* __restrict__ out) {
    int b = blockIdx.x;
    int which = blockIdx.y;   // 0 = key, 1 = val
    __shared__ float sc[512];
    __shared__ int   si[512];
    int tid = threadIdx.x;

    {   // inline confidence
        int t = b * SS + tid;
        float l0 = logits[3*t+0], l1 = logits[3*t+1], l2 = logits[3*t+2];
        int pred = 0; float best = l0;
        if (l1 > best) { pred = 1; best = l1; }
        if (l2 > best) { pred = 2; best = l2; }
        float e0 = expf(l0 - best), e1 = expf(l1 - best), e2 = expf(l2 - best);
        float inv = 1.0f / (e0 + e1 + e2);
        bool valid = (mask[t] == 1);
        float conf;
        if (which == 0) conf = (pred == 1 && valid) ? e1 * inv : -INFINITY;
        else            conf = (pred == 2 && valid) ? e2 * inv : -INFINITY;
        sc[tid] = conf; si[tid] = tid;
    }

    for (int k = 2; k <= 512; k <<= 1) {
        for (int j = k >> 1; j > 0; j >>= 1) {
            __syncthreads();
            int ixj = tid ^ j;
            if (ixj > tid) {
                float c1 = sc[tid], c2 = sc[ixj];
                int   i1 = si[tid], i2 = si[ixj];
                bool b2 = (c2 > c1) || (c2 == c1 && i2 < i1);
                bool doswap = ((tid & k) == 0) ? b2 : !b2;
                if (doswap) {
                    sc[tid] = c2; si[tid] = i2;
                    sc[ixj] = c1; si[ixj] = i1;
                }
            }
        }
    }
    __syncthreads();

    if (tid < MC) {
        int   idx = si[tid];
        float cf  = sc[tid];
        int*   gi = (which == 0) ? g_kidx : g_vidx;
        float* gb = (which == 0) ? g_kbox : g_vbox;
        gi[b * MC + tid] = idx;
        const float* src = bboxes + ((long long)b * SS + idx) * 4;
        float* dst = gb + (b * MC + tid) * 4;
        dst[0] = src[0]; dst[1] = src[1]; dst[2] = src[2]; dst[3] = src[3];
        long long base = (long long)BB * MC * MC;            // 524288
        float vf = (cf != -INFINITY) ? 1.0f : 0.0f;
        out[base + (long long)which * (BB * MC) + b * MC + tid] = vf;
        out[base + 2LL * (BB * MC) + (long long)which * (BB * MC) + b * MC + tid] = (float)idx;
    }
}

// ---------------- setupA: s1 = bk @ Wbil ; r = Wbil @ bv -------------------
__global__ void setupA(const float* __restrict__ bk,
                       const float* __restrict__ Wbil,
                       const float* __restrict__ bv) {
    int bx = blockIdx.x, tid = threadIdx.x;
    if (bx < 3) {                 // s1: column dots, thread per output
        int j = bx * 256 + tid;
        float s = 0.f;
        for (int h = 0; h < HH; h++) s = fmaf(bk[h], Wbil[h * HH + j], s);
        g_s1[j] = s;
    } else {                      // r: row dots, warp per row
        int row = (bx - 3) * 8 + (tid >> 5);
        int lane = tid & 31;
        const float* rp = Wbil + (long long)row * HH;
        float s = 0.f;
        #pragma unroll 4
        for (int cdx = lane; cdx < HH; cdx += 32) s = fmaf(rp[cdx], bv[cdx], s);
        #pragma unroll
        for (int o = 16; o; o >>= 1) s += __shfl_xor_sync(0xffffffffu, s, o);
        if (lane == 0) g_r[row] = s;
    }
}

// -------- setupB: q = Wv@s1 ; p = Wk@r ; c = s1.bv ; MLP fold --------------
__global__ void setupB(const float* __restrict__ Wv, const float* __restrict__ Wk,
                       const float* __restrict__ bv,
                       const float* __restrict__ Ws2, const float* __restrict__ bs2,
                       const float* __restrict__ Wf1, const float* __restrict__ bf1) {
    int bx = blockIdx.x, tid = threadIdx.x;
    if (bx < 192) {               // warp-per-row dots
        const float* A   = (bx < 96) ? Wv : Wk;
        const float* x   = (bx < 96) ? g_s1 : g_r;
        float* outv      = (bx < 96) ? g_q : g_p;
        int row = ((bx < 96) ? bx : bx - 96) * 8 + (tid >> 5);
        int lane = tid & 31;
        const float* rp = A + (long long)row * HH;
        float s = 0.f;
        #pragma unroll 4
        for (int cdx = lane; cdx < HH; cdx += 32) s = fmaf(rp[cdx], x[cdx], s);
        #pragma unroll
        for (int o = 16; o; o >>= 1) s += __shfl_xor_sync(0xffffffffu, s, o);
        if (lane == 0) outv[row] = s;
    } else {                      // fold + c
        #pragma unroll
        for (int e = 0; e < 4; e++) {
            int o = tid * 4 + e;
            if (o < 1024) {
                int u = o >> 4, t = o & 15;
                float s = 0.f;
                #pragma unroll
                for (int s2 = 0; s2 < 32; s2++)
                    s = fmaf(Ws2[u * 32 + s2], Wf1[(s2 + 1) * 16 + t], s);
                g_W2f[o] = s;
            }
        }
        if (tid < 16) {
            float s = bf1[tid];
            #pragma unroll
            for (int s2 = 0; s2 < 32; s2++)
                s = fmaf(bs2[s2], Wf1[(s2 + 1) * 16 + tid], s);
            g_b2f[tid] = s;
        }
        __shared__ float red[256];
        float s = 0.f;
        for (int g = tid; g < HH; g += 256) s = fmaf(g_s1[g], bv[g], s);
        red[tid] = s; __syncthreads();
        for (int o = 128; o; o >>= 1) { if (tid < o) red[tid] += red[tid + o]; __syncthreads(); }
        if (tid == 0) g_c[0] = red[0];
    }
}

// ------ NT split-K x4 atomic: Wc2 = Wbil @ Wv^T (8x8, 256 thr) ------------
__global__ __launch_bounds__(256)
void nt_atomic(const float* __restrict__ A, const float* __restrict__ B,
               float* __restrict__ C) {
    __shared__ __align__(16) float As[2][TK][132];
    __shared__ __align__(16) float Bs[2][TK][132];
    const int nslabs = 12;
    int tid = threadIdx.x;
    int tx = tid & 15, ty = tid >> 4;
    int m0 = blockIdx.y * 128, n0 = blockIdx.x * 128;
    int kbase = blockIdx.z * nslabs * TK;
    int ar0 = tid >> 2, ak = (tid & 3) * 4, ar1 = ar0 + 64;

    float4 a0v, a1v, b0v, b1v;
#define LOAD(K0) do { \
        a0v = *(const float4*)(A + (long long)(m0 + ar0) * HH + (K0) + ak); \
        a1v = *(const float4*)(A + (long long)(m0 + ar1) * HH + (K0) + ak); \
        b0v = *(const float4*)(B + (long long)(n0 + ar0) * HH + (K0) + ak); \
        b1v = *(const float4*)(B + (long long)(n0 + ar1) * HH + (K0) + ak); \
    } while (0)
#define STORE(BUF) do { \
        As[BUF][ak+0][ar0] = a0v.x; As[BUF][ak+1][ar0] = a0v.y; \
        As[BUF][ak+2][ar0] = a0v.z; As[BUF][ak+3][ar0] = a0v.w; \
        As[BUF][ak+0][ar1] = a1v.x; As[BUF][ak+1][ar1] = a1v.y; \
        As[BUF][ak+2][ar1] = a1v.z; As[BUF][ak+3][ar1] = a1v.w; \
        Bs[BUF][ak+0][ar0] = b0v.x; Bs[BUF][ak+1][ar0] = b0v.y; \
        Bs[BUF][ak+2][ar0] = b0v.z; Bs[BUF][ak+3][ar0] = b0v.w; \
        Bs[BUF][ak+0][ar1] = b1v.x; Bs[BUF][ak+1][ar1] = b1v.y; \
        Bs[BUF][ak+2][ar1] = b1v.z; Bs[BUF][ak+3][ar1] = b1v.w; \
    } while (0)

    float acc[8][8];
    #pragma unroll
    for (int i = 0; i < 8; i++)
        #pragma unroll
        for (int j = 0; j < 8; j++) acc[i][j] = 0.f;

    LOAD(kbase); STORE(0); __syncthreads();
    for (int kt = 0; kt < nslabs; kt++) {
        int cur = kt & 1;
        if (kt + 1 < nslabs) LOAD(kbase + (kt + 1) * TK);
        #pragma unroll
        for (int kk = 0; kk < TK; kk++) {
            float a[8], b[8];
            *(float4*)(a)     = *(const float4*)&As[cur][kk][ty * 8];
            *(float4*)(a + 4) = *(const float4*)&As[cur][kk][ty * 8 + 4];
            *(float4*)(b)     = *(const float4*)&Bs[cur][kk][tx * 8];
            *(float4*)(b + 4) = *(const float4*)&Bs[cur][kk][tx * 8 + 4];
            #pragma unroll
            for (int i = 0; i < 8; i++)
                #pragma unroll
                for (int j = 0; j < 8; j++)
                    acc[i][j] = fmaf(a[i], b[j], acc[i][j]);
        }
        if (kt + 1 < nslabs) { STORE(cur ^ 1); __syncthreads(); }
    }
    #pragma unroll
    for (int i = 0; i < 8; i++)
        #pragma unroll
        for (int j = 0; j < 8; j++)
            atomicAdd(&C[(long long)(m0 + ty * 8 + i) * HH + n0 + tx * 8 + j], acc[i][j]);
#undef LOAD
#undef STORE
}

// ------ NN split-K x4 atomic: M = Wk @ Wc2 (8x8, 256 thr) ------------------
__global__ __launch_bounds__(256)
void nn_atomic(const float* __restrict__ A, const float* __restrict__ B,
               float* __restrict__ C) {
    __shared__ __align__(16) float As[2][TK][132];
    __shared__ __align__(16) float Bs[2][TK][128];
    const int nslabs = 12;
    int tid = threadIdx.x;
    int tx = tid & 15, ty = tid >> 4;
    int m0 = blockIdx.y * 128, c0 = blockIdx.x * 128;
    int kbase = blockIdx.z * nslabs * TK;
    int ar0 = tid >> 2, ak = (tid & 3) * 4, ar1 = ar0 + 64;
    int bk0 = tid >> 5, bcc = (tid & 31) * 4, bk1 = bk0 + 8;

    float4 a0v, a1v, b0v, b1v;
#define LOAD(K0) do { \
        a0v = *(const float4*)(A + (long long)(m0 + ar0) * HH + (K0) + ak); \
        a1v = *(const float4*)(A + (long long)(m0 + ar1) * HH + (K0) + ak); \
        b0v = *(const float4*)(B + (long long)((K0) + bk0) * HH + c0 + bcc); \
        b1v = *(const float4*)(B + (long long)((K0) + bk1) * HH + c0 + bcc); \
    } while (0)
#define STORE(BUF) do { \
        As[BUF][ak+0][ar0] = a0v.x; As[BUF][ak+1][ar0] = a0v.y; \
        As[BUF][ak+2][ar0] = a0v.z; As[BUF][ak+3][ar0] = a0v.w; \
        As[BUF][ak+0][ar1] = a1v.x; As[BUF][ak+1][ar1] = a1v.y; \
        As[BUF][ak+2][ar1] = a1v.z; As[BUF][ak+3][ar1] = a1v.w; \
        *(float4*)&Bs[BUF][bk0][bcc] = b0v; \
        *(float4*)&Bs[BUF][bk1][bcc] = b1v; \
    } while (0)

    float acc[8][8];
    #pragma unroll
    for (int i = 0; i < 8; i++)
        #pragma unroll
        for (int j = 0; j < 8; j++) acc[i][j] = 0.f;

    LOAD(kbase); STORE(0); __syncthreads();
    for (int kt = 0; kt < nslabs; kt++) {
        int cur = kt & 1;
        if (kt + 1 < nslabs) LOAD(kbase + (kt + 1) * TK);
        #pragma unroll
        for (int kk = 0; kk < TK; kk++) {
            float a[8], b[8];
            *(float4*)(a)     = *(const float4*)&As[cur][kk][ty * 8];
            *(float4*)(a + 4) = *(const float4*)&As[cur][kk][ty * 8 + 4];
            *(float4*)(b)     = *(const float4*)&Bs[cur][kk][tx * 8];
            *(float4*)(b + 4) = *(const float4*)&Bs[cur][kk][tx * 8 + 4];
            #pragma unroll
            for (int i = 0; i < 8; i++)
                #pragma unroll
                for (int j = 0; j < 8; j++)
                    acc[i][j] = fmaf(a[i], b[j], acc[i][j]);
        }
        if (kt + 1 < nslabs) { STORE(cur ^ 1); __syncthreads(); }
    }
    #pragma unroll
    for (int i = 0; i < 8; i++)
        #pragma unroll
        for (int j = 0; j < 8; j++)
            atomicAdd(&C[(long long)(m0 + ty * 8 + i) * HH + c0 + tx * 8 + j], acc[i][j]);
#undef LOAD
#undef STORE
}

// --------- u = Gk(seq) @ M : full-K gathered NN, 128x128 tile, 8x8 --------
__global__ __launch_bounds__(256)
void u_gemm(const float* __restrict__ A, const float* __restrict__ Bm) {
    __shared__ __align__(16) float As[2][TK][132];
    __shared__ __align__(16) float Bs[2][TK][128];
    __shared__ long long rowbase[128];

    int tid = threadIdx.x;
    int tx = tid & 15, ty = tid >> 4;
    int m0 = blockIdx.y * 128, c0 = blockIdx.x * 128;

    if (tid < 128) {
        int m = m0 + tid;
        rowbase[tid] = ((long long)(m >> 7) * SS + g_kidx[m]) * HH;
    }
    __syncthreads();

    int ar0 = tid >> 2, ak0 = (tid & 3) * 4, ar1 = ar0 + 64;
    int bk0 = tid >> 5, bc0 = (tid & 31) * 4, bk1 = bk0 + 8;
    long long ra0 = rowbase[ar0];
    long long ra1 = rowbase[ar1];

    float4 a0v, a1v, b0v, b1v;
#define LOAD_REGS(K0) do { \
        a0v = *(const float4*)(A + ra0 + (K0) + ak0); \
        a1v = *(const float4*)(A + ra1 + (K0) + ak0); \
        b0v = *(const float4*)(Bm + (long long)((K0) + bk0) * HH + c0 + bc0); \
        b1v = *(const float4*)(Bm + (long long)((K0) + bk1) * HH + c0 + bc0); \
    } while (0)
#define STORE_SMEM(BUF) do { \
        As[BUF][ak0+0][ar0] = a0v.x; As[BUF][ak0+1][ar0] = a0v.y; \
        As[BUF][ak0+2][ar0] = a0v.z; As[BUF][ak0+3][ar0] = a0v.w; \
        As[BUF][ak0+0][ar1] = a1v.x; As[BUF][ak0+1][ar1] = a1v.y; \
        As[BUF][ak0+2][ar1] = a1v.z; As[BUF][ak0+3][ar1] = a1v.w; \
        *(float4*)&Bs[BUF][bk0][bc0] = b0v; \
        *(float4*)&Bs[BUF][bk1][bc0] = b1v; \
    } while (0)

    float acc[8][8];
    #pragma unroll
    for (int i = 0; i < 8; i++)
        #pragma unroll
        for (int j = 0; j < 8; j++) acc[i][j] = 0.0f;

    LOAD_REGS(0);
    STORE_SMEM(0);
    __syncthreads();

    const int NT = HH / TK;   // 48
    for (int kt = 0; kt < NT; kt++) {
        int cur = kt & 1;
        if (kt + 1 < NT) LOAD_REGS((kt + 1) * TK);
        #pragma unroll
        for (int kk = 0; kk < TK; kk++) {
            float a[8], b[8];
            *(float4*)(a)     = *(const float4*)&As[cur][kk][ty * 8];
            *(float4*)(a + 4) = *(const float4*)&As[cur][kk][ty * 8 + 4];
            *(float4*)(b)     = *(const float4*)&Bs[cur][kk][tx * 8];
            *(float4*)(b + 4) = *(const float4*)&Bs[cur][kk][tx * 8 + 4];
            #pragma unroll
            for (int i = 0; i < 8; i++)
                #pragma unroll
                for (int j = 0; j < 8; j++)
                    acc[i][j] = fmaf(a[i], b[j], acc[i][j]);
        }
        if (kt + 1 < NT) { STORE_SMEM(cur ^ 1); __syncthreads(); }
    }

    #pragma unroll
    for (int i = 0; i < 8; i++) {
        long long r = m0 + ty * 8 + i;
        *(float4*)&g_u[r * HH + c0 + tx * 8]     = *(float4*)&acc[i][0];
        *(float4*)&g_u[r * HH + c0 + tx * 8 + 4] = *(float4*)&acc[i][4];
    }
#undef LOAD_REGS
#undef STORE_SMEM
}

// -------- rowk = Gk.p ; rowv = Gv.q + c  (warp per row) --------------------
__global__ void growdot_kernel(const float* __restrict__ seq) {
    int r = blockIdx.x * 8 + (threadIdx.x >> 5);
    int lane = threadIdx.x & 31;
    int which = blockIdx.y;
    const int* gidx = which ? g_vidx : g_kidx;
    const float* vec = which ? g_q : g_p;
    const float* row = seq + ((long long)(r >> 7) * SS + gidx[r]) * HH;
    float s = 0.f;
    #pragma unroll 4
    for (int cdx = lane; cdx < HH; cdx += 32) s = fmaf(row[cdx], vec[cdx], s);
    #pragma unroll
    for (int o = 16; o; o >>= 1) s += __shfl_xor_sync(0xffffffffu, s, o);
    if (lane == 0) {
        if (which) g_rowv[r] = s + g_c[0];
        else       g_rowk[r] = s;
    }
}

// ----- biaffine: biaf4[s][b,i,j] = u[b,i,ks] . Gv_seq[b,j,ks] (4 splits) ---
__global__ __launch_bounds__(512)
void biaf_splitk(const float* __restrict__ seq) {
    __shared__ __align__(16) float As[2][TK][132];
    __shared__ __align__(16) float Bs[2][TK][132];
    __shared__ long long vrowbase[128];
    const int nslabs = 12;
    int b = blockIdx.y;
    int split = blockIdx.x;
    int kbase = split * nslabs * TK;
    int tid = threadIdx.x;
    int tx = tid & 15, ty = tid >> 4;

    const float* A = g_u + (long long)b * MC * HH;

    if (tid < 128)
        vrowbase[tid] = ((long long)b * SS + g_vidx[b * MC + tid]) * HH;
    __syncthreads();

    int ar = tid >> 2, ak = (tid & 3) * 4;
    long long vb = vrowbase[ar];

    float4 av, bv4;
#define LOAD(K0) do { \
        av  = *(const float4*)(A + (long long)ar * HH + (K0) + ak); \
        bv4 = *(const float4*)(seq + vb + (K0) + ak); \
    } while (0)
#define STORE(BUF) do { \
        As[BUF][ak+0][ar] = av.x; As[BUF][ak+1][ar] = av.y; \
        As[BUF][ak+2][ar] = av.z; As[BUF][ak+3][ar] = av.w; \
        Bs[BUF][ak+0][ar] = bv4.x; Bs[BUF][ak+1][ar] = bv4.y; \
        Bs[BUF][ak+2][ar] = bv4.z; Bs[BUF][ak+3][ar] = bv4.w; \
    } while (0)

    float acc[4][8];
    #pragma unroll
    for (int i = 0; i < 4; i++)
        #pragma unroll
        for (int j = 0; j < 8; j++) acc[i][j] = 0.f;

    LOAD(kbase); STORE(0); __syncthreads();
    for (int kt = 0; kt < nslabs; kt++) {
        int cur = kt & 1;
        if (kt + 1 < nslabs) LOAD(kbase + (kt + 1) * TK);
        #pragma unroll
        for (int kk = 0; kk < TK; kk++) {
            float a[4], bb[8];
            *(float4*)a        = *(const float4*)&As[cur][kk][ty * 4];
            *(float4*)bb       = *(const float4*)&Bs[cur][kk][tx * 8];
            *(float4*)(bb + 4) = *(const float4*)&Bs[cur][kk][tx * 8 + 4];
            #pragma unroll
            for (int i = 0; i < 4; i++)
                #pragma unroll
                for (int j = 0; j < 8; j++)
                    acc[i][j] = fmaf(a[i], bb[j], acc[i][j]);
        }
        if (kt + 1 < nslabs) { STORE(cur ^ 1); __syncthreads(); }
    }

    float* dst = g_biaf4[split] + (long long)b * (MC * MC);
    #pragma unroll
    for (int i = 0; i < 4; i++) {
        int r = ty * 4 + i;
        *(float4*)&dst[r * MC + tx * 8]     = *(float4*)&acc[i][0];
        *(float4*)&dst[r * MC + tx * 8 + 4] = *(float4*)&acc[i][4];
    }
#undef LOAD
#undef STORE
}

// ----- spatial features + folded MLP, 2 key rows per thread ---------------
__global__ __launch_bounds__(128)
void pair_kernel(float* __restrict__ out,
                 const float* __restrict__ Ws1, const float* __restrict__ bs1,
                 const float* __restrict__ Wf1,
                 const float* __restrict__ Wf2, const float* __restrict__ bf2,
                 const float* __restrict__ bbilp) {
    __shared__ float sW1[8 * 64], sb1[64];
    __shared__ float sW2f[64 * 16], sb2f[16];
    __shared__ float sF0[16], sF2[16];
    __shared__ float sbf2, sbil;
    __shared__ float kb[2][4];
    __shared__ float srowk[2];

    int b = blockIdx.y;
    int i0 = blockIdx.x * 2;
    int j = threadIdx.x;

    for (int t = j; t < 512;  t += 128) sW1[t] = Ws1[t];
    for (int t = j; t < 1024; t += 128) sW2f[t] = g_W2f[t];
    if (j < 64) sb1[j] = bs1[j];
    if (j < 16) { sb2f[j] = g_b2f[j]; sF0[j] = Wf1[j]; sF2[j] = Wf2[j]; }
    if (j == 0) { sbf2 = bf2[0]; sbil = bbilp[0]; }
    if (j < 2)  srowk[j] = g_rowk[b * MC + i0 + j];
    if (j < 8)  kb[j >> 2][j & 3] = g_kbox[(b * MC + i0 + (j >> 2)) * 4 + (j & 3)];
    __syncthreads();

    float vx1 = g_vbox[(b * MC + j) * 4 + 0];
    float vy1 = g_vbox[(b * MC + j) * 4 + 1];
    float vx2 = g_vbox[(b * MC + j) * 4 + 2];
    float vy2 = g_vbox[(b * MC + j) * 4 + 3];
    float vcx = (vx1 + vx2) * 0.5f, vcy = (vy1 + vy2) * 0.5f;
    float vh = vy2 - vy1, vw = vx2 - vx1;

    float sfa[2][8];
    #pragma unroll
    for (int s = 0; s < 2; s++) {
        float kx1 = kb[s][0], ky1 = kb[s][1], kx2 = kb[s][2], ky2 = kb[s][3];
        float kcx = (kx1 + kx2) * 0.5f, kcy = (ky1 + ky2) * 0.5f;
        float dx = vcx - kcx, dy = vcy - kcy;
        float dist  = sqrtf(dx * dx + dy * dy + EPSF);
        float angle = atan2f(dy, dx);
        float kh = ky2 - ky1, kw = kx2 - kx1;
        float h_ov = fmaxf(fminf(ky2, vy2) - fmaxf(ky1, vy1), 0.0f);
        float h_align = h_ov / (fminf(kh, vh) + EPSF);
        float v_ov = fmaxf(fminf(kx2, vx2) - fmaxf(kx1, vx1), 0.0f);
        float v_align = v_ov / (fminf(kw, vw) + EPSF);
        float area_ratio   = (vh * vw) / (kh * kw + EPSF);
        float aspect_ratio = (vw / (vh + EPSF)) / (kw / (kh + EPSF));
        sfa[s][0] = dx; sfa[s][1] = dy; sfa[s][2] = dist; sfa[s][3] = angle;
        sfa[s][4] = h_align; sfa[s][5] = v_align;
        sfa[s][6] = area_ratio; sfa[s][7] = aspect_ratio;
    }

    float rowvj = g_rowv[b * MC + j];
    long long bidx0 = (long long)b * (MC * MC) + i0 * MC + j;
    long long bidx1 = bidx0 + MC;
    float biaf0 = srowk[0] + rowvj + sbil;
    float biaf1 = srowk[1] + rowvj + sbil;
    #pragma unroll
    for (int s = 0; s < 4; s++) {
        biaf0 += g_biaf4[s][bidx0];
        biaf1 += g_biaf4[s][bidx1];
    }

    float f1a[16], f1b[16];
    #pragma unroll
    for (int t = 0; t < 16; t++) {
        float f0 = sF0[t], bb = sb2f[t];
        f1a[t] = fmaf(biaf0, f0, bb);
        f1b[t] = fmaf(biaf1, f0, bb);
    }

    for (int u = 0; u < 64; u++) {
        float h0 = sb1[u], h1 = h0;
        #pragma unroll
        for (int f = 0; f < 8; f++) {
            float w = sW1[f * 64 + u];
            h0 = fmaf(sfa[0][f], w, h0);
            h1 = fmaf(sfa[1][f], w, h1);
        }
        h0 = fmaxf(h0, 0.0f);
        h1 = fmaxf(h1, 0.0f);
        #pragma unroll
        for (int t = 0; t < 16; t++) {
            float w2 = sW2f[u * 16 + t];
            f1a[t] = fmaf(h0, w2, f1a[t]);
            f1b[t] = fmaf(h1, w2, f1b[t]);
        }
    }

    float s0 = sbf2, s1 = sbf2;
    #pragma unroll
    for (int t = 0; t < 16; t++) {
        float w = sF2[t];
        s0 = fmaf(fmaxf(f1a[t], 0.0f), w, s0);
        s1 = fmaf(fmaxf(f1b[t], 0.0f), w, s1);
    }

    out[bidx0] = s0;
    out[bidx1] = s1;
}

// ---------------- launch ----------------
extern "C" void kernel_launch(void* const* d_in, const int* in_sizes, int n_in,
                              void* d_out, int out_size) {
    (void)in_sizes; (void)n_in; (void)out_size;
    const float* seq    = (const float*)d_in[0];
    const float* logits = (const float*)d_in[1];
    const float* bboxes = (const float*)d_in[2];
    const int*   mask   = (const int*)  d_in[3];
    const float* Wk  = (const float*)d_in[4];
    const float* bk  = (const float*)d_in[5];
    const float* Wv  = (const float*)d_in[6];
    const float* bv  = (const float*)d_in[7];
    const float* Wbil= (const float*)d_in[8];
    const float* bbil= (const float*)d_in[9];
    const float* Ws1 = (const float*)d_in[10];
    const float* bs1 = (const float*)d_in[11];
    const float* Ws2 = (const float*)d_in[12];
    const float* bs2 = (const float*)d_in[13];
    const float* Wf1 = (const float*)d_in[14];
    const float* bf1 = (const float*)d_in[15];
    const float* Wf2 = (const float*)d_in[16];
    const float* bf2 = (const float*)d_in[17];
    float* out = (float*)d_out;

    float *pWc2, *pM;
    cudaGetSymbolAddress((void**)&pWc2, g_Wc2);
    cudaGetSymbolAddress((void**)&pM,   g_M);

    cudaMemsetAsync(pWc2, 0, (size_t)HH * HH * sizeof(float));
    cudaMemsetAsync(pM,   0, (size_t)HH * HH * sizeof(float));

    topk_kernel<<<dim3(BB, 2), 512>>>(logits, mask, bboxes, out);
    setupA<<<99, 256>>>(bk, Wbil, bv);
    setupB<<<193, 256>>>(Wv, Wk, bv, Ws2, bs2, Wf1, bf1);

    // Wc2 = Wbil @ Wv^T  (split-K x4, 144 blocks, 256 threads, 8x8)
    nt_atomic<<<dim3(HH / 128, HH / 128, 4), 256>>>(Wbil, Wv, pWc2);
    // M = Wk @ Wc2       (split-K x4, 8x8)
    nn_atomic<<<dim3(HH / 128, HH / 128, 4), 256>>>(Wk, pWc2, pM);

    // u = Gk(seq) @ M   (full K, 192 blocks)
    u_gemm<<<dim3(HH / 128, (BB * MC) / 128), 256>>>(seq, pM);

    // rowk = Gk.p ; rowv = Gv.q + c
    growdot_kernel<<<dim3((BB * MC) / 8, 2), 256>>>(seq);

    // biaffine term1: 4 split buffers
    biaf_splitk<<<dim3(4, BB), 512>>>(seq);

    pair_kernel<<<dim3(MC / 2, BB), 128>>>(out, Ws1, bs1, Wf1, Wf2, bf2, bbil);
}

// round 11
// speedup vs baseline: 1.2633x; 1.0415x over previous
#include <cuda_runtime.h>
#include <math.h>

#define BB 32
#define SS 512
#define HH 768
#define MC 128
#define EPSF 1e-8f
#define TK 16

// ---------------- scratch (static device memory; no allocs) ----------------
__device__ int   g_kidx[BB*MC];
__device__ int   g_vidx[BB*MC];
__device__ float g_kbox[BB*MC*4];
__device__ float g_vbox[BB*MC*4];
__device__ float g_uA[BB*MC*HH];
__device__ float g_uB[BB*MC*HH];
__device__ float g_biaf4[4][BB*MC*MC];
__device__ float g_Wc2s[4][HH*HH]; // Wbil @ Wv^T, 4 K-split partials
__device__ float g_M[HH*HH];       // Wk @ Wc2
__device__ float g_s1[HH];         // bk @ Wbil
__device__ float g_r[HH];          // Wbil @ bv
__device__ float g_q[HH];          // Wv @ s1
__device__ float g_p[HH];          // Wk @ r
__device__ float g_c[1];           // s1 . bv
__device__ float g_rowk[BB*MC];
__device__ float g_rowv[BB*MC];
__device__ float g_W2f[64*16];
__device__ float g_b2f[16];

// -------- 1+2) conf (inline) + exact top-128 of 512 via bitonic sort ------
__global__ void topk_kernel(const float* __restrict__ logits,
                            const int* __restrict__ mask,
                            const float* __restrict__ bboxes,
                            float* __restrict__ out) {
    int b = blockIdx.x;
    int which = blockIdx.y;   // 0 = key, 1 = val
    __shared__ float sc[512];
    __shared__ int   si[512];
    int tid = threadIdx.x;

    {   // inline confidence
        int t = b * SS + tid;
        float l0 = logits[3*t+0], l1 = logits[3*t+1], l2 = logits[3*t+2];
        int pred = 0; float best = l0;
        if (l1 > best) { pred = 1; best = l1; }
        if (l2 > best) { pred = 2; best = l2; }
        float e0 = expf(l0 - best), e1 = expf(l1 - best), e2 = expf(l2 - best);
        float inv = 1.0f / (e0 + e1 + e2);
        bool valid = (mask[t] == 1);
        float conf;
        if (which == 0) conf = (pred == 1 && valid) ? e1 * inv : -INFINITY;
        else            conf = (pred == 2 && valid) ? e2 * inv : -INFINITY;
        sc[tid] = conf; si[tid] = tid;
    }

    for (int k = 2; k <= 512; k <<= 1) {
        for (int j = k >> 1; j > 0; j >>= 1) {
            __syncthreads();
            int ixj = tid ^ j;
            if (ixj > tid) {
                float c1 = sc[tid], c2 = sc[ixj];
                int   i1 = si[tid], i2 = si[ixj];
                bool b2 = (c2 > c1) || (c2 == c1 && i2 < i1);
                bool doswap = ((tid & k) == 0) ? b2 : !b2;
                if (doswap) {
                    sc[tid] = c2; si[tid] = i2;
                    sc[ixj] = c1; si[ixj] = i1;
                }
            }
        }
    }
    __syncthreads();

    if (tid < MC) {
        int   idx = si[tid];
        float cf  = sc[tid];
        int*   gi = (which == 0) ? g_kidx : g_vidx;
        float* gb = (which == 0) ? g_kbox : g_vbox;
        gi[b * MC + tid] = idx;
        const float* src = bboxes + ((long long)b * SS + idx) * 4;
        float* dst = gb + (b * MC + tid) * 4;
        dst[0] = src[0]; dst[1] = src[1]; dst[2] = src[2]; dst[3] = src[3];
        long long base = (long long)BB * MC * MC;            // 524288
        float vf = (cf != -INFINITY) ? 1.0f : 0.0f;
        out[base + (long long)which * (BB * MC) + b * MC + tid] = vf;
        out[base + 2LL * (BB * MC) + (long long)which * (BB * MC) + b * MC + tid] = (float)idx;
    }
}

// ---------------- setupA: s1 = bk @ Wbil ; r = Wbil @ bv -------------------
__global__ void setupA(const float* __restrict__ bk,
                       const float* __restrict__ Wbil,
                       const float* __restrict__ bv) {
    int bx = blockIdx.x, tid = threadIdx.x;
    if (bx < 3) {
        int j = bx * 256 + tid;
        float s = 0.f;
        for (int h = 0; h < HH; h++) s = fmaf(bk[h], Wbil[h * HH + j], s);
        g_s1[j] = s;
    } else {
        int row = (bx - 3) * 8 + (tid >> 5);
        int lane = tid & 31;
        const float* rp = Wbil + (long long)row * HH;
        float s = 0.f;
        #pragma unroll 4
        for (int cdx = lane; cdx < HH; cdx += 32) s = fmaf(rp[cdx], bv[cdx], s);
        #pragma unroll
        for (int o = 16; o; o >>= 1) s += __shfl_xor_sync(0xffffffffu, s, o);
        if (lane == 0) g_r[row] = s;
    }
}

// -------- setupB: q = Wv@s1 ; p = Wk@r ; c = s1.bv ; MLP fold --------------
__global__ void setupB(const float* __restrict__ Wv, const float* __restrict__ Wk,
                       const float* __restrict__ bv,
                       const float* __restrict__ Ws2, const float* __restrict__ bs2,
                       const float* __restrict__ Wf1, const float* __restrict__ bf1) {
    int bx = blockIdx.x, tid = threadIdx.x;
    if (bx < 192) {
        const float* A   = (bx < 96) ? Wv : Wk;
        const float* x   = (bx < 96) ? g_s1 : g_r;
        float* outv      = (bx < 96) ? g_q : g_p;
        int row = ((bx < 96) ? bx : bx - 96) * 8 + (tid >> 5);
        int lane = tid & 31;
        const float* rp = A + (long long)row * HH;
        float s = 0.f;
        #pragma unroll 4
        for (int cdx = lane; cdx < HH; cdx += 32) s = fmaf(rp[cdx], x[cdx], s);
        #pragma unroll
        for (int o = 16; o; o >>= 1) s += __shfl_xor_sync(0xffffffffu, s, o);
        if (lane == 0) outv[row] = s;
    } else {
        #pragma unroll
        for (int e = 0; e < 4; e++) {
            int o = tid * 4 + e;
            if (o < 1024) {
                int u = o >> 4, t = o & 15;
                float s = 0.f;
                #pragma unroll
                for (int s2 = 0; s2 < 32; s2++)
                    s = fmaf(Ws2[u * 32 + s2], Wf1[(s2 + 1) * 16 + t], s);
                g_W2f[o] = s;
            }
        }
        if (tid < 16) {
            float s = bf1[tid];
            #pragma unroll
            for (int s2 = 0; s2 < 32; s2++)
                s = fmaf(bs2[s2], Wf1[(s2 + 1) * 16 + tid], s);
            g_b2f[tid] = s;
        }
        __shared__ float red[256];
        float s = 0.f;
        for (int g = tid; g < HH; g += 256) s = fmaf(g_s1[g], bv[g], s);
        red[tid] = s; __syncthreads();
        for (int o = 128; o; o >>= 1) { if (tid < o) red[tid] += red[tid + o]; __syncthreads(); }
        if (tid == 0) g_c[0] = red[0];
    }
}

// ------ NT split-K x4, plain stores to 4 buffers: Wc2_s = Wbil @ Wv^T ------
__global__ __launch_bounds__(256)
void nt_split(const float* __restrict__ A, const float* __restrict__ B) {
    __shared__ __align__(16) float As[2][TK][132];
    __shared__ __align__(16) float Bs[2][TK][132];
    const int nslabs = 12;
    int tid = threadIdx.x;
    int tx = tid & 15, ty = tid >> 4;
    int m0 = blockIdx.y * 128, n0 = blockIdx.x * 128;
    int split = blockIdx.z;
    int kbase = split * nslabs * TK;
    int ar0 = tid >> 2, ak = (tid & 3) * 4, ar1 = ar0 + 64;

    float4 a0v, a1v, b0v, b1v;
#define LOAD(K0) do { \
        a0v = *(const float4*)(A + (long long)(m0 + ar0) * HH + (K0) + ak); \
        a1v = *(const float4*)(A + (long long)(m0 + ar1) * HH + (K0) + ak); \
        b0v = *(const float4*)(B + (long long)(n0 + ar0) * HH + (K0) + ak); \
        b1v = *(const float4*)(B + (long long)(n0 + ar1) * HH + (K0) + ak); \
    } while (0)
#define STORE(BUF) do { \
        As[BUF][ak+0][ar0] = a0v.x; As[BUF][ak+1][ar0] = a0v.y; \
        As[BUF][ak+2][ar0] = a0v.z; As[BUF][ak+3][ar0] = a0v.w; \
        As[BUF][ak+0][ar1] = a1v.x; As[BUF][ak+1][ar1] = a1v.y; \
        As[BUF][ak+2][ar1] = a1v.z; As[BUF][ak+3][ar1] = a1v.w; \
        Bs[BUF][ak+0][ar0] = b0v.x; Bs[BUF][ak+1][ar0] = b0v.y; \
        Bs[BUF][ak+2][ar0] = b0v.z; Bs[BUF][ak+3][ar0] = b0v.w; \
        Bs[BUF][ak+0][ar1] = b1v.x; Bs[BUF][ak+1][ar1] = b1v.y; \
        Bs[BUF][ak+2][ar1] = b1v.z; Bs[BUF][ak+3][ar1] = b1v.w; \
    } while (0)

    float acc[8][8];
    #pragma unroll
    for (int i = 0; i < 8; i++)
        #pragma unroll
        for (int j = 0; j < 8; j++) acc[i][j] = 0.f;

    LOAD(kbase); STORE(0); __syncthreads();
    for (int kt = 0; kt < nslabs; kt++) {
        int cur = kt & 1;
        if (kt + 1 < nslabs) LOAD(kbase + (kt + 1) * TK);
        #pragma unroll
        for (int kk = 0; kk < TK; kk++) {
            float a[8], b[8];
            *(float4*)(a)     = *(const float4*)&As[cur][kk][ty * 8];
            *(float4*)(a + 4) = *(const float4*)&As[cur][kk][ty * 8 + 4];
            *(float4*)(b)     = *(const float4*)&Bs[cur][kk][tx * 8];
            *(float4*)(b + 4) = *(const float4*)&Bs[cur][kk][tx * 8 + 4];
            #pragma unroll
            for (int i = 0; i < 8; i++)
                #pragma unroll
                for (int j = 0; j < 8; j++)
                    acc[i][j] = fmaf(a[i], b[j], acc[i][j]);
        }
        if (kt + 1 < nslabs) { STORE(cur ^ 1); __syncthreads(); }
    }
    float* C = g_Wc2s[split];
    #pragma unroll
    for (int i = 0; i < 8; i++) {
        long long r = m0 + ty * 8 + i;
        *(float4*)&C[r * HH + n0 + tx * 8]     = *(float4*)&acc[i][0];
        *(float4*)&C[r * HH + n0 + tx * 8 + 4] = *(float4*)&acc[i][4];
    }
#undef LOAD
#undef STORE
}

// ------ NN split-K x4 atomic: M = Wk @ sum(Wc2_s) (8x8, 256 thr) -----------
__global__ __launch_bounds__(256)
void nn_atomic(const float* __restrict__ A, float* __restrict__ C) {
    __shared__ __align__(16) float As[2][TK][132];
    __shared__ __align__(16) float Bs[2][TK][128];
    const int nslabs = 12;
    int tid = threadIdx.x;
    int tx = tid & 15, ty = tid >> 4;
    int m0 = blockIdx.y * 128, c0 = blockIdx.x * 128;
    int kbase = blockIdx.z * nslabs * TK;
    int ar0 = tid >> 2, ak = (tid & 3) * 4, ar1 = ar0 + 64;
    int bk0 = tid >> 5, bcc = (tid & 31) * 4, bk1 = bk0 + 8;

    float4 a0v, a1v, b0v, b1v;
#define LOAD(K0) do { \
        a0v = *(const float4*)(A + (long long)(m0 + ar0) * HH + (K0) + ak); \
        a1v = *(const float4*)(A + (long long)(m0 + ar1) * HH + (K0) + ak); \
        long long o0 = (long long)((K0) + bk0) * HH + c0 + bcc; \
        long long o1 = (long long)((K0) + bk1) * HH + c0 + bcc; \
        float4 t0 = *(const float4*)(g_Wc2s[0] + o0); \
        float4 t1 = *(const float4*)(g_Wc2s[1] + o0); \
        float4 t2 = *(const float4*)(g_Wc2s[2] + o0); \
        float4 t3 = *(const float4*)(g_Wc2s[3] + o0); \
        b0v.x = t0.x + t1.x + t2.x + t3.x; b0v.y = t0.y + t1.y + t2.y + t3.y; \
        b0v.z = t0.z + t1.z + t2.z + t3.z; b0v.w = t0.w + t1.w + t2.w + t3.w; \
        t0 = *(const float4*)(g_Wc2s[0] + o1); \
        t1 = *(const float4*)(g_Wc2s[1] + o1); \
        t2 = *(const float4*)(g_Wc2s[2] + o1); \
        t3 = *(const float4*)(g_Wc2s[3] + o1); \
        b1v.x = t0.x + t1.x + t2.x + t3.x; b1v.y = t0.y + t1.y + t2.y + t3.y; \
        b1v.z = t0.z + t1.z + t2.z + t3.z; b1v.w = t0.w + t1.w + t2.w + t3.w; \
    } while (0)
#define STORE(BUF) do { \
        As[BUF][ak+0][ar0] = a0v.x; As[BUF][ak+1][ar0] = a0v.y; \
        As[BUF][ak+2][ar0] = a0v.z; As[BUF][ak+3][ar0] = a0v.w; \
        As[BUF][ak+0][ar1] = a1v.x; As[BUF][ak+1][ar1] = a1v.y; \
        As[BUF][ak+2][ar1] = a1v.z; As[BUF][ak+3][ar1] = a1v.w; \
        *(float4*)&Bs[BUF][bk0][bcc] = b0v; \
        *(float4*)&Bs[BUF][bk1][bcc] = b1v; \
    } while (0)

    float acc[8][8];
    #pragma unroll
    for (int i = 0; i < 8; i++)
        #pragma unroll
        for (int j = 0; j < 8; j++) acc[i][j] = 0.f;

    LOAD(kbase); STORE(0); __syncthreads();
    for (int kt = 0; kt < nslabs; kt++) {
        int cur = kt & 1;
        if (kt + 1 < nslabs) LOAD(kbase + (kt + 1) * TK);
        #pragma unroll
        for (int kk = 0; kk < TK; kk++) {
            float a[8], b[8];
            *(float4*)(a)     = *(const float4*)&As[cur][kk][ty * 8];
            *(float4*)(a + 4) = *(const float4*)&As[cur][kk][ty * 8 + 4];
            *(float4*)(b)     = *(const float4*)&Bs[cur][kk][tx * 8];
            *(float4*)(b + 4) = *(const float4*)&Bs[cur][kk][tx * 8 + 4];
            #pragma unroll
            for (int i = 0; i < 8; i++)
                #pragma unroll
                for (int j = 0; j < 8; j++)
                    acc[i][j] = fmaf(a[i], b[j], acc[i][j]);
        }
        if (kt + 1 < nslabs) { STORE(cur ^ 1); __syncthreads(); }
    }
    #pragma unroll
    for (int i = 0; i < 8; i++)
        #pragma unroll
        for (int j = 0; j < 8; j++)
            atomicAdd(&C[(long long)(m0 + ty * 8 + i) * HH + c0 + tx * 8 + j], acc[i][j]);
#undef LOAD
#undef STORE
}

// --- u = Gk(seq) @ M : gathered NN, 128x128 tile, 8x8, split-K x2 ----------
__global__ __launch_bounds__(256)
void u_gemm(const float* __restrict__ A, const float* __restrict__ Bm) {
    __shared__ __align__(16) float As[2][TK][132];
    __shared__ __align__(16) float Bs[2][TK][128];
    __shared__ long long rowbase[128];
    const int nslabs = 24;     // 384 K per split

    int tid = threadIdx.x;
    int tx = tid & 15, ty = tid >> 4;
    int m0 = blockIdx.y * 128, c0 = blockIdx.x * 128;
    int kbase = blockIdx.z * nslabs * TK;
    float* C = blockIdx.z ? g_uB : g_uA;

    if (tid < 128) {
        int m = m0 + tid;
        rowbase[tid] = ((long long)(m >> 7) * SS + g_kidx[m]) * HH;
    }
    __syncthreads();

    int ar0 = tid >> 2, ak0 = (tid & 3) * 4, ar1 = ar0 + 64;
    int bk0 = tid >> 5, bc0 = (tid & 31) * 4, bk1 = bk0 + 8;
    long long ra0 = rowbase[ar0];
    long long ra1 = rowbase[ar1];

    float4 a0v, a1v, b0v, b1v;
#define LOAD_REGS(K0) do { \
        a0v = *(const float4*)(A + ra0 + (K0) + ak0); \
        a1v = *(const float4*)(A + ra1 + (K0) + ak0); \
        b0v = *(const float4*)(Bm + (long long)((K0) + bk0) * HH + c0 + bc0); \
        b1v = *(const float4*)(Bm + (long long)((K0) + bk1) * HH + c0 + bc0); \
    } while (0)
#define STORE_SMEM(BUF) do { \
        As[BUF][ak0+0][ar0] = a0v.x; As[BUF][ak0+1][ar0] = a0v.y; \
        As[BUF][ak0+2][ar0] = a0v.z; As[BUF][ak0+3][ar0] = a0v.w; \
        As[BUF][ak0+0][ar1] = a1v.x; As[BUF][ak0+1][ar1] = a1v.y; \
        As[BUF][ak0+2][ar1] = a1v.z; As[BUF][ak0+3][ar1] = a1v.w; \
        *(float4*)&Bs[BUF][bk0][bc0] = b0v; \
        *(float4*)&Bs[BUF][bk1][bc0] = b1v; \
    } while (0)

    float acc[8][8];
    #pragma unroll
    for (int i = 0; i < 8; i++)
        #pragma unroll
        for (int j = 0; j < 8; j++) acc[i][j] = 0.0f;

    LOAD_REGS(kbase);
    STORE_SMEM(0);
    __syncthreads();

    for (int kt = 0; kt < nslabs; kt++) {
        int cur = kt & 1;
        if (kt + 1 < nslabs) LOAD_REGS(kbase + (kt + 1) * TK);
        #pragma unroll
        for (int kk = 0; kk < TK; kk++) {
            float a[8], b[8];
            *(float4*)(a)     = *(const float4*)&As[cur][kk][ty * 8];
            *(float4*)(a + 4) = *(const float4*)&As[cur][kk][ty * 8 + 4];
            *(float4*)(b)     = *(const float4*)&Bs[cur][kk][tx * 8];
            *(float4*)(b + 4) = *(const float4*)&Bs[cur][kk][tx * 8 + 4];
            #pragma unroll
            for (int i = 0; i < 8; i++)
                #pragma unroll
                for (int j = 0; j < 8; j++)
                    acc[i][j] = fmaf(a[i], b[j], acc[i][j]);
        }
        if (kt + 1 < nslabs) { STORE_SMEM(cur ^ 1); __syncthreads(); }
    }

    #pragma unroll
    for (int i = 0; i < 8; i++) {
        long long r = m0 + ty * 8 + i;
        *(float4*)&C[r * HH + c0 + tx * 8]     = *(float4*)&acc[i][0];
        *(float4*)&C[r * HH + c0 + tx * 8 + 4] = *(float4*)&acc[i][4];
    }
#undef LOAD_REGS
#undef STORE_SMEM
}

// -------- rowk = Gk.p ; rowv = Gv.q + c  (warp per row) --------------------
__global__ void growdot_kernel(const float* __restrict__ seq) {
    int r = blockIdx.x * 8 + (threadIdx.x >> 5);
    int lane = threadIdx.x & 31;
    int which = blockIdx.y;
    const int* gidx = which ? g_vidx : g_kidx;
    const float* vec = which ? g_q : g_p;
    const float* row = seq + ((long long)(r >> 7) * SS + gidx[r]) * HH;
    float s = 0.f;
    #pragma unroll 4
    for (int cdx = lane; cdx < HH; cdx += 32) s = fmaf(row[cdx], vec[cdx], s);
    #pragma unroll
    for (int o = 16; o; o >>= 1) s += __shfl_xor_sync(0xffffffffu, s, o);
    if (lane == 0) {
        if (which) g_rowv[r] = s + g_c[0];
        else       g_rowk[r] = s;
    }
}

// -- biaffine: biaf4[s][b,i,j] = (uA+uB)[b,i,ks] . Gv_seq[b,j,ks], 8x8@256 --
__global__ __launch_bounds__(256)
void biaf_splitk(const float* __restrict__ seq) {
    __shared__ __align__(16) float As[2][TK][132];
    __shared__ __align__(16) float Bs[2][TK][132];
    __shared__ long long vrowbase[128];
    const int nslabs = 12;
    int b = blockIdx.y;
    int split = blockIdx.x;
    int kbase = split * nslabs * TK;
    int tid = threadIdx.x;
    int tx = tid & 15, ty = tid >> 4;

    const float* A0 = g_uA + (long long)b * MC * HH;
    const float* A1 = g_uB + (long long)b * MC * HH;

    if (tid < 128)
        vrowbase[tid] = ((long long)b * SS + g_vidx[b * MC + tid]) * HH;
    __syncthreads();

    int ar0 = tid >> 2, ak = (tid & 3) * 4, ar1 = ar0 + 64;
    long long vb0 = vrowbase[ar0];
    long long vb1 = vrowbase[ar1];

    float4 a0v, a1v, b0v, b1v;
#define LOAD(K0) do { \
        float4 x0 = *(const float4*)(A0 + (long long)ar0 * HH + (K0) + ak); \
        float4 x1 = *(const float4*)(A1 + (long long)ar0 * HH + (K0) + ak); \
        a0v.x = x0.x + x1.x; a0v.y = x0.y + x1.y; a0v.z = x0.z + x1.z; a0v.w = x0.w + x1.w; \
        x0 = *(const float4*)(A0 + (long long)ar1 * HH + (K0) + ak); \
        x1 = *(const float4*)(A1 + (long long)ar1 * HH + (K0) + ak); \
        a1v.x = x0.x + x1.x; a1v.y = x0.y + x1.y; a1v.z = x0.z + x1.z; a1v.w = x0.w + x1.w; \
        b0v = *(const float4*)(seq + vb0 + (K0) + ak); \
        b1v = *(const float4*)(seq + vb1 + (K0) + ak); \
    } while (0)
#define STORE(BUF) do { \
        As[BUF][ak+0][ar0] = a0v.x; As[BUF][ak+1][ar0] = a0v.y; \
        As[BUF][ak+2][ar0] = a0v.z; As[BUF][ak+3][ar0] = a0v.w; \
        As[BUF][ak+0][ar1] = a1v.x; As[BUF][ak+1][ar1] = a1v.y; \
        As[BUF][ak+2][ar1] = a1v.z; As[BUF][ak+3][ar1] = a1v.w; \
        Bs[BUF][ak+0][ar0] = b0v.x; Bs[BUF][ak+1][ar0] = b0v.y; \
        Bs[BUF][ak+2][ar0] = b0v.z; Bs[BUF][ak+3][ar0] = b0v.w; \
        Bs[BUF][ak+0][ar1] = b1v.x; Bs[BUF][ak+1][ar1] = b1v.y; \
        Bs[BUF][ak+2][ar1] = b1v.z; Bs[BUF][ak+3][ar1] = b1v.w; \
    } while (0)

    float acc[8][8];
    #pragma unroll
    for (int i = 0; i < 8; i++)
        #pragma unroll
        for (int j = 0; j < 8; j++) acc[i][j] = 0.f;

    LOAD(kbase); STORE(0); __syncthreads();
    for (int kt = 0; kt < nslabs; kt++) {
        int cur = kt & 1;
        if (kt + 1 < nslabs) LOAD(kbase + (kt + 1) * TK);
        #pragma unroll
        for (int kk = 0; kk < TK; kk++) {
            float a[8], bb[8];
            *(float4*)(a)      = *(const float4*)&As[cur][kk][ty * 8];
            *(float4*)(a + 4)  = *(const float4*)&As[cur][kk][ty * 8 + 4];
            *(float4*)(bb)     = *(const float4*)&Bs[cur][kk][tx * 8];
            *(float4*)(bb + 4) = *(const float4*)&Bs[cur][kk][tx * 8 + 4];
            #pragma unroll
            for (int i = 0; i < 8; i++)
                #pragma unroll
                for (int j = 0; j < 8; j++)
                    acc[i][j] = fmaf(a[i], bb[j], acc[i][j]);
        }
        if (kt + 1 < nslabs) { STORE(cur ^ 1); __syncthreads(); }
    }

    float* dst = g_biaf4[split] + (long long)b * (MC * MC);
    #pragma unroll
    for (int i = 0; i < 8; i++) {
        int r = ty * 8 + i;
        *(float4*)&dst[r * MC + tx * 8]     = *(float4*)&acc[i][0];
        *(float4*)&dst[r * MC + tx * 8 + 4] = *(float4*)&acc[i][4];
    }
#undef LOAD
#undef STORE
}

// ----- spatial features + folded MLP, 2 key rows per thread ---------------
__global__ __launch_bounds__(128)
void pair_kernel(float* __restrict__ out,
                 const float* __restrict__ Ws1, const float* __restrict__ bs1,
                 const float* __restrict__ Wf1,
                 const float* __restrict__ Wf2, const float* __restrict__ bf2,
                 const float* __restrict__ bbilp) {
    __shared__ float sW1[8 * 64], sb1[64];
    __shared__ float sW2f[64 * 16], sb2f[16];
    __shared__ float sF0[16], sF2[16];
    __shared__ float sbf2, sbil;
    __shared__ float kb[2][4];
    __shared__ float srowk[2];

    int b = blockIdx.y;
    int i0 = blockIdx.x * 2;
    int j = threadIdx.x;

    for (int t = j; t < 512;  t += 128) sW1[t] = Ws1[t];
    for (int t = j; t < 1024; t += 128) sW2f[t] = g_W2f[t];
    if (j < 64) sb1[j] = bs1[j];
    if (j < 16) { sb2f[j] = g_b2f[j]; sF0[j] = Wf1[j]; sF2[j] = Wf2[j]; }
    if (j == 0) { sbf2 = bf2[0]; sbil = bbilp[0]; }
    if (j < 2)  srowk[j] = g_rowk[b * MC + i0 + j];
    if (j < 8)  kb[j >> 2][j & 3] = g_kbox[(b * MC + i0 + (j >> 2)) * 4 + (j & 3)];
    __syncthreads();

    float vx1 = g_vbox[(b * MC + j) * 4 + 0];
    float vy1 = g_vbox[(b * MC + j) * 4 + 1];
    float vx2 = g_vbox[(b * MC + j) * 4 + 2];
    float vy2 = g_vbox[(b * MC + j) * 4 + 3];
    float vcx = (vx1 + vx2) * 0.5f, vcy = (vy1 + vy2) * 0.5f;
    float vh = vy2 - vy1, vw = vx2 - vx1;

    float sfa[2][8];
    #pragma unroll
    for (int s = 0; s < 2; s++) {
        float kx1 = kb[s][0], ky1 = kb[s][1], kx2 = kb[s][2], ky2 = kb[s][3];
        float kcx = (kx1 + kx2) * 0.5f, kcy = (ky1 + ky2) * 0.5f;
        float dx = vcx - kcx, dy = vcy - kcy;
        float dist  = sqrtf(dx * dx + dy * dy + EPSF);
        float angle = atan2f(dy, dx);
        float kh = ky2 - ky1, kw = kx2 - kx1;
        float h_ov = fmaxf(fminf(ky2, vy2) - fmaxf(ky1, vy1), 0.0f);
        float h_align = h_ov / (fminf(kh, vh) + EPSF);
        float v_ov = fmaxf(fminf(kx2, vx2) - fmaxf(kx1, vx1), 0.0f);
        float v_align = v_ov / (fminf(kw, vw) + EPSF);
        float area_ratio   = (vh * vw) / (kh * kw + EPSF);
        float aspect_ratio = (vw / (vh + EPSF)) / (kw / (kh + EPSF));
        sfa[s][0] = dx; sfa[s][1] = dy; sfa[s][2] = dist; sfa[s][3] = angle;
        sfa[s][4] = h_align; sfa[s][5] = v_align;
        sfa[s][6] = area_ratio; sfa[s][7] = aspect_ratio;
    }

    float rowvj = g_rowv[b * MC + j];
    long long bidx0 = (long long)b * (MC * MC) + i0 * MC + j;
    long long bidx1 = bidx0 + MC;
    float biaf0 = srowk[0] + rowvj + sbil;
    float biaf1 = srowk[1] + rowvj + sbil;
    #pragma unroll
    for (int s = 0; s < 4; s++) {
        biaf0 += g_biaf4[s][bidx0];
        biaf1 += g_biaf4[s][bidx1];
    }

    float f1a[16], f1b[16];
    #pragma unroll
    for (int t = 0; t < 16; t++) {
        float f0 = sF0[t], bb = sb2f[t];
        f1a[t] = fmaf(biaf0, f0, bb);
        f1b[t] = fmaf(biaf1, f0, bb);
    }

    for (int u = 0; u < 64; u++) {
        float h0 = sb1[u], h1 = h0;
        #pragma unroll
        for (int f = 0; f < 8; f++) {
            float w = sW1[f * 64 + u];
            h0 = fmaf(sfa[0][f], w, h0);
            h1 = fmaf(sfa[1][f], w, h1);
        }
        h0 = fmaxf(h0, 0.0f);
        h1 = fmaxf(h1, 0.0f);
        #pragma unroll
        for (int t = 0; t < 16; t++) {
            float w2 = sW2f[u * 16 + t];
            f1a[t] = fmaf(h0, w2, f1a[t]);
            f1b[t] = fmaf(h1, w2, f1b[t]);
        }
    }

    float s0 = sbf2, s1 = sbf2;
    #pragma unroll
    for (int t = 0; t < 16; t++) {
        float w = sF2[t];
        s0 = fmaf(fmaxf(f1a[t], 0.0f), w, s0);
        s1 = fmaf(fmaxf(f1b[t], 0.0f), w, s1);
    }

    out[bidx0] = s0;
    out[bidx1] = s1;
}

// ---------------- launch ----------------
extern "C" void kernel_launch(void* const* d_in, const int* in_sizes, int n_in,
                              void* d_out, int out_size) {
    (void)in_sizes; (void)n_in; (void)out_size;
    const float* seq    = (const float*)d_in[0];
    const float* logits = (const float*)d_in[1];
    const float* bboxes = (const float*)d_in[2];
    const int*   mask   = (const int*)  d_in[3];
    const float* Wk  = (const float*)d_in[4];
    const float* bk  = (const float*)d_in[5];
    const float* Wv  = (const float*)d_in[6];
    const float* bv  = (const float*)d_in[7];
    const float* Wbil= (const float*)d_in[8];
    const float* bbil= (const float*)d_in[9];
    const float* Ws1 = (const float*)d_in[10];
    const float* bs1 = (const float*)d_in[11];
    const float* Ws2 = (const float*)d_in[12];
    const float* bs2 = (const float*)d_in[13];
    const float* Wf1 = (const float*)d_in[14];
    const float* bf1 = (const float*)d_in[15];
    const float* Wf2 = (const float*)d_in[16];
    const float* bf2 = (const float*)d_in[17];
    float* out = (float*)d_out;

    float *pM;
    cudaGetSymbolAddress((void**)&pM, g_M);
    cudaMemsetAsync(pM, 0, (size_t)HH * HH * sizeof(float));

    topk_kernel<<<dim3(BB, 2), 512>>>(logits, mask, bboxes, out);
    setupA<<<99, 256>>>(bk, Wbil, bv);
    setupB<<<193, 256>>>(Wv, Wk, bv, Ws2, bs2, Wf1, bf1);

    // Wc2 split buffers = Wbil @ Wv^T  (split-K x4, plain stores)
    nt_split<<<dim3(HH / 128, HH / 128, 4), 256>>>(Wbil, Wv);
    // M = Wk @ sum(Wc2_s)  (split-K x4, atomics)
    nn_atomic<<<dim3(HH / 128, HH / 128, 4), 256>>>(Wk, pM);

    // u = Gk(seq) @ M   (split-K x2 into uA/uB, 384 blocks)
    u_gemm<<<dim3(HH / 128, (BB * MC) / 128, 2), 256>>>(seq, pM);

    // rowk = Gk.p ; rowv = Gv.q + c
    growdot_kernel<<<dim3((BB * MC) / 8, 2), 256>>>(seq);

    // biaffine term1: 4 split buffers, 8x8@256
    biaf_splitk<<<dim3(4, BB), 256>>>(seq);

    pair_kernel<<<dim3(MC / 2, BB), 128>>>(out, Ws1, bs1, Wf1, Wf2, bf2, bbil);
}

// round 12
// speedup vs baseline: 1.7165x; 1.3588x over previous
#include <cuda_runtime.h>
#include <math.h>
#include <stdint.h>

#define BB 32
#define SS 512
#define HH 768
#define MC 128
#define EPSF 1e-8f
#define TK 16

// ---------------- scratch (static device memory; no allocs) ----------------
__device__ int   g_kidx[BB*MC];
__device__ int   g_vidx[BB*MC];
__device__ float g_kbox[BB*MC*4];
__device__ float g_vbox[BB*MC*4];
__device__ float g_uA[BB*MC*HH];
__device__ float g_uB[BB*MC*HH];
__device__ float g_biaf4[4][BB*MC*MC];
__device__ float g_Wc2s[4][HH*HH]; // Wbil @ Wv^T, 4 K-split partials
__device__ float g_M[HH*HH];       // Wk @ Wc2
__device__ float g_s1[HH];         // bk @ Wbil
__device__ float g_r[HH];          // Wbil @ bv
__device__ float g_q[HH];          // Wv @ s1
__device__ float g_p[HH];          // Wk @ r
__device__ float g_c[1];           // s1 . bv
__device__ float g_rowk[BB*MC];
__device__ float g_rowv[BB*MC];
__device__ float g_W2f[64*16];
__device__ float g_b2f[16];

__device__ __forceinline__ unsigned int f2tf32(float x) {
    unsigned int r;
    asm("cvt.rna.tf32.f32 %0, %1;" : "=r"(r) : "f"(x));
    return r;
}

// -------- 1+2) conf (inline) + exact top-128 of 512 via bitonic sort ------
__global__ void topk_kernel(const float* __restrict__ logits,
                            const int* __restrict__ mask,
                            const float* __restrict__ bboxes,
                            float* __restrict__ out) {
    int b = blockIdx.x;
    int which = blockIdx.y;   // 0 = key, 1 = val
    __shared__ float sc[512];
    __shared__ int   si[512];
    int tid = threadIdx.x;

    {   // inline confidence
        int t = b * SS + tid;
        float l0 = logits[3*t+0], l1 = logits[3*t+1], l2 = logits[3*t+2];
        int pred = 0; float best = l0;
        if (l1 > best) { pred = 1; best = l1; }
        if (l2 > best) { pred = 2; best = l2; }
        float e0 = expf(l0 - best), e1 = expf(l1 - best), e2 = expf(l2 - best);
        float inv = 1.0f / (e0 + e1 + e2);
        bool valid = (mask[t] == 1);
        float conf;
        if (which == 0) conf = (pred == 1 && valid) ? e1 * inv : -INFINITY;
        else            conf = (pred == 2 && valid) ? e2 * inv : -INFINITY;
        sc[tid] = conf; si[tid] = tid;
    }

    for (int k = 2; k <= 512; k <<= 1) {
        for (int j = k >> 1; j > 0; j >>= 1) {
            __syncthreads();
            int ixj = tid ^ j;
            if (ixj > tid) {
                float c1 = sc[tid], c2 = sc[ixj];
                int   i1 = si[tid], i2 = si[ixj];
                bool b2 = (c2 > c1) || (c2 == c1 && i2 < i1);
                bool doswap = ((tid & k) == 0) ? b2 : !b2;
                if (doswap) {
                    sc[tid] = c2; si[tid] = i2;
                    sc[ixj] = c1; si[ixj] = i1;
                }
            }
        }
    }
    __syncthreads();

    if (tid < MC) {
        int   idx = si[tid];
        float cf  = sc[tid];
        int*   gi = (which == 0) ? g_kidx : g_vidx;
        float* gb = (which == 0) ? g_kbox : g_vbox;
        gi[b * MC + tid] = idx;
        const float* src = bboxes + ((long long)b * SS + idx) * 4;
        float* dst = gb + (b * MC + tid) * 4;
        dst[0] = src[0]; dst[1] = src[1]; dst[2] = src[2]; dst[3] = src[3];
        long long base = (long long)BB * MC * MC;            // 524288
        float vf = (cf != -INFINITY) ? 1.0f : 0.0f;
        out[base + (long long)which * (BB * MC) + b * MC + tid] = vf;
        out[base + 2LL * (BB * MC) + (long long)which * (BB * MC) + b * MC + tid] = (float)idx;
    }
}

// ---------------- setupA: s1 = bk @ Wbil ; r = Wbil @ bv -------------------
__global__ void setupA(const float* __restrict__ bk,
                       const float* __restrict__ Wbil,
                       const float* __restrict__ bv) {
    int bx = blockIdx.x, tid = threadIdx.x;
    if (bx < 3) {
        int j = bx * 256 + tid;
        float s = 0.f;
        for (int h = 0; h < HH; h++) s = fmaf(bk[h], Wbil[h * HH + j], s);
        g_s1[j] = s;
    } else {
        int row = (bx - 3) * 8 + (tid >> 5);
        int lane = tid & 31;
        const float* rp = Wbil + (long long)row * HH;
        float s = 0.f;
        #pragma unroll 4
        for (int cdx = lane; cdx < HH; cdx += 32) s = fmaf(rp[cdx], bv[cdx], s);
        #pragma unroll
        for (int o = 16; o; o >>= 1) s += __shfl_xor_sync(0xffffffffu, s, o);
        if (lane == 0) g_r[row] = s;
    }
}

// -------- setupB: q = Wv@s1 ; p = Wk@r ; c = s1.bv ; MLP fold --------------
__global__ void setupB(const float* __restrict__ Wv, const float* __restrict__ Wk,
                       const float* __restrict__ bv,
                       const float* __restrict__ Ws2, const float* __restrict__ bs2,
                       const float* __restrict__ Wf1, const float* __restrict__ bf1) {
    int bx = blockIdx.x, tid = threadIdx.x;
    if (bx < 192) {
        const float* A   = (bx < 96) ? Wv : Wk;
        const float* x   = (bx < 96) ? g_s1 : g_r;
        float* outv      = (bx < 96) ? g_q : g_p;
        int row = ((bx < 96) ? bx : bx - 96) * 8 + (tid >> 5);
        int lane = tid & 31;
        const float* rp = A + (long long)row * HH;
        float s = 0.f;
        #pragma unroll 4
        for (int cdx = lane; cdx < HH; cdx += 32) s = fmaf(rp[cdx], x[cdx], s);
        #pragma unroll
        for (int o = 16; o; o >>= 1) s += __shfl_xor_sync(0xffffffffu, s, o);
        if (lane == 0) outv[row] = s;
    } else {
        #pragma unroll
        for (int e = 0; e < 4; e++) {
            int o = tid * 4 + e;
            if (o < 1024) {
                int u = o >> 4, t = o & 15;
                float s = 0.f;
                #pragma unroll
                for (int s2 = 0; s2 < 32; s2++)
                    s = fmaf(Ws2[u * 32 + s2], Wf1[(s2 + 1) * 16 + t], s);
                g_W2f[o] = s;
            }
        }
        if (tid < 16) {
            float s = bf1[tid];
            #pragma unroll
            for (int s2 = 0; s2 < 32; s2++)
                s = fmaf(bs2[s2], Wf1[(s2 + 1) * 16 + tid], s);
            g_b2f[tid] = s;
        }
        __shared__ float red[256];
        float s = 0.f;
        for (int g = tid; g < HH; g += 256) s = fmaf(g_s1[g], bv[g], s);
        red[tid] = s; __syncthreads();
        for (int o = 128; o; o >>= 1) { if (tid < o) red[tid] += red[tid + o]; __syncthreads(); }
        if (tid == 0) g_c[0] = red[0];
    }
}

// ------ NT split-K x4, plain stores to 4 buffers: Wc2_s = Wbil @ Wv^T ------
__global__ __launch_bounds__(256)
void nt_split(const float* __restrict__ A, const float* __restrict__ B) {
    __shared__ __align__(16) float As[2][TK][132];
    __shared__ __align__(16) float Bs[2][TK][132];
    const int nslabs = 12;
    int tid = threadIdx.x;
    int tx = tid & 15, ty = tid >> 4;
    int m0 = blockIdx.y * 128, n0 = blockIdx.x * 128;
    int split = blockIdx.z;
    int kbase = split * nslabs * TK;
    int ar0 = tid >> 2, ak = (tid & 3) * 4, ar1 = ar0 + 64;

    float4 a0v, a1v, b0v, b1v;
#define LOAD(K0) do { \
        a0v = *(const float4*)(A + (long long)(m0 + ar0) * HH + (K0) + ak); \
        a1v = *(const float4*)(A + (long long)(m0 + ar1) * HH + (K0) + ak); \
        b0v = *(const float4*)(B + (long long)(n0 + ar0) * HH + (K0) + ak); \
        b1v = *(const float4*)(B + (long long)(n0 + ar1) * HH + (K0) + ak); \
    } while (0)
#define STORE(BUF) do { \
        As[BUF][ak+0][ar0] = a0v.x; As[BUF][ak+1][ar0] = a0v.y; \
        As[BUF][ak+2][ar0] = a0v.z; As[BUF][ak+3][ar0] = a0v.w; \
        As[BUF][ak+0][ar1] = a1v.x; As[BUF][ak+1][ar1] = a1v.y; \
        As[BUF][ak+2][ar1] = a1v.z; As[BUF][ak+3][ar1] = a1v.w; \
        Bs[BUF][ak+0][ar0] = b0v.x; Bs[BUF][ak+1][ar0] = b0v.y; \
        Bs[BUF][ak+2][ar0] = b0v.z; Bs[BUF][ak+3][ar0] = b0v.w; \
        Bs[BUF][ak+0][ar1] = b1v.x; Bs[BUF][ak+1][ar1] = b1v.y; \
        Bs[BUF][ak+2][ar1] = b1v.z; Bs[BUF][ak+3][ar1] = b1v.w; \
    } while (0)

    float acc[8][8];
    #pragma unroll
    for (int i = 0; i < 8; i++)
        #pragma unroll
        for (int j = 0; j < 8; j++) acc[i][j] = 0.f;

    LOAD(kbase); STORE(0); __syncthreads();
    for (int kt = 0; kt < nslabs; kt++) {
        int cur = kt & 1;
        if (kt + 1 < nslabs) LOAD(kbase + (kt + 1) * TK);
        #pragma unroll
        for (int kk = 0; kk < TK; kk++) {
            float a[8], b[8];
            *(float4*)(a)     = *(const float4*)&As[cur][kk][ty * 8];
            *(float4*)(a + 4) = *(const float4*)&As[cur][kk][ty * 8 + 4];
            *(float4*)(b)     = *(const float4*)&Bs[cur][kk][tx * 8];
            *(float4*)(b + 4) = *(const float4*)&Bs[cur][kk][tx * 8 + 4];
            #pragma unroll
            for (int i = 0; i < 8; i++)
                #pragma unroll
                for (int j = 0; j < 8; j++)
                    acc[i][j] = fmaf(a[i], b[j], acc[i][j]);
        }
        if (kt + 1 < nslabs) { STORE(cur ^ 1); __syncthreads(); }
    }
    float* C = g_Wc2s[split];
    #pragma unroll
    for (int i = 0; i < 8; i++) {
        long long r = m0 + ty * 8 + i;
        *(float4*)&C[r * HH + n0 + tx * 8]     = *(float4*)&acc[i][0];
        *(float4*)&C[r * HH + n0 + tx * 8 + 4] = *(float4*)&acc[i][4];
    }
#undef LOAD
#undef STORE
}

// ------ NN split-K x4 atomic: M = Wk @ sum(Wc2_s) (8x8, 256 thr) -----------
__global__ __launch_bounds__(256)
void nn_atomic(const float* __restrict__ A, float* __restrict__ C) {
    __shared__ __align__(16) float As[2][TK][132];
    __shared__ __align__(16) float Bs[2][TK][128];
    const int nslabs = 12;
    int tid = threadIdx.x;
    int tx = tid & 15, ty = tid >> 4;
    int m0 = blockIdx.y * 128, c0 = blockIdx.x * 128;
    int kbase = blockIdx.z * nslabs * TK;
    int ar0 = tid >> 2, ak = (tid & 3) * 4, ar1 = ar0 + 64;
    int bk0 = tid >> 5, bcc = (tid & 31) * 4, bk1 = bk0 + 8;

    float4 a0v, a1v, b0v, b1v;
#define LOAD(K0) do { \
        a0v = *(const float4*)(A + (long long)(m0 + ar0) * HH + (K0) + ak); \
        a1v = *(const float4*)(A + (long long)(m0 + ar1) * HH + (K0) + ak); \
        long long o0 = (long long)((K0) + bk0) * HH + c0 + bcc; \
        long long o1 = (long long)((K0) + bk1) * HH + c0 + bcc; \
        float4 t0 = *(const float4*)(g_Wc2s[0] + o0); \
        float4 t1 = *(const float4*)(g_Wc2s[1] + o0); \
        float4 t2 = *(const float4*)(g_Wc2s[2] + o0); \
        float4 t3 = *(const float4*)(g_Wc2s[3] + o0); \
        b0v.x = t0.x + t1.x + t2.x + t3.x; b0v.y = t0.y + t1.y + t2.y + t3.y; \
        b0v.z = t0.z + t1.z + t2.z + t3.z; b0v.w = t0.w + t1.w + t2.w + t3.w; \
        t0 = *(const float4*)(g_Wc2s[0] + o1); \
        t1 = *(const float4*)(g_Wc2s[1] + o1); \
        t2 = *(const float4*)(g_Wc2s[2] + o1); \
        t3 = *(const float4*)(g_Wc2s[3] + o1); \
        b1v.x = t0.x + t1.x + t2.x + t3.x; b1v.y = t0.y + t1.y + t2.y + t3.y; \
        b1v.z = t0.z + t1.z + t2.z + t3.z; b1v.w = t0.w + t1.w + t2.w + t3.w; \
    } while (0)
#define STORE(BUF) do { \
        As[BUF][ak+0][ar0] = a0v.x; As[BUF][ak+1][ar0] = a0v.y; \
        As[BUF][ak+2][ar0] = a0v.z; As[BUF][ak+3][ar0] = a0v.w; \
        As[BUF][ak+0][ar1] = a1v.x; As[BUF][ak+1][ar1] = a1v.y; \
        As[BUF][ak+2][ar1] = a1v.z; As[BUF][ak+3][ar1] = a1v.w; \
        *(float4*)&Bs[BUF][bk0][bcc] = b0v; \
        *(float4*)&Bs[BUF][bk1][bcc] = b1v; \
    } while (0)

    float acc[8][8];
    #pragma unroll
    for (int i = 0; i < 8; i++)
        #pragma unroll
        for (int j = 0; j < 8; j++) acc[i][j] = 0.f;

    LOAD(kbase); STORE(0); __syncthreads();
    for (int kt = 0; kt < nslabs; kt++) {
        int cur = kt & 1;
        if (kt + 1 < nslabs) LOAD(kbase + (kt + 1) * TK);
        #pragma unroll
        for (int kk = 0; kk < TK; kk++) {
            float a[8], b[8];
            *(float4*)(a)     = *(const float4*)&As[cur][kk][ty * 8];
            *(float4*)(a + 4) = *(const float4*)&As[cur][kk][ty * 8 + 4];
            *(float4*)(b)     = *(const float4*)&Bs[cur][kk][tx * 8];
            *(float4*)(b + 4) = *(const float4*)&Bs[cur][kk][tx * 8 + 4];
            #pragma unroll
            for (int i = 0; i < 8; i++)
                #pragma unroll
                for (int j = 0; j < 8; j++)
                    acc[i][j] = fmaf(a[i], b[j], acc[i][j]);
        }
        if (kt + 1 < nslabs) { STORE(cur ^ 1); __syncthreads(); }
    }
    #pragma unroll
    for (int i = 0; i < 8; i++)
        #pragma unroll
        for (int j = 0; j < 8; j++)
            atomicAdd(&C[(long long)(m0 + ty * 8 + i) * HH + c0 + tx * 8 + j], acc[i][j]);
#undef LOAD
#undef STORE
}

// --- u = Gk(seq) @ M : tf32 mma.sync, 128x128 tile, split-K x2 -------------
__global__ __launch_bounds__(256)
void u_gemm_tf32(const float* __restrict__ A, const float* __restrict__ Bm) {
    __shared__ __align__(16) float As[2][TK][136];  // [k][m], tf32 bits
    __shared__ __align__(16) float Bs[2][TK][136];  // [k][n], tf32 bits
    __shared__ long long rowbase[128];
    const int nslabs = 24;     // 384 K per split

    int tid = threadIdx.x;
    int m0 = blockIdx.y * 128, c0 = blockIdx.x * 128;
    int kbase = blockIdx.z * nslabs * TK;
    float* C = blockIdx.z ? g_uB : g_uA;

    if (tid < 128) {
        int m = m0 + tid;
        rowbase[tid] = ((long long)(m >> 7) * SS + g_kidx[m]) * HH;
    }
    __syncthreads();

    // global-load assignments (same as scalar version)
    int ar0 = tid >> 2, ak0 = (tid & 3) * 4, ar1 = ar0 + 64;
    int bk0 = tid >> 5, bc0 = (tid & 31) * 4, bk1 = bk0 + 8;
    long long ra0 = rowbase[ar0];
    long long ra1 = rowbase[ar1];

    float4 a0v, a1v, b0v, b1v;
#define LOAD_REGS(K0) do { \
        a0v = *(const float4*)(A + ra0 + (K0) + ak0); \
        a1v = *(const float4*)(A + ra1 + (K0) + ak0); \
        b0v = *(const float4*)(Bm + (long long)((K0) + bk0) * HH + c0 + bc0); \
        b1v = *(const float4*)(Bm + (long long)((K0) + bk1) * HH + c0 + bc0); \
    } while (0)
#define STORE_SMEM(BUF) do { \
        As[BUF][ak0+0][ar0] = __uint_as_float(f2tf32(a0v.x)); \
        As[BUF][ak0+1][ar0] = __uint_as_float(f2tf32(a0v.y)); \
        As[BUF][ak0+2][ar0] = __uint_as_float(f2tf32(a0v.z)); \
        As[BUF][ak0+3][ar0] = __uint_as_float(f2tf32(a0v.w)); \
        As[BUF][ak0+0][ar1] = __uint_as_float(f2tf32(a1v.x)); \
        As[BUF][ak0+1][ar1] = __uint_as_float(f2tf32(a1v.y)); \
        As[BUF][ak0+2][ar1] = __uint_as_float(f2tf32(a1v.z)); \
        As[BUF][ak0+3][ar1] = __uint_as_float(f2tf32(a1v.w)); \
        float4 cb0, cb1; \
        cb0.x = __uint_as_float(f2tf32(b0v.x)); cb0.y = __uint_as_float(f2tf32(b0v.y)); \
        cb0.z = __uint_as_float(f2tf32(b0v.z)); cb0.w = __uint_as_float(f2tf32(b0v.w)); \
        cb1.x = __uint_as_float(f2tf32(b1v.x)); cb1.y = __uint_as_float(f2tf32(b1v.y)); \
        cb1.z = __uint_as_float(f2tf32(b1v.z)); cb1.w = __uint_as_float(f2tf32(b1v.w)); \
        *(float4*)&Bs[BUF][bk0][bc0] = cb0; \
        *(float4*)&Bs[BUF][bk1][bc0] = cb1; \
    } while (0)

    // warp / fragment indexing
    int wid = tid >> 5;
    int lane = tid & 31;
    int warp_m = wid & 1;          // 0..1 -> 64 rows each
    int warp_n = wid >> 1;         // 0..3 -> 32 cols each
    int mw = warp_m * 64;
    int nw = warp_n * 32;
    int lm = lane >> 2;            // 0..7
    int lk = lane & 3;             // 0..3

    float acc[4][4][4];
    #pragma unroll
    for (int mf = 0; mf < 4; mf++)
        #pragma unroll
        for (int nf = 0; nf < 4; nf++)
            #pragma unroll
            for (int e = 0; e < 4; e++) acc[mf][nf][e] = 0.f;

    LOAD_REGS(kbase);
    STORE_SMEM(0);
    __syncthreads();

    for (int kt = 0; kt < nslabs; kt++) {
        int cur = kt & 1;
        if (kt + 1 < nslabs) LOAD_REGS(kbase + (kt + 1) * TK);
        #pragma unroll
        for (int ks = 0; ks < TK; ks += 8) {
            uint32_t af[4][4];
            #pragma unroll
            for (int mf = 0; mf < 4; mf++) {
                int mb = mw + mf * 16 + lm;
                af[mf][0] = __float_as_uint(As[cur][ks + lk][mb]);
                af[mf][1] = __float_as_uint(As[cur][ks + lk][mb + 8]);
                af[mf][2] = __float_as_uint(As[cur][ks + lk + 4][mb]);
                af[mf][3] = __float_as_uint(As[cur][ks + lk + 4][mb + 8]);
            }
            uint32_t bf[4][2];
            #pragma unroll
            for (int nf = 0; nf < 4; nf++) {
                int nb = nw + nf * 8 + lm;
                bf[nf][0] = __float_as_uint(Bs[cur][ks + lk][nb]);
                bf[nf][1] = __float_as_uint(Bs[cur][ks + lk + 4][nb]);
            }
            #pragma unroll
            for (int mf = 0; mf < 4; mf++)
                #pragma unroll
                for (int nf = 0; nf < 4; nf++) {
                    asm volatile(
                        "mma.sync.aligned.m16n8k8.row.col.f32.tf32.tf32.f32 "
                        "{%0,%1,%2,%3}, {%4,%5,%6,%7}, {%8,%9}, {%0,%1,%2,%3};"
                        : "+f"(acc[mf][nf][0]), "+f"(acc[mf][nf][1]),
                          "+f"(acc[mf][nf][2]), "+f"(acc[mf][nf][3])
                        : "r"(af[mf][0]), "r"(af[mf][1]), "r"(af[mf][2]), "r"(af[mf][3]),
                          "r"(bf[nf][0]), "r"(bf[nf][1]));
                }
        }
        if (kt + 1 < nslabs) { STORE_SMEM(cur ^ 1); __syncthreads(); }
    }

    // epilogue: c0: (row=lane/4, col=2*(lane%4)); c1: col+1; c2/c3: row+8
    #pragma unroll
    for (int mf = 0; mf < 4; mf++) {
        #pragma unroll
        for (int nf = 0; nf < 4; nf++) {
            long long r0 = m0 + mw + mf * 16 + lm;
            long long cc = c0 + nw + nf * 8 + lk * 2;
            float2 v0 = { acc[mf][nf][0], acc[mf][nf][1] };
            float2 v1 = { acc[mf][nf][2], acc[mf][nf][3] };
            *(float2*)&C[r0 * HH + cc]       = v0;
            *(float2*)&C[(r0 + 8) * HH + cc] = v1;
        }
    }
#undef LOAD_REGS
#undef STORE_SMEM
}

// -------- rowk = Gk.p ; rowv = Gv.q + c  (warp per row) --------------------
__global__ void growdot_kernel(const float* __restrict__ seq) {
    int r = blockIdx.x * 8 + (threadIdx.x >> 5);
    int lane = threadIdx.x & 31;
    int which = blockIdx.y;
    const int* gidx = which ? g_vidx : g_kidx;
    const float* vec = which ? g_q : g_p;
    const float* row = seq + ((long long)(r >> 7) * SS + gidx[r]) * HH;
    float s = 0.f;
    #pragma unroll 4
    for (int cdx = lane; cdx < HH; cdx += 32) s = fmaf(row[cdx], vec[cdx], s);
    #pragma unroll
    for (int o = 16; o; o >>= 1) s += __shfl_xor_sync(0xffffffffu, s, o);
    if (lane == 0) {
        if (which) g_rowv[r] = s + g_c[0];
        else       g_rowk[r] = s;
    }
}

// -- biaffine: biaf4[s][b,i,j] = (uA+uB)[b,i,ks] . Gv_seq[b,j,ks], 8x8@256 --
__global__ __launch_bounds__(256)
void biaf_splitk(const float* __restrict__ seq) {
    __shared__ __align__(16) float As[2][TK][132];
    __shared__ __align__(16) float Bs[2][TK][132];
    __shared__ long long vrowbase[128];
    const int nslabs = 12;
    int b = blockIdx.y;
    int split = blockIdx.x;
    int kbase = split * nslabs * TK;
    int tid = threadIdx.x;
    int tx = tid & 15, ty = tid >> 4;

    const float* A0 = g_uA + (long long)b * MC * HH;
    const float* A1 = g_uB + (long long)b * MC * HH;

    if (tid < 128)
        vrowbase[tid] = ((long long)b * SS + g_vidx[b * MC + tid]) * HH;
    __syncthreads();

    int ar0 = tid >> 2, ak = (tid & 3) * 4, ar1 = ar0 + 64;
    long long vb0 = vrowbase[ar0];
    long long vb1 = vrowbase[ar1];

    float4 a0v, a1v, b0v, b1v;
#define LOAD(K0) do { \
        float4 x0 = *(const float4*)(A0 + (long long)ar0 * HH + (K0) + ak); \
        float4 x1 = *(const float4*)(A1 + (long long)ar0 * HH + (K0) + ak); \
        a0v.x = x0.x + x1.x; a0v.y = x0.y + x1.y; a0v.z = x0.z + x1.z; a0v.w = x0.w + x1.w; \
        x0 = *(const float4*)(A0 + (long long)ar1 * HH + (K0) + ak); \
        x1 = *(const float4*)(A1 + (long long)ar1 * HH + (K0) + ak); \
        a1v.x = x0.x + x1.x; a1v.y = x0.y + x1.y; a1v.z = x0.z + x1.z; a1v.w = x0.w + x1.w; \
        b0v = *(const float4*)(seq + vb0 + (K0) + ak); \
        b1v = *(const float4*)(seq + vb1 + (K0) + ak); \
    } while (0)
#define STORE(BUF) do { \
        As[BUF][ak+0][ar0] = a0v.x; As[BUF][ak+1][ar0] = a0v.y; \
        As[BUF][ak+2][ar0] = a0v.z; As[BUF][ak+3][ar0] = a0v.w; \
        As[BUF][ak+0][ar1] = a1v.x; As[BUF][ak+1][ar1] = a1v.y; \
        As[BUF][ak+2][ar1] = a1v.z; As[BUF][ak+3][ar1] = a1v.w; \
        Bs[BUF][ak+0][ar0] = b0v.x; Bs[BUF][ak+1][ar0] = b0v.y; \
        Bs[BUF][ak+2][ar0] = b0v.z; Bs[BUF][ak+3][ar0] = b0v.w; \
        Bs[BUF][ak+0][ar1] = b1v.x; Bs[BUF][ak+1][ar1] = b1v.y; \
        Bs[BUF][ak+2][ar1] = b1v.z; Bs[BUF][ak+3][ar1] = b1v.w; \
    } while (0)

    float acc[8][8];
    #pragma unroll
    for (int i = 0; i < 8; i++)
        #pragma unroll
        for (int j = 0; j < 8; j++) acc[i][j] = 0.f;

    LOAD(kbase); STORE(0); __syncthreads();
    for (int kt = 0; kt < nslabs; kt++) {
        int cur = kt & 1;
        if (kt + 1 < nslabs) LOAD(kbase + (kt + 1) * TK);
        #pragma unroll
        for (int kk = 0; kk < TK; kk++) {
            float a[8], bb[8];
            *(float4*)(a)      = *(const float4*)&As[cur][kk][ty * 8];
            *(float4*)(a + 4)  = *(const float4*)&As[cur][kk][ty * 8 + 4];
            *(float4*)(bb)     = *(const float4*)&Bs[cur][kk][tx * 8];
            *(float4*)(bb + 4) = *(const float4*)&Bs[cur][kk][tx * 8 + 4];
            #pragma unroll
            for (int i = 0; i < 8; i++)
                #pragma unroll
                for (int j = 0; j < 8; j++)
                    acc[i][j] = fmaf(a[i], bb[j], acc[i][j]);
        }
        if (kt + 1 < nslabs) { STORE(cur ^ 1); __syncthreads(); }
    }

    float* dst = g_biaf4[split] + (long long)b * (MC * MC);
    #pragma unroll
    for (int i = 0; i < 8; i++) {
        int r = ty * 8 + i;
        *(float4*)&dst[r * MC + tx * 8]     = *(float4*)&acc[i][0];
        *(float4*)&dst[r * MC + tx * 8 + 4] = *(float4*)&acc[i][4];
    }
#undef LOAD
#undef STORE
}

// ----- spatial features + folded MLP, 2 key rows per thread ---------------
__global__ __launch_bounds__(128)
void pair_kernel(float* __restrict__ out,
                 const float* __restrict__ Ws1, const float* __restrict__ bs1,
                 const float* __restrict__ Wf1,
                 const float* __restrict__ Wf2, const float* __restrict__ bf2,
                 const float* __restrict__ bbilp) {
    __shared__ float sW1[8 * 64], sb1[64];
    __shared__ float sW2f[64 * 16], sb2f[16];
    __shared__ float sF0[16], sF2[16];
    __shared__ float sbf2, sbil;
    __shared__ float kb[2][4];
    __shared__ float srowk[2];

    int b = blockIdx.y;
    int i0 = blockIdx.x * 2;
    int j = threadIdx.x;

    for (int t = j; t < 512;  t += 128) sW1[t] = Ws1[t];
    for (int t = j; t < 1024; t += 128) sW2f[t] = g_W2f[t];
    if (j < 64) sb1[j] = bs1[j];
    if (j < 16) { sb2f[j] = g_b2f[j]; sF0[j] = Wf1[j]; sF2[j] = Wf2[j]; }
    if (j == 0) { sbf2 = bf2[0]; sbil = bbilp[0]; }
    if (j < 2)  srowk[j] = g_rowk[b * MC + i0 + j];
    if (j < 8)  kb[j >> 2][j & 3] = g_kbox[(b * MC + i0 + (j >> 2)) * 4 + (j & 3)];
    __syncthreads();

    float vx1 = g_vbox[(b * MC + j) * 4 + 0];
    float vy1 = g_vbox[(b * MC + j) * 4 + 1];
    float vx2 = g_vbox[(b * MC + j) * 4 + 2];
    float vy2 = g_vbox[(b * MC + j) * 4 + 3];
    float vcx = (vx1 + vx2) * 0.5f, vcy = (vy1 + vy2) * 0.5f;
    float vh = vy2 - vy1, vw = vx2 - vx1;

    float sfa[2][8];
    #pragma unroll
    for (int s = 0; s < 2; s++) {
        float kx1 = kb[s][0], ky1 = kb[s][1], kx2 = kb[s][2], ky2 = kb[s][3];
        float kcx = (kx1 + kx2) * 0.5f, kcy = (ky1 + ky2) * 0.5f;
        float dx = vcx - kcx, dy = vcy - kcy;
        float dist  = sqrtf(dx * dx + dy * dy + EPSF);
        float angle = atan2f(dy, dx);
        float kh = ky2 - ky1, kw = kx2 - kx1;
        float h_ov = fmaxf(fminf(ky2, vy2) - fmaxf(ky1, vy1), 0.0f);
        float h_align = h_ov / (fminf(kh, vh) + EPSF);
        float v_ov = fmaxf(fminf(kx2, vx2) - fmaxf(kx1, vx1), 0.0f);
        float v_align = v_ov / (fminf(kw, vw) + EPSF);
        float area_ratio   = (vh * vw) / (kh * kw + EPSF);
        float aspect_ratio = (vw / (vh + EPSF)) / (kw / (kh + EPSF));
        sfa[s][0] = dx; sfa[s][1] = dy; sfa[s][2] = dist; sfa[s][3] = angle;
        sfa[s][4] = h_align; sfa[s][5] = v_align;
        sfa[s][6] = area_ratio; sfa[s][7] = aspect_ratio;
    }

    float rowvj = g_rowv[b * MC + j];
    long long bidx0 = (long long)b * (MC * MC) + i0 * MC + j;
    long long bidx1 = bidx0 + MC;
    float biaf0 = srowk[0] + rowvj + sbil;
    float biaf1 = srowk[1] + rowvj + sbil;
    #pragma unroll
    for (int s = 0; s < 4; s++) {
        biaf0 += g_biaf4[s][bidx0];
        biaf1 += g_biaf4[s][bidx1];
    }

    float f1a[16], f1b[16];
    #pragma unroll
    for (int t = 0; t < 16; t++) {
        float f0 = sF0[t], bb = sb2f[t];
        f1a[t] = fmaf(biaf0, f0, bb);
        f1b[t] = fmaf(biaf1, f0, bb);
    }

    for (int u = 0; u < 64; u++) {
        float h0 = sb1[u], h1 = h0;
        #pragma unroll
        for (int f = 0; f < 8; f++) {
            float w = sW1[f * 64 + u];
            h0 = fmaf(sfa[0][f], w, h0);
            h1 = fmaf(sfa[1][f], w, h1);
        }
        h0 = fmaxf(h0, 0.0f);
        h1 = fmaxf(h1, 0.0f);
        #pragma unroll
        for (int t = 0; t < 16; t++) {
            float w2 = sW2f[u * 16 + t];
            f1a[t] = fmaf(h0, w2, f1a[t]);
            f1b[t] = fmaf(h1, w2, f1b[t]);
        }
    }

    float s0 = sbf2, s1 = sbf2;
    #pragma unroll
    for (int t = 0; t < 16; t++) {
        float w = sF2[t];
        s0 = fmaf(fmaxf(f1a[t], 0.0f), w, s0);
        s1 = fmaf(fmaxf(f1b[t], 0.0f), w, s1);
    }

    out[bidx0] = s0;
    out[bidx1] = s1;
}

// ---------------- launch ----------------
extern "C" void kernel_launch(void* const* d_in, const int* in_sizes, int n_in,
                              void* d_out, int out_size) {
    (void)in_sizes; (void)n_in; (void)out_size;
    const float* seq    = (const float*)d_in[0];
    const float* logits = (const float*)d_in[1];
    const float* bboxes = (const float*)d_in[2];
    const int*   mask   = (const int*)  d_in[3];
    const float* Wk  = (const float*)d_in[4];
    const float* bk  = (const float*)d_in[5];
    const float* Wv  = (const float*)d_in[6];
    const float* bv  = (const float*)d_in[7];
    const float* Wbil= (const float*)d_in[8];
    const float* bbil= (const float*)d_in[9];
    const float* Ws1 = (const float*)d_in[10];
    const float* bs1 = (const float*)d_in[11];
    const float* Ws2 = (const float*)d_in[12];
    const float* bs2 = (const float*)d_in[13];
    const float* Wf1 = (const float*)d_in[14];
    const float* bf1 = (const float*)d_in[15];
    const float* Wf2 = (const float*)d_in[16];
    const float* bf2 = (const float*)d_in[17];
    float* out = (float*)d_out;

    float *pM;
    cudaGetSymbolAddress((void**)&pM, g_M);
    cudaMemsetAsync(pM, 0, (size_t)HH * HH * sizeof(float));

    topk_kernel<<<dim3(BB, 2), 512>>>(logits, mask, bboxes, out);
    setupA<<<99, 256>>>(bk, Wbil, bv);
    setupB<<<193, 256>>>(Wv, Wk, bv, Ws2, bs2, Wf1, bf1);

    // Wc2 split buffers = Wbil @ Wv^T  (split-K x4, plain stores)
    nt_split<<<dim3(HH / 128, HH / 128, 4), 256>>>(Wbil, Wv);
    // M = Wk @ sum(Wc2_s)  (split-K x4, atomics)
    nn_atomic<<<dim3(HH / 128, HH / 128, 4), 256>>>(Wk, pM);

    // u = Gk(seq) @ M   (tf32 mma, split-K x2 into uA/uB, 384 blocks)
    u_gemm_tf32<<<dim3(HH / 128, (BB * MC) / 128, 2), 256>>>(seq, pM);

    // rowk = Gk.p ; rowv = Gv.q + c
    growdot_kernel<<<dim3((BB * MC) / 8, 2), 256>>>(seq);

    // biaffine term1: 4 split buffers, 8x8@256
    biaf_splitk<<<dim3(4, BB), 256>>>(seq);

    pair_kernel<<<dim3(MC / 2, BB), 128>>>(out, Ws1, bs1, Wf1, Wf2, bf2, bbil);
}

// round 13
// speedup vs baseline: 2.0970x; 1.2217x over previous
#include <cuda_runtime.h>
#include <math.h>
#include <stdint.h>

#define BB 32
#define SS 512
#define HH 768
#define MC 128
#define EPSF 1e-8f
#define TK 16

// ---------------- scratch (static device memory; no allocs) ----------------
__device__ int   g_kidx[BB*MC];
__device__ int   g_vidx[BB*MC];
__device__ float g_kbox[BB*MC*4];
__device__ float g_vbox[BB*MC*4];
__device__ float g_uA[BB*MC*HH];
__device__ float g_uB[BB*MC*HH];
__device__ float g_biaf4[4][BB*MC*MC];
__device__ float g_Wc2s[4][HH*HH]; // Wbil @ Wv^T, 4 K-split partials
__device__ float g_M[HH*HH];       // Wk @ Wc2
__device__ float g_s1[HH];         // bk @ Wbil
__device__ float g_r[HH];          // Wbil @ bv
__device__ float g_q[HH];          // Wv @ s1
__device__ float g_p[HH];          // Wk @ r
__device__ float g_c[1];           // s1 . bv
__device__ float g_rowk[BB*MC];
__device__ float g_rowv[BB*MC];
__device__ float g_W2f[64*16];
__device__ float g_b2f[16];

__device__ __forceinline__ unsigned int f2tf32(float x) {
    unsigned int r;
    asm("cvt.rna.tf32.f32 %0, %1;" : "=r"(r) : "f"(x));
    return r;
}
__device__ __forceinline__ float tf(float x) { return __uint_as_float(f2tf32(x)); }

// ---- shared tf32 fragment compute: needs As/Bs [2][TK][136], cur, ---------
// ---- lane vars (lm, lk, mw, nw), acc[4][4][4] --------------------------
#define TF32_COMPUTE(CUR) do { \
    _Pragma("unroll") \
    for (int ks = 0; ks < TK; ks += 8) { \
        uint32_t af[4][4]; \
        _Pragma("unroll") \
        for (int mf = 0; mf < 4; mf++) { \
            int mb = mw + mf * 16 + lm; \
            af[mf][0] = __float_as_uint(As[CUR][ks + lk][mb]); \
            af[mf][1] = __float_as_uint(As[CUR][ks + lk][mb + 8]); \
            af[mf][2] = __float_as_uint(As[CUR][ks + lk + 4][mb]); \
            af[mf][3] = __float_as_uint(As[CUR][ks + lk + 4][mb + 8]); \
        } \
        uint32_t bf[4][2]; \
        _Pragma("unroll") \
        for (int nf = 0; nf < 4; nf++) { \
            int nb = nw + nf * 8 + lm; \
            bf[nf][0] = __float_as_uint(Bs[CUR][ks + lk][nb]); \
            bf[nf][1] = __float_as_uint(Bs[CUR][ks + lk + 4][nb]); \
        } \
        _Pragma("unroll") \
        for (int mf = 0; mf < 4; mf++) \
            _Pragma("unroll") \
            for (int nf = 0; nf < 4; nf++) { \
                asm volatile( \
                    "mma.sync.aligned.m16n8k8.row.col.f32.tf32.tf32.f32 " \
                    "{%0,%1,%2,%3}, {%4,%5,%6,%7}, {%8,%9}, {%0,%1,%2,%3};" \
                    : "+f"(acc[mf][nf][0]), "+f"(acc[mf][nf][1]), \
                      "+f"(acc[mf][nf][2]), "+f"(acc[mf][nf][3]) \
                    : "r"(af[mf][0]), "r"(af[mf][1]), "r"(af[mf][2]), "r"(af[mf][3]), \
                      "r"(bf[nf][0]), "r"(bf[nf][1])); \
            } \
    } \
} while (0)

#define TF32_DECL_FRAG() \
    int wid = tid >> 5; \
    int lane = tid & 31; \
    int mw = (wid & 1) * 64; \
    int nw = (wid >> 1) * 32; \
    int lm = lane >> 2; \
    int lk = lane & 3; \
    float acc[4][4][4]; \
    _Pragma("unroll") \
    for (int mf = 0; mf < 4; mf++) \
        _Pragma("unroll") \
        for (int nf = 0; nf < 4; nf++) \
            _Pragma("unroll") \
            for (int e = 0; e < 4; e++) acc[mf][nf][e] = 0.f;

// -------- 1+2) conf (inline) + exact top-128 of 512 via bitonic sort ------
__global__ void topk_kernel(const float* __restrict__ logits,
                            const int* __restrict__ mask,
                            const float* __restrict__ bboxes,
                            float* __restrict__ out) {
    int b = blockIdx.x;
    int which = blockIdx.y;   // 0 = key, 1 = val
    __shared__ float sc[512];
    __shared__ int   si[512];
    int tid = threadIdx.x;

    {   // inline confidence
        int t = b * SS + tid;
        float l0 = logits[3*t+0], l1 = logits[3*t+1], l2 = logits[3*t+2];
        int pred = 0; float best = l0;
        if (l1 > best) { pred = 1; best = l1; }
        if (l2 > best) { pred = 2; best = l2; }
        float e0 = expf(l0 - best), e1 = expf(l1 - best), e2 = expf(l2 - best);
        float inv = 1.0f / (e0 + e1 + e2);
        bool valid = (mask[t] == 1);
        float conf;
        if (which == 0) conf = (pred == 1 && valid) ? e1 * inv : -INFINITY;
        else            conf = (pred == 2 && valid) ? e2 * inv : -INFINITY;
        sc[tid] = conf; si[tid] = tid;
    }

    for (int k = 2; k <= 512; k <<= 1) {
        for (int j = k >> 1; j > 0; j >>= 1) {
            __syncthreads();
            int ixj = tid ^ j;
            if (ixj > tid) {
                float c1 = sc[tid], c2 = sc[ixj];
                int   i1 = si[tid], i2 = si[ixj];
                bool b2 = (c2 > c1) || (c2 == c1 && i2 < i1);
                bool doswap = ((tid & k) == 0) ? b2 : !b2;
                if (doswap) {
                    sc[tid] = c2; si[tid] = i2;
                    sc[ixj] = c1; si[ixj] = i1;
                }
            }
        }
    }
    __syncthreads();

    if (tid < MC) {
        int   idx = si[tid];
        float cf  = sc[tid];
        int*   gi = (which == 0) ? g_kidx : g_vidx;
        float* gb = (which == 0) ? g_kbox : g_vbox;
        gi[b * MC + tid] = idx;
        const float* src = bboxes + ((long long)b * SS + idx) * 4;
        float* dst = gb + (b * MC + tid) * 4;
        dst[0] = src[0]; dst[1] = src[1]; dst[2] = src[2]; dst[3] = src[3];
        long long base = (long long)BB * MC * MC;            // 524288
        float vf = (cf != -INFINITY) ? 1.0f : 0.0f;
        out[base + (long long)which * (BB * MC) + b * MC + tid] = vf;
        out[base + 2LL * (BB * MC) + (long long)which * (BB * MC) + b * MC + tid] = (float)idx;
    }
}

// ---------------- setupA: s1 = bk @ Wbil ; r = Wbil @ bv -------------------
__global__ void setupA(const float* __restrict__ bk,
                       const float* __restrict__ Wbil,
                       const float* __restrict__ bv) {
    int bx = blockIdx.x, tid = threadIdx.x;
    if (bx < 3) {
        int j = bx * 256 + tid;
        float s = 0.f;
        for (int h = 0; h < HH; h++) s = fmaf(bk[h], Wbil[h * HH + j], s);
        g_s1[j] = s;
    } else {
        int row = (bx - 3) * 8 + (tid >> 5);
        int lane = tid & 31;
        const float* rp = Wbil + (long long)row * HH;
        float s = 0.f;
        #pragma unroll 4
        for (int cdx = lane; cdx < HH; cdx += 32) s = fmaf(rp[cdx], bv[cdx], s);
        #pragma unroll
        for (int o = 16; o; o >>= 1) s += __shfl_xor_sync(0xffffffffu, s, o);
        if (lane == 0) g_r[row] = s;
    }
}

// -------- setupB: q = Wv@s1 ; p = Wk@r ; c = s1.bv ; MLP fold --------------
__global__ void setupB(const float* __restrict__ Wv, const float* __restrict__ Wk,
                       const float* __restrict__ bv,
                       const float* __restrict__ Ws2, const float* __restrict__ bs2,
                       const float* __restrict__ Wf1, const float* __restrict__ bf1) {
    int bx = blockIdx.x, tid = threadIdx.x;
    if (bx < 192) {
        const float* A   = (bx < 96) ? Wv : Wk;
        const float* x   = (bx < 96) ? g_s1 : g_r;
        float* outv      = (bx < 96) ? g_q : g_p;
        int row = ((bx < 96) ? bx : bx - 96) * 8 + (tid >> 5);
        int lane = tid & 31;
        const float* rp = A + (long long)row * HH;
        float s = 0.f;
        #pragma unroll 4
        for (int cdx = lane; cdx < HH; cdx += 32) s = fmaf(rp[cdx], x[cdx], s);
        #pragma unroll
        for (int o = 16; o; o >>= 1) s += __shfl_xor_sync(0xffffffffu, s, o);
        if (lane == 0) outv[row] = s;
    } else {
        #pragma unroll
        for (int e = 0; e < 4; e++) {
            int o = tid * 4 + e;
            if (o < 1024) {
                int u = o >> 4, t = o & 15;
                float s = 0.f;
                #pragma unroll
                for (int s2 = 0; s2 < 32; s2++)
                    s = fmaf(Ws2[u * 32 + s2], Wf1[(s2 + 1) * 16 + t], s);
                g_W2f[o] = s;
            }
        }
        if (tid < 16) {
            float s = bf1[tid];
            #pragma unroll
            for (int s2 = 0; s2 < 32; s2++)
                s = fmaf(bs2[s2], Wf1[(s2 + 1) * 16 + tid], s);
            g_b2f[tid] = s;
        }
        __shared__ float red[256];
        float s = 0.f;
        for (int g = tid; g < HH; g += 256) s = fmaf(g_s1[g], bv[g], s);
        red[tid] = s; __syncthreads();
        for (int o = 128; o; o >>= 1) { if (tid < o) red[tid] += red[tid + o]; __syncthreads(); }
        if (tid == 0) g_c[0] = red[0];
    }
}

// ------ NT tf32 split-K x4, plain stores: Wc2_s = Wbil @ Wv^T --------------
__global__ __launch_bounds__(256)
void nt_split(const float* __restrict__ A, const float* __restrict__ B) {
    __shared__ __align__(16) float As[2][TK][136];
    __shared__ __align__(16) float Bs[2][TK][136];
    const int nslabs = 12;
    int tid = threadIdx.x;
    int m0 = blockIdx.y * 128, n0 = blockIdx.x * 128;
    int kbase = blockIdx.z * nslabs * TK;
    int ar0 = tid >> 2, ak = (tid & 3) * 4, ar1 = ar0 + 64;

    float4 a0v, a1v, b0v, b1v;
#define LOAD(K0) do { \
        a0v = *(const float4*)(A + (long long)(m0 + ar0) * HH + (K0) + ak); \
        a1v = *(const float4*)(A + (long long)(m0 + ar1) * HH + (K0) + ak); \
        b0v = *(const float4*)(B + (long long)(n0 + ar0) * HH + (K0) + ak); \
        b1v = *(const float4*)(B + (long long)(n0 + ar1) * HH + (K0) + ak); \
    } while (0)
#define STORE(BUF) do { \
        As[BUF][ak+0][ar0] = tf(a0v.x); As[BUF][ak+1][ar0] = tf(a0v.y); \
        As[BUF][ak+2][ar0] = tf(a0v.z); As[BUF][ak+3][ar0] = tf(a0v.w); \
        As[BUF][ak+0][ar1] = tf(a1v.x); As[BUF][ak+1][ar1] = tf(a1v.y); \
        As[BUF][ak+2][ar1] = tf(a1v.z); As[BUF][ak+3][ar1] = tf(a1v.w); \
        Bs[BUF][ak+0][ar0] = tf(b0v.x); Bs[BUF][ak+1][ar0] = tf(b0v.y); \
        Bs[BUF][ak+2][ar0] = tf(b0v.z); Bs[BUF][ak+3][ar0] = tf(b0v.w); \
        Bs[BUF][ak+0][ar1] = tf(b1v.x); Bs[BUF][ak+1][ar1] = tf(b1v.y); \
        Bs[BUF][ak+2][ar1] = tf(b1v.z); Bs[BUF][ak+3][ar1] = tf(b1v.w); \
    } while (0)

    TF32_DECL_FRAG();

    LOAD(kbase); STORE(0); __syncthreads();
    for (int kt = 0; kt < nslabs; kt++) {
        int cur = kt & 1;
        if (kt + 1 < nslabs) LOAD(kbase + (kt + 1) * TK);
        TF32_COMPUTE(cur);
        if (kt + 1 < nslabs) { STORE(cur ^ 1); __syncthreads(); }
    }
    float* C = g_Wc2s[blockIdx.z];
    #pragma unroll
    for (int mf = 0; mf < 4; mf++)
        #pragma unroll
        for (int nf = 0; nf < 4; nf++) {
            long long r0 = m0 + mw + mf * 16 + lm;
            long long cc = n0 + nw + nf * 8 + lk * 2;
            float2 v0 = { acc[mf][nf][0], acc[mf][nf][1] };
            float2 v1 = { acc[mf][nf][2], acc[mf][nf][3] };
            *(float2*)&C[r0 * HH + cc]       = v0;
            *(float2*)&C[(r0 + 8) * HH + cc] = v1;
        }
#undef LOAD
#undef STORE
}

// ------ NN tf32 split-K x4 atomic: M = Wk @ sum(Wc2_s) ---------------------
__global__ __launch_bounds__(256)
void nn_atomic(const float* __restrict__ A, float* __restrict__ C) {
    __shared__ __align__(16) float As[2][TK][136];
    __shared__ __align__(16) float Bs[2][TK][136];
    const int nslabs = 12;
    int tid = threadIdx.x;
    int m0 = blockIdx.y * 128, c0 = blockIdx.x * 128;
    int kbase = blockIdx.z * nslabs * TK;
    int ar0 = tid >> 2, ak = (tid & 3) * 4, ar1 = ar0 + 64;
    int bk0 = tid >> 5, bcc = (tid & 31) * 4, bk1 = bk0 + 8;

    float4 a0v, a1v, b0v, b1v;
#define LOAD(K0) do { \
        a0v = *(const float4*)(A + (long long)(m0 + ar0) * HH + (K0) + ak); \
        a1v = *(const float4*)(A + (long long)(m0 + ar1) * HH + (K0) + ak); \
        long long o0 = (long long)((K0) + bk0) * HH + c0 + bcc; \
        long long o1 = (long long)((K0) + bk1) * HH + c0 + bcc; \
        float4 t0 = *(const float4*)(g_Wc2s[0] + o0); \
        float4 t1 = *(const float4*)(g_Wc2s[1] + o0); \
        float4 t2 = *(const float4*)(g_Wc2s[2] + o0); \
        float4 t3 = *(const float4*)(g_Wc2s[3] + o0); \
        b0v.x = t0.x + t1.x + t2.x + t3.x; b0v.y = t0.y + t1.y + t2.y + t3.y; \
        b0v.z = t0.z + t1.z + t2.z + t3.z; b0v.w = t0.w + t1.w + t2.w + t3.w; \
        t0 = *(const float4*)(g_Wc2s[0] + o1); \
        t1 = *(const float4*)(g_Wc2s[1] + o1); \
        t2 = *(const float4*)(g_Wc2s[2] + o1); \
        t3 = *(const float4*)(g_Wc2s[3] + o1); \
        b1v.x = t0.x + t1.x + t2.x + t3.x; b1v.y = t0.y + t1.y + t2.y + t3.y; \
        b1v.z = t0.z + t1.z + t2.z + t3.z; b1v.w = t0.w + t1.w + t2.w + t3.w; \
    } while (0)
#define STORE(BUF) do { \
        As[BUF][ak+0][ar0] = tf(a0v.x); As[BUF][ak+1][ar0] = tf(a0v.y); \
        As[BUF][ak+2][ar0] = tf(a0v.z); As[BUF][ak+3][ar0] = tf(a0v.w); \
        As[BUF][ak+0][ar1] = tf(a1v.x); As[BUF][ak+1][ar1] = tf(a1v.y); \
        As[BUF][ak+2][ar1] = tf(a1v.z); As[BUF][ak+3][ar1] = tf(a1v.w); \
        float4 cb0, cb1; \
        cb0.x = tf(b0v.x); cb0.y = tf(b0v.y); cb0.z = tf(b0v.z); cb0.w = tf(b0v.w); \
        cb1.x = tf(b1v.x); cb1.y = tf(b1v.y); cb1.z = tf(b1v.z); cb1.w = tf(b1v.w); \
        *(float4*)&Bs[BUF][bk0][bcc] = cb0; \
        *(float4*)&Bs[BUF][bk1][bcc] = cb1; \
    } while (0)

    TF32_DECL_FRAG();

    LOAD(kbase); STORE(0); __syncthreads();
    for (int kt = 0; kt < nslabs; kt++) {
        int cur = kt & 1;
        if (kt + 1 < nslabs) LOAD(kbase + (kt + 1) * TK);
        TF32_COMPUTE(cur);
        if (kt + 1 < nslabs) { STORE(cur ^ 1); __syncthreads(); }
    }
    #pragma unroll
    for (int mf = 0; mf < 4; mf++)
        #pragma unroll
        for (int nf = 0; nf < 4; nf++) {
            long long r0 = m0 + mw + mf * 16 + lm;
            long long cc = c0 + nw + nf * 8 + lk * 2;
            atomicAdd(&C[r0 * HH + cc],           acc[mf][nf][0]);
            atomicAdd(&C[r0 * HH + cc + 1],       acc[mf][nf][1]);
            atomicAdd(&C[(r0 + 8) * HH + cc],     acc[mf][nf][2]);
            atomicAdd(&C[(r0 + 8) * HH + cc + 1], acc[mf][nf][3]);
        }
#undef LOAD
#undef STORE
}

// --- u = Gk(seq) @ M : tf32 mma, 128x128 tile, split-K x2 ------------------
__global__ __launch_bounds__(256)
void u_gemm_tf32(const float* __restrict__ A, const float* __restrict__ Bm) {
    __shared__ __align__(16) float As[2][TK][136];
    __shared__ __align__(16) float Bs[2][TK][136];
    __shared__ long long rowbase[128];
    const int nslabs = 24;     // 384 K per split

    int tid = threadIdx.x;
    int m0 = blockIdx.y * 128, c0 = blockIdx.x * 128;
    int kbase = blockIdx.z * nslabs * TK;
    float* C = blockIdx.z ? g_uB : g_uA;

    if (tid < 128) {
        int m = m0 + tid;
        rowbase[tid] = ((long long)(m >> 7) * SS + g_kidx[m]) * HH;
    }
    __syncthreads();

    int ar0 = tid >> 2, ak0 = (tid & 3) * 4, ar1 = ar0 + 64;
    int bk0 = tid >> 5, bc0 = (tid & 31) * 4, bk1 = bk0 + 8;
    long long ra0 = rowbase[ar0];
    long long ra1 = rowbase[ar1];

    float4 a0v, a1v, b0v, b1v;
#define LOAD_REGS(K0) do { \
        a0v = *(const float4*)(A + ra0 + (K0) + ak0); \
        a1v = *(const float4*)(A + ra1 + (K0) + ak0); \
        b0v = *(const float4*)(Bm + (long long)((K0) + bk0) * HH + c0 + bc0); \
        b1v = *(const float4*)(Bm + (long long)((K0) + bk1) * HH + c0 + bc0); \
    } while (0)
#define STORE_SMEM(BUF) do { \
        As[BUF][ak0+0][ar0] = tf(a0v.x); As[BUF][ak0+1][ar0] = tf(a0v.y); \
        As[BUF][ak0+2][ar0] = tf(a0v.z); As[BUF][ak0+3][ar0] = tf(a0v.w); \
        As[BUF][ak0+0][ar1] = tf(a1v.x); As[BUF][ak0+1][ar1] = tf(a1v.y); \
        As[BUF][ak0+2][ar1] = tf(a1v.z); As[BUF][ak0+3][ar1] = tf(a1v.w); \
        float4 cb0, cb1; \
        cb0.x = tf(b0v.x); cb0.y = tf(b0v.y); cb0.z = tf(b0v.z); cb0.w = tf(b0v.w); \
        cb1.x = tf(b1v.x); cb1.y = tf(b1v.y); cb1.z = tf(b1v.z); cb1.w = tf(b1v.w); \
        *(float4*)&Bs[BUF][bk0][bc0] = cb0; \
        *(float4*)&Bs[BUF][bk1][bc0] = cb1; \
    } while (0)

    TF32_DECL_FRAG();

    LOAD_REGS(kbase);
    STORE_SMEM(0);
    __syncthreads();

    for (int kt = 0; kt < nslabs; kt++) {
        int cur = kt & 1;
        if (kt + 1 < nslabs) LOAD_REGS(kbase + (kt + 1) * TK);
        TF32_COMPUTE(cur);
        if (kt + 1 < nslabs) { STORE_SMEM(cur ^ 1); __syncthreads(); }
    }

    #pragma unroll
    for (int mf = 0; mf < 4; mf++) {
        #pragma unroll
        for (int nf = 0; nf < 4; nf++) {
            long long r0 = m0 + mw + mf * 16 + lm;
            long long cc = c0 + nw + nf * 8 + lk * 2;
            float2 v0 = { acc[mf][nf][0], acc[mf][nf][1] };
            float2 v1 = { acc[mf][nf][2], acc[mf][nf][3] };
            *(float2*)&C[r0 * HH + cc]       = v0;
            *(float2*)&C[(r0 + 8) * HH + cc] = v1;
        }
    }
#undef LOAD_REGS
#undef STORE_SMEM
}

// -------- rowk = Gk.p ; rowv = Gv.q + c  (warp per row) --------------------
__global__ void growdot_kernel(const float* __restrict__ seq) {
    int r = blockIdx.x * 8 + (threadIdx.x >> 5);
    int lane = threadIdx.x & 31;
    int which = blockIdx.y;
    const int* gidx = which ? g_vidx : g_kidx;
    const float* vec = which ? g_q : g_p;
    const float* row = seq + ((long long)(r >> 7) * SS + gidx[r]) * HH;
    float s = 0.f;
    #pragma unroll 4
    for (int cdx = lane; cdx < HH; cdx += 32) s = fmaf(row[cdx], vec[cdx], s);
    #pragma unroll
    for (int o = 16; o; o >>= 1) s += __shfl_xor_sync(0xffffffffu, s, o);
    if (lane == 0) {
        if (which) g_rowv[r] = s + g_c[0];
        else       g_rowk[r] = s;
    }
}

// -- biaffine tf32: biaf4[s][b,i,j] = (uA+uB)[b,i,ks] . Gv_seq[b,j,ks] ------
__global__ __launch_bounds__(256)
void biaf_splitk(const float* __restrict__ seq) {
    __shared__ __align__(16) float As[2][TK][136];
    __shared__ __align__(16) float Bs[2][TK][136];
    __shared__ long long vrowbase[128];
    const int nslabs = 12;
    int b = blockIdx.y;
    int split = blockIdx.x;
    int kbase = split * nslabs * TK;
    int tid = threadIdx.x;

    const float* A0 = g_uA + (long long)b * MC * HH;
    const float* A1 = g_uB + (long long)b * MC * HH;

    if (tid < 128)
        vrowbase[tid] = ((long long)b * SS + g_vidx[b * MC + tid]) * HH;
    __syncthreads();

    int ar0 = tid >> 2, ak = (tid & 3) * 4, ar1 = ar0 + 64;
    long long vb0 = vrowbase[ar0];
    long long vb1 = vrowbase[ar1];

    float4 a0v, a1v, b0v, b1v;
#define LOAD(K0) do { \
        float4 x0 = *(const float4*)(A0 + (long long)ar0 * HH + (K0) + ak); \
        float4 x1 = *(const float4*)(A1 + (long long)ar0 * HH + (K0) + ak); \
        a0v.x = x0.x + x1.x; a0v.y = x0.y + x1.y; a0v.z = x0.z + x1.z; a0v.w = x0.w + x1.w; \
        x0 = *(const float4*)(A0 + (long long)ar1 * HH + (K0) + ak); \
        x1 = *(const float4*)(A1 + (long long)ar1 * HH + (K0) + ak); \
        a1v.x = x0.x + x1.x; a1v.y = x0.y + x1.y; a1v.z = x0.z + x1.z; a1v.w = x0.w + x1.w; \
        b0v = *(const float4*)(seq + vb0 + (K0) + ak); \
        b1v = *(const float4*)(seq + vb1 + (K0) + ak); \
    } while (0)
#define STORE(BUF) do { \
        As[BUF][ak+0][ar0] = tf(a0v.x); As[BUF][ak+1][ar0] = tf(a0v.y); \
        As[BUF][ak+2][ar0] = tf(a0v.z); As[BUF][ak+3][ar0] = tf(a0v.w); \
        As[BUF][ak+0][ar1] = tf(a1v.x); As[BUF][ak+1][ar1] = tf(a1v.y); \
        As[BUF][ak+2][ar1] = tf(a1v.z); As[BUF][ak+3][ar1] = tf(a1v.w); \
        Bs[BUF][ak+0][ar0] = tf(b0v.x); Bs[BUF][ak+1][ar0] = tf(b0v.y); \
        Bs[BUF][ak+2][ar0] = tf(b0v.z); Bs[BUF][ak+3][ar0] = tf(b0v.w); \
        Bs[BUF][ak+0][ar1] = tf(b1v.x); Bs[BUF][ak+1][ar1] = tf(b1v.y); \
        Bs[BUF][ak+2][ar1] = tf(b1v.z); Bs[BUF][ak+3][ar1] = tf(b1v.w); \
    } while (0)

    TF32_DECL_FRAG();

    LOAD(kbase); STORE(0); __syncthreads();
    for (int kt = 0; kt < nslabs; kt++) {
        int cur = kt & 1;
        if (kt + 1 < nslabs) LOAD(kbase + (kt + 1) * TK);
        TF32_COMPUTE(cur);
        if (kt + 1 < nslabs) { STORE(cur ^ 1); __syncthreads(); }
    }

    float* dst = g_biaf4[split] + (long long)b * (MC * MC);
    #pragma unroll
    for (int mf = 0; mf < 4; mf++)
        #pragma unroll
        for (int nf = 0; nf < 4; nf++) {
            int r0 = mw + mf * 16 + lm;
            int cc = nw + nf * 8 + lk * 2;
            float2 v0 = { acc[mf][nf][0], acc[mf][nf][1] };
            float2 v1 = { acc[mf][nf][2], acc[mf][nf][3] };
            *(float2*)&dst[r0 * MC + cc]       = v0;
            *(float2*)&dst[(r0 + 8) * MC + cc] = v1;
        }
#undef LOAD
#undef STORE
}

// ----- spatial features + folded MLP, 2 key rows per thread ---------------
__global__ __launch_bounds__(128)
void pair_kernel(float* __restrict__ out,
                 const float* __restrict__ Ws1, const float* __restrict__ bs1,
                 const float* __restrict__ Wf1,
                 const float* __restrict__ Wf2, const float* __restrict__ bf2,
                 const float* __restrict__ bbilp) {
    __shared__ float sW1[8 * 64], sb1[64];
    __shared__ float sW2f[64 * 16], sb2f[16];
    __shared__ float sF0[16], sF2[16];
    __shared__ float sbf2, sbil;
    __shared__ float kb[2][4];
    __shared__ float srowk[2];

    int b = blockIdx.y;
    int i0 = blockIdx.x * 2;
    int j = threadIdx.x;

    for (int t = j; t < 512;  t += 128) sW1[t] = Ws1[t];
    for (int t = j; t < 1024; t += 128) sW2f[t] = g_W2f[t];
    if (j < 64) sb1[j] = bs1[j];
    if (j < 16) { sb2f[j] = g_b2f[j]; sF0[j] = Wf1[j]; sF2[j] = Wf2[j]; }
    if (j == 0) { sbf2 = bf2[0]; sbil = bbilp[0]; }
    if (j < 2)  srowk[j] = g_rowk[b * MC + i0 + j];
    if (j < 8)  kb[j >> 2][j & 3] = g_kbox[(b * MC + i0 + (j >> 2)) * 4 + (j & 3)];
    __syncthreads();

    float vx1 = g_vbox[(b * MC + j) * 4 + 0];
    float vy1 = g_vbox[(b * MC + j) * 4 + 1];
    float vx2 = g_vbox[(b * MC + j) * 4 + 2];
    float vy2 = g_vbox[(b * MC + j) * 4 + 3];
    float vcx = (vx1 + vx2) * 0.5f, vcy = (vy1 + vy2) * 0.5f;
    float vh = vy2 - vy1, vw = vx2 - vx1;

    float sfa[2][8];
    #pragma unroll
    for (int s = 0; s < 2; s++) {
        float kx1 = kb[s][0], ky1 = kb[s][1], kx2 = kb[s][2], ky2 = kb[s][3];
        float kcx = (kx1 + kx2) * 0.5f, kcy = (ky1 + ky2) * 0.5f;
        float dx = vcx - kcx, dy = vcy - kcy;
        float dist  = sqrtf(dx * dx + dy * dy + EPSF);
        float angle = atan2f(dy, dx);
        float kh = ky2 - ky1, kw = kx2 - kx1;
        float h_ov = fmaxf(fminf(ky2, vy2) - fmaxf(ky1, vy1), 0.0f);
        float h_align = h_ov / (fminf(kh, vh) + EPSF);
        float v_ov = fmaxf(fminf(kx2, vx2) - fmaxf(kx1, vx1), 0.0f);
        float v_align = v_ov / (fminf(kw, vw) + EPSF);
        float area_ratio   = (vh * vw) / (kh * kw + EPSF);
        float aspect_ratio = (vw / (vh + EPSF)) / (kw / (kh + EPSF));
        sfa[s][0] = dx; sfa[s][1] = dy; sfa[s][2] = dist; sfa[s][3] = angle;
        sfa[s][4] = h_align; sfa[s][5] = v_align;
        sfa[s][6] = area_ratio; sfa[s][7] = aspect_ratio;
    }

    float rowvj = g_rowv[b * MC + j];
    long long bidx0 = (long long)b * (MC * MC) + i0 * MC + j;
    long long bidx1 = bidx0 + MC;
    float biaf0 = srowk[0] + rowvj + sbil;
    float biaf1 = srowk[1] + rowvj + sbil;
    #pragma unroll
    for (int s = 0; s < 4; s++) {
        biaf0 += g_biaf4[s][bidx0];
        biaf1 += g_biaf4[s][bidx1];
    }

    float f1a[16], f1b[16];
    #pragma unroll
    for (int t = 0; t < 16; t++) {
        float f0 = sF0[t], bb = sb2f[t];
        f1a[t] = fmaf(biaf0, f0, bb);
        f1b[t] = fmaf(biaf1, f0, bb);
    }

    for (int u = 0; u < 64; u++) {
        float h0 = sb1[u], h1 = h0;
        #pragma unroll
        for (int f = 0; f < 8; f++) {
            float w = sW1[f * 64 + u];
            h0 = fmaf(sfa[0][f], w, h0);
            h1 = fmaf(sfa[1][f], w, h1);
        }
        h0 = fmaxf(h0, 0.0f);
        h1 = fmaxf(h1, 0.0f);
        #pragma unroll
        for (int t = 0; t < 16; t++) {
            float w2 = sW2f[u * 16 + t];
            f1a[t] = fmaf(h0, w2, f1a[t]);
            f1b[t] = fmaf(h1, w2, f1b[t]);
        }
    }

    float s0 = sbf2, s1 = sbf2;
    #pragma unroll
    for (int t = 0; t < 16; t++) {
        float w = sF2[t];
        s0 = fmaf(fmaxf(f1a[t], 0.0f), w, s0);
        s1 = fmaf(fmaxf(f1b[t], 0.0f), w, s1);
    }

    out[bidx0] = s0;
    out[bidx1] = s1;
}

// ---------------- launch ----------------
extern "C" void kernel_launch(void* const* d_in, const int* in_sizes, int n_in,
                              void* d_out, int out_size) {
    (void)in_sizes; (void)n_in; (void)out_size;
    const float* seq    = (const float*)d_in[0];
    const float* logits = (const float*)d_in[1];
    const float* bboxes = (const float*)d_in[2];
    const int*   mask   = (const int*)  d_in[3];
    const float* Wk  = (const float*)d_in[4];
    const float* bk  = (const float*)d_in[5];
    const float* Wv  = (const float*)d_in[6];
    const float* bv  = (const float*)d_in[7];
    const float* Wbil= (const float*)d_in[8];
    const float* bbil= (const float*)d_in[9];
    const float* Ws1 = (const float*)d_in[10];
    const float* bs1 = (const float*)d_in[11];
    const float* Ws2 = (const float*)d_in[12];
    const float* bs2 = (const float*)d_in[13];
    const float* Wf1 = (const float*)d_in[14];
    const float* bf1 = (const float*)d_in[15];
    const float* Wf2 = (const float*)d_in[16];
    const float* bf2 = (const float*)d_in[17];
    float* out = (float*)d_out;

    float *pM;
    cudaGetSymbolAddress((void**)&pM, g_M);
    cudaMemsetAsync(pM, 0, (size_t)HH * HH * sizeof(float));

    topk_kernel<<<dim3(BB, 2), 512>>>(logits, mask, bboxes, out);
    setupA<<<99, 256>>>(bk, Wbil, bv);
    setupB<<<193, 256>>>(Wv, Wk, bv, Ws2, bs2, Wf1, bf1);

    // Wc2 split buffers = Wbil @ Wv^T  (tf32, split-K x4, plain stores)
    nt_split<<<dim3(HH / 128, HH / 128, 4), 256>>>(Wbil, Wv);
    // M = Wk @ sum(Wc2_s)  (tf32, split-K x4, atomics)
    nn_atomic<<<dim3(HH / 128, HH / 128, 4), 256>>>(Wk, pM);

    // u = Gk(seq) @ M   (tf32, split-K x2 into uA/uB, 384 blocks)
    u_gemm_tf32<<<dim3(HH / 128, (BB * MC) / 128, 2), 256>>>(seq, pM);

    // rowk = Gk.p ; rowv = Gv.q + c
    growdot_kernel<<<dim3((BB * MC) / 8, 2), 256>>>(seq);

    // biaffine term1: 4 split buffers (tf32)
    biaf_splitk<<<dim3(4, BB), 256>>>(seq);

    pair_kernel<<<dim3(MC / 2, BB), 128>>>(out, Ws1, bs1, Wf1, Wf2, bf2, bbil);
}

// round 14
// speedup vs baseline: 2.3268x; 1.1096x over previous
#include <cuda_runtime.h>
#include <math.h>
#include <stdint.h>

#define BB 32
#define SS 512
#define HH 768
#define MC 128
#define EPSF 1e-8f
#define TK 16

// ---------------- scratch (static device memory; no allocs) ----------------
__device__ int   g_kidx[BB*MC];
__device__ int   g_vidx[BB*MC];
__device__ float g_kbox[BB*MC*4];
__device__ float g_vbox[BB*MC*4];
__device__ float g_uA[BB*MC*HH];
__device__ float g_uB[BB*MC*HH];
__device__ float g_biaf4[4][BB*MC*MC];
__device__ float g_Wc2s[4][HH*HH]; // Wbil @ Wv^T, 4 K-split partials
__device__ float g_M[HH*HH];       // Wk @ Wc2
__device__ float g_s1[HH];         // bk @ Wbil
__device__ float g_r[HH];          // Wbil @ bv
__device__ float g_q[HH];          // Wv @ s1
__device__ float g_p[HH];          // Wk @ r
__device__ float g_c[1];           // s1 . bv
__device__ float g_rowk[BB*MC];
__device__ float g_rowv[BB*MC];
__device__ float g_W2f[64*16];
__device__ float g_b2f[16];

__device__ __forceinline__ unsigned int f2tf32(float x) {
    unsigned int r;
    asm("cvt.rna.tf32.f32 %0, %1;" : "=r"(r) : "f"(x));
    return r;
}
__device__ __forceinline__ float tf(float x) { return __uint_as_float(f2tf32(x)); }

#define TF32_COMPUTE(CUR) do { \
    _Pragma("unroll") \
    for (int ks = 0; ks < TK; ks += 8) { \
        uint32_t af[4][4]; \
        _Pragma("unroll") \
        for (int mf = 0; mf < 4; mf++) { \
            int mb = mw + mf * 16 + lm; \
            af[mf][0] = __float_as_uint(As[CUR][ks + lk][mb]); \
            af[mf][1] = __float_as_uint(As[CUR][ks + lk][mb + 8]); \
            af[mf][2] = __float_as_uint(As[CUR][ks + lk + 4][mb]); \
            af[mf][3] = __float_as_uint(As[CUR][ks + lk + 4][mb + 8]); \
        } \
        uint32_t bf[4][2]; \
        _Pragma("unroll") \
        for (int nf = 0; nf < 4; nf++) { \
            int nb = nw + nf * 8 + lm; \
            bf[nf][0] = __float_as_uint(Bs[CUR][ks + lk][nb]); \
            bf[nf][1] = __float_as_uint(Bs[CUR][ks + lk + 4][nb]); \
        } \
        _Pragma("unroll") \
        for (int mf = 0; mf < 4; mf++) \
            _Pragma("unroll") \
            for (int nf = 0; nf < 4; nf++) { \
                asm volatile( \
                    "mma.sync.aligned.m16n8k8.row.col.f32.tf32.tf32.f32 " \
                    "{%0,%1,%2,%3}, {%4,%5,%6,%7}, {%8,%9}, {%0,%1,%2,%3};" \
                    : "+f"(acc[mf][nf][0]), "+f"(acc[mf][nf][1]), \
                      "+f"(acc[mf][nf][2]), "+f"(acc[mf][nf][3]) \
                    : "r"(af[mf][0]), "r"(af[mf][1]), "r"(af[mf][2]), "r"(af[mf][3]), \
                      "r"(bf[nf][0]), "r"(bf[nf][1])); \
            } \
    } \
} while (0)

#define TF32_DECL_FRAG() \
    int wid = tid >> 5; \
    int lane = tid & 31; \
    int mw = (wid & 1) * 64; \
    int nw = (wid >> 1) * 32; \
    int lm = lane >> 2; \
    int lk = lane & 3; \
    float acc[4][4][4]; \
    _Pragma("unroll") \
    for (int mf = 0; mf < 4; mf++) \
        _Pragma("unroll") \
        for (int nf = 0; nf < 4; nf++) \
            _Pragma("unroll") \
            for (int e = 0; e < 4; e++) acc[mf][nf][e] = 0.f;

// -------- 1+2) conf (inline) + exact top-128 of 512 via bitonic sort ------
__global__ void topk_kernel(const float* __restrict__ logits,
                            const int* __restrict__ mask,
                            const float* __restrict__ bboxes,
                            float* __restrict__ out) {
    int b = blockIdx.x;
    int which = blockIdx.y;   // 0 = key, 1 = val
    __shared__ float sc[512];
    __shared__ int   si[512];
    int tid = threadIdx.x;

    {   // inline confidence
        int t = b * SS + tid;
        float l0 = logits[3*t+0], l1 = logits[3*t+1], l2 = logits[3*t+2];
        int pred = 0; float best = l0;
        if (l1 > best) { pred = 1; best = l1; }
        if (l2 > best) { pred = 2; best = l2; }
        float e0 = expf(l0 - best), e1 = expf(l1 - best), e2 = expf(l2 - best);
        float inv = 1.0f / (e0 + e1 + e2);
        bool valid = (mask[t] == 1);
        float conf;
        if (which == 0) conf = (pred == 1 && valid) ? e1 * inv : -INFINITY;
        else            conf = (pred == 2 && valid) ? e2 * inv : -INFINITY;
        sc[tid] = conf; si[tid] = tid;
    }

    for (int k = 2; k <= 512; k <<= 1) {
        for (int j = k >> 1; j > 0; j >>= 1) {
            __syncthreads();
            int ixj = tid ^ j;
            if (ixj > tid) {
                float c1 = sc[tid], c2 = sc[ixj];
                int   i1 = si[tid], i2 = si[ixj];
                bool b2 = (c2 > c1) || (c2 == c1 && i2 < i1);
                bool doswap = ((tid & k) == 0) ? b2 : !b2;
                if (doswap) {
                    sc[tid] = c2; si[tid] = i2;
                    sc[ixj] = c1; si[ixj] = i1;
                }
            }
        }
    }
    __syncthreads();

    if (tid < MC) {
        int   idx = si[tid];
        float cf  = sc[tid];
        int*   gi = (which == 0) ? g_kidx : g_vidx;
        float* gb = (which == 0) ? g_kbox : g_vbox;
        gi[b * MC + tid] = idx;
        const float* src = bboxes + ((long long)b * SS + idx) * 4;
        float* dst = gb + (b * MC + tid) * 4;
        dst[0] = src[0]; dst[1] = src[1]; dst[2] = src[2]; dst[3] = src[3];
        long long base = (long long)BB * MC * MC;            // 524288
        float vf = (cf != -INFINITY) ? 1.0f : 0.0f;
        out[base + (long long)which * (BB * MC) + b * MC + tid] = vf;
        out[base + 2LL * (BB * MC) + (long long)which * (BB * MC) + b * MC + tid] = (float)idx;
    }
}

// ---------------- setupA: s1 = bk @ Wbil ; r = Wbil @ bv -------------------
__global__ void setupA(const float* __restrict__ bk,
                       const float* __restrict__ Wbil,
                       const float* __restrict__ bv) {
    int bx = blockIdx.x, tid = threadIdx.x;
    if (bx < 3) {
        int j = bx * 256 + tid;
        float s = 0.f;
        for (int h = 0; h < HH; h++) s = fmaf(bk[h], Wbil[h * HH + j], s);
        g_s1[j] = s;
    } else {
        int row = (bx - 3) * 8 + (tid >> 5);
        int lane = tid & 31;
        const float* rp = Wbil + (long long)row * HH;
        float s = 0.f;
        #pragma unroll 4
        for (int cdx = lane; cdx < HH; cdx += 32) s = fmaf(rp[cdx], bv[cdx], s);
        #pragma unroll
        for (int o = 16; o; o >>= 1) s += __shfl_xor_sync(0xffffffffu, s, o);
        if (lane == 0) g_r[row] = s;
    }
}

// -------- setupB: q = Wv@s1 ; p = Wk@r ; c = s1.bv ; MLP fold --------------
__global__ void setupB(const float* __restrict__ Wv, const float* __restrict__ Wk,
                       const float* __restrict__ bv,
                       const float* __restrict__ Ws2, const float* __restrict__ bs2,
                       const float* __restrict__ Wf1, const float* __restrict__ bf1) {
    int bx = blockIdx.x, tid = threadIdx.x;
    if (bx < 192) {
        const float* A   = (bx < 96) ? Wv : Wk;
        const float* x   = (bx < 96) ? g_s1 : g_r;
        float* outv      = (bx < 96) ? g_q : g_p;
        int row = ((bx < 96) ? bx : bx - 96) * 8 + (tid >> 5);
        int lane = tid & 31;
        const float* rp = A + (long long)row * HH;
        float s = 0.f;
        #pragma unroll 4
        for (int cdx = lane; cdx < HH; cdx += 32) s = fmaf(rp[cdx], x[cdx], s);
        #pragma unroll
        for (int o = 16; o; o >>= 1) s += __shfl_xor_sync(0xffffffffu, s, o);
        if (lane == 0) outv[row] = s;
    } else {
        #pragma unroll
        for (int e = 0; e < 4; e++) {
            int o = tid * 4 + e;
            if (o < 1024) {
                int u = o >> 4, t = o & 15;
                float s = 0.f;
                #pragma unroll
                for (int s2 = 0; s2 < 32; s2++)
                    s = fmaf(Ws2[u * 32 + s2], Wf1[(s2 + 1) * 16 + t], s);
                g_W2f[o] = s;
            }
        }
        if (tid < 16) {
            float s = bf1[tid];
            #pragma unroll
            for (int s2 = 0; s2 < 32; s2++)
                s = fmaf(bs2[s2], Wf1[(s2 + 1) * 16 + tid], s);
            g_b2f[tid] = s;
        }
        __shared__ float red[256];
        float s = 0.f;
        for (int g = tid; g < HH; g += 256) s = fmaf(g_s1[g], bv[g], s);
        red[tid] = s; __syncthreads();
        for (int o = 128; o; o >>= 1) { if (tid < o) red[tid] += red[tid + o]; __syncthreads(); }
        if (tid == 0) g_c[0] = red[0];
    }
}

// ------ NT tf32 split-K x4, plain stores: Wc2_s = Wbil @ Wv^T --------------
__global__ __launch_bounds__(256)
void nt_split(const float* __restrict__ A, const float* __restrict__ B) {
    __shared__ __align__(16) float As[2][TK][136];
    __shared__ __align__(16) float Bs[2][TK][136];
    const int nslabs = 12;
    int tid = threadIdx.x;
    int m0 = blockIdx.y * 128, n0 = blockIdx.x * 128;
    int kbase = blockIdx.z * nslabs * TK;
    int ar0 = tid >> 2, ak = (tid & 3) * 4, ar1 = ar0 + 64;

    float4 a0v, a1v, b0v, b1v;
#define LOAD(K0) do { \
        a0v = *(const float4*)(A + (long long)(m0 + ar0) * HH + (K0) + ak); \
        a1v = *(const float4*)(A + (long long)(m0 + ar1) * HH + (K0) + ak); \
        b0v = *(const float4*)(B + (long long)(n0 + ar0) * HH + (K0) + ak); \
        b1v = *(const float4*)(B + (long long)(n0 + ar1) * HH + (K0) + ak); \
    } while (0)
#define STORE(BUF) do { \
        As[BUF][ak+0][ar0] = tf(a0v.x); As[BUF][ak+1][ar0] = tf(a0v.y); \
        As[BUF][ak+2][ar0] = tf(a0v.z); As[BUF][ak+3][ar0] = tf(a0v.w); \
        As[BUF][ak+0][ar1] = tf(a1v.x); As[BUF][ak+1][ar1] = tf(a1v.y); \
        As[BUF][ak+2][ar1] = tf(a1v.z); As[BUF][ak+3][ar1] = tf(a1v.w); \
        Bs[BUF][ak+0][ar0] = tf(b0v.x); Bs[BUF][ak+1][ar0] = tf(b0v.y); \
        Bs[BUF][ak+2][ar0] = tf(b0v.z); Bs[BUF][ak+3][ar0] = tf(b0v.w); \
        Bs[BUF][ak+0][ar1] = tf(b1v.x); Bs[BUF][ak+1][ar1] = tf(b1v.y); \
        Bs[BUF][ak+2][ar1] = tf(b1v.z); Bs[BUF][ak+3][ar1] = tf(b1v.w); \
    } while (0)

    TF32_DECL_FRAG();

    LOAD(kbase); STORE(0); __syncthreads();
    for (int kt = 0; kt < nslabs; kt++) {
        int cur = kt & 1;
        if (kt + 1 < nslabs) LOAD(kbase + (kt + 1) * TK);
        TF32_COMPUTE(cur);
        if (kt + 1 < nslabs) { STORE(cur ^ 1); __syncthreads(); }
    }
    float* C = g_Wc2s[blockIdx.z];
    #pragma unroll
    for (int mf = 0; mf < 4; mf++)
        #pragma unroll
        for (int nf = 0; nf < 4; nf++) {
            long long r0 = m0 + mw + mf * 16 + lm;
            long long cc = n0 + nw + nf * 8 + lk * 2;
            float2 v0 = { acc[mf][nf][0], acc[mf][nf][1] };
            float2 v1 = { acc[mf][nf][2], acc[mf][nf][3] };
            *(float2*)&C[r0 * HH + cc]       = v0;
            *(float2*)&C[(r0 + 8) * HH + cc] = v1;
        }
#undef LOAD
#undef STORE
}

// ------ NN tf32 split-K x4 atomic: M = Wk @ sum(Wc2_s) ---------------------
__global__ __launch_bounds__(256)
void nn_atomic(const float* __restrict__ A, float* __restrict__ C) {
    __shared__ __align__(16) float As[2][TK][136];
    __shared__ __align__(16) float Bs[2][TK][136];
    const int nslabs = 12;
    int tid = threadIdx.x;
    int m0 = blockIdx.y * 128, c0 = blockIdx.x * 128;
    int kbase = blockIdx.z * nslabs * TK;
    int ar0 = tid >> 2, ak = (tid & 3) * 4, ar1 = ar0 + 64;
    int bk0 = tid >> 5, bcc = (tid & 31) * 4, bk1 = bk0 + 8;

    float4 a0v, a1v, b0v, b1v;
#define LOAD(K0) do { \
        a0v = *(const float4*)(A + (long long)(m0 + ar0) * HH + (K0) + ak); \
        a1v = *(const float4*)(A + (long long)(m0 + ar1) * HH + (K0) + ak); \
        long long o0 = (long long)((K0) + bk0) * HH + c0 + bcc; \
        long long o1 = (long long)((K0) + bk1) * HH + c0 + bcc; \
        float4 t0 = *(const float4*)(g_Wc2s[0] + o0); \
        float4 t1 = *(const float4*)(g_Wc2s[1] + o0); \
        float4 t2 = *(const float4*)(g_Wc2s[2] + o0); \
        float4 t3 = *(const float4*)(g_Wc2s[3] + o0); \
        b0v.x = t0.x + t1.x + t2.x + t3.x; b0v.y = t0.y + t1.y + t2.y + t3.y; \
        b0v.z = t0.z + t1.z + t2.z + t3.z; b0v.w = t0.w + t1.w + t2.w + t3.w; \
        t0 = *(const float4*)(g_Wc2s[0] + o1); \
        t1 = *(const float4*)(g_Wc2s[1] + o1); \
        t2 = *(const float4*)(g_Wc2s[2] + o1); \
        t3 = *(const float4*)(g_Wc2s[3] + o1); \
        b1v.x = t0.x + t1.x + t2.x + t3.x; b1v.y = t0.y + t1.y + t2.y + t3.y; \
        b1v.z = t0.z + t1.z + t2.z + t3.z; b1v.w = t0.w + t1.w + t2.w + t3.w; \
    } while (0)
#define STORE(BUF) do { \
        As[BUF][ak+0][ar0] = tf(a0v.x); As[BUF][ak+1][ar0] = tf(a0v.y); \
        As[BUF][ak+2][ar0] = tf(a0v.z); As[BUF][ak+3][ar0] = tf(a0v.w); \
        As[BUF][ak+0][ar1] = tf(a1v.x); As[BUF][ak+1][ar1] = tf(a1v.y); \
        As[BUF][ak+2][ar1] = tf(a1v.z); As[BUF][ak+3][ar1] = tf(a1v.w); \
        float4 cb0, cb1; \
        cb0.x = tf(b0v.x); cb0.y = tf(b0v.y); cb0.z = tf(b0v.z); cb0.w = tf(b0v.w); \
        cb1.x = tf(b1v.x); cb1.y = tf(b1v.y); cb1.z = tf(b1v.z); cb1.w = tf(b1v.w); \
        *(float4*)&Bs[BUF][bk0][bcc] = cb0; \
        *(float4*)&Bs[BUF][bk1][bcc] = cb1; \
    } while (0)

    TF32_DECL_FRAG();

    LOAD(kbase); STORE(0); __syncthreads();
    for (int kt = 0; kt < nslabs; kt++) {
        int cur = kt & 1;
        if (kt + 1 < nslabs) LOAD(kbase + (kt + 1) * TK);
        TF32_COMPUTE(cur);
        if (kt + 1 < nslabs) { STORE(cur ^ 1); __syncthreads(); }
    }
    #pragma unroll
    for (int mf = 0; mf < 4; mf++)
        #pragma unroll
        for (int nf = 0; nf < 4; nf++) {
            long long r0 = m0 + mw + mf * 16 + lm;
            long long cc = c0 + nw + nf * 8 + lk * 2;
            atomicAdd(&C[r0 * HH + cc],           acc[mf][nf][0]);
            atomicAdd(&C[r0 * HH + cc + 1],       acc[mf][nf][1]);
            atomicAdd(&C[(r0 + 8) * HH + cc],     acc[mf][nf][2]);
            atomicAdd(&C[(r0 + 8) * HH + cc + 1], acc[mf][nf][3]);
        }
#undef LOAD
#undef STORE
}

// --- u = Gk(seq) @ M : tf32 mma, 128x128 tile, split-K x2 ------------------
__global__ __launch_bounds__(256)
void u_gemm_tf32(const float* __restrict__ A, const float* __restrict__ Bm) {
    __shared__ __align__(16) float As[2][TK][136];
    __shared__ __align__(16) float Bs[2][TK][136];
    __shared__ long long rowbase[128];
    const int nslabs = 24;     // 384 K per split

    int tid = threadIdx.x;
    int m0 = blockIdx.y * 128, c0 = blockIdx.x * 128;
    int kbase = blockIdx.z * nslabs * TK;
    float* C = blockIdx.z ? g_uB : g_uA;

    if (tid < 128) {
        int m = m0 + tid;
        rowbase[tid] = ((long long)(m >> 7) * SS + g_kidx[m]) * HH;
    }
    __syncthreads();

    int ar0 = tid >> 2, ak0 = (tid & 3) * 4, ar1 = ar0 + 64;
    int bk0 = tid >> 5, bc0 = (tid & 31) * 4, bk1 = bk0 + 8;
    long long ra0 = rowbase[ar0];
    long long ra1 = rowbase[ar1];

    float4 a0v, a1v, b0v, b1v;
#define LOAD_REGS(K0) do { \
        a0v = *(const float4*)(A + ra0 + (K0) + ak0); \
        a1v = *(const float4*)(A + ra1 + (K0) + ak0); \
        b0v = *(const float4*)(Bm + (long long)((K0) + bk0) * HH + c0 + bc0); \
        b1v = *(const float4*)(Bm + (long long)((K0) + bk1) * HH + c0 + bc0); \
    } while (0)
#define STORE_SMEM(BUF) do { \
        As[BUF][ak0+0][ar0] = tf(a0v.x); As[BUF][ak0+1][ar0] = tf(a0v.y); \
        As[BUF][ak0+2][ar0] = tf(a0v.z); As[BUF][ak0+3][ar0] = tf(a0v.w); \
        As[BUF][ak0+0][ar1] = tf(a1v.x); As[BUF][ak0+1][ar1] = tf(a1v.y); \
        As[BUF][ak0+2][ar1] = tf(a1v.z); As[BUF][ak0+3][ar1] = tf(a1v.w); \
        float4 cb0, cb1; \
        cb0.x = tf(b0v.x); cb0.y = tf(b0v.y); cb0.z = tf(b0v.z); cb0.w = tf(b0v.w); \
        cb1.x = tf(b1v.x); cb1.y = tf(b1v.y); cb1.z = tf(b1v.z); cb1.w = tf(b1v.w); \
        *(float4*)&Bs[BUF][bk0][bc0] = cb0; \
        *(float4*)&Bs[BUF][bk1][bc0] = cb1; \
    } while (0)

    TF32_DECL_FRAG();

    LOAD_REGS(kbase);
    STORE_SMEM(0);
    __syncthreads();

    for (int kt = 0; kt < nslabs; kt++) {
        int cur = kt & 1;
        if (kt + 1 < nslabs) LOAD_REGS(kbase + (kt + 1) * TK);
        TF32_COMPUTE(cur);
        if (kt + 1 < nslabs) { STORE_SMEM(cur ^ 1); __syncthreads(); }
    }

    #pragma unroll
    for (int mf = 0; mf < 4; mf++) {
        #pragma unroll
        for (int nf = 0; nf < 4; nf++) {
            long long r0 = m0 + mw + mf * 16 + lm;
            long long cc = c0 + nw + nf * 8 + lk * 2;
            float2 v0 = { acc[mf][nf][0], acc[mf][nf][1] };
            float2 v1 = { acc[mf][nf][2], acc[mf][nf][3] };
            *(float2*)&C[r0 * HH + cc]       = v0;
            *(float2*)&C[(r0 + 8) * HH + cc] = v1;
        }
    }
#undef LOAD_REGS
#undef STORE_SMEM
}

// -------- rowk = Gk.p ; rowv = Gv.q + c  (warp per row) --------------------
__global__ void growdot_kernel(const float* __restrict__ seq) {
    int r = blockIdx.x * 8 + (threadIdx.x >> 5);
    int lane = threadIdx.x & 31;
    int which = blockIdx.y;
    const int* gidx = which ? g_vidx : g_kidx;
    const float* vec = which ? g_q : g_p;
    const float* row = seq + ((long long)(r >> 7) * SS + gidx[r]) * HH;
    float s = 0.f;
    #pragma unroll 4
    for (int cdx = lane; cdx < HH; cdx += 32) s = fmaf(row[cdx], vec[cdx], s);
    #pragma unroll
    for (int o = 16; o; o >>= 1) s += __shfl_xor_sync(0xffffffffu, s, o);
    if (lane == 0) {
        if (which) g_rowv[r] = s + g_c[0];
        else       g_rowk[r] = s;
    }
}

// -- biaffine tf32: biaf4[s][b,i,j] = (uA+uB)[b,i,ks] . Gv_seq[b,j,ks] ------
__global__ __launch_bounds__(256)
void biaf_splitk(const float* __restrict__ seq) {
    __shared__ __align__(16) float As[2][TK][136];
    __shared__ __align__(16) float Bs[2][TK][136];
    __shared__ long long vrowbase[128];
    const int nslabs = 12;
    int b = blockIdx.y;
    int split = blockIdx.x;
    int kbase = split * nslabs * TK;
    int tid = threadIdx.x;

    const float* A0 = g_uA + (long long)b * MC * HH;
    const float* A1 = g_uB + (long long)b * MC * HH;

    if (tid < 128)
        vrowbase[tid] = ((long long)b * SS + g_vidx[b * MC + tid]) * HH;
    __syncthreads();

    int ar0 = tid >> 2, ak = (tid & 3) * 4, ar1 = ar0 + 64;
    long long vb0 = vrowbase[ar0];
    long long vb1 = vrowbase[ar1];

    float4 a0v, a1v, b0v, b1v;
#define LOAD(K0) do { \
        float4 x0 = *(const float4*)(A0 + (long long)ar0 * HH + (K0) + ak); \
        float4 x1 = *(const float4*)(A1 + (long long)ar0 * HH + (K0) + ak); \
        a0v.x = x0.x + x1.x; a0v.y = x0.y + x1.y; a0v.z = x0.z + x1.z; a0v.w = x0.w + x1.w; \
        x0 = *(const float4*)(A0 + (long long)ar1 * HH + (K0) + ak); \
        x1 = *(const float4*)(A1 + (long long)ar1 * HH + (K0) + ak); \
        a1v.x = x0.x + x1.x; a1v.y = x0.y + x1.y; a1v.z = x0.z + x1.z; a1v.w = x0.w + x1.w; \
        b0v = *(const float4*)(seq + vb0 + (K0) + ak); \
        b1v = *(const float4*)(seq + vb1 + (K0) + ak); \
    } while (0)
#define STORE(BUF) do { \
        As[BUF][ak+0][ar0] = tf(a0v.x); As[BUF][ak+1][ar0] = tf(a0v.y); \
        As[BUF][ak+2][ar0] = tf(a0v.z); As[BUF][ak+3][ar0] = tf(a0v.w); \
        As[BUF][ak+0][ar1] = tf(a1v.x); As[BUF][ak+1][ar1] = tf(a1v.y); \
        As[BUF][ak+2][ar1] = tf(a1v.z); As[BUF][ak+3][ar1] = tf(a1v.w); \
        Bs[BUF][ak+0][ar0] = tf(b0v.x); Bs[BUF][ak+1][ar0] = tf(b0v.y); \
        Bs[BUF][ak+2][ar0] = tf(b0v.z); Bs[BUF][ak+3][ar0] = tf(b0v.w); \
        Bs[BUF][ak+0][ar1] = tf(b1v.x); Bs[BUF][ak+1][ar1] = tf(b1v.y); \
        Bs[BUF][ak+2][ar1] = tf(b1v.z); Bs[BUF][ak+3][ar1] = tf(b1v.w); \
    } while (0)

    TF32_DECL_FRAG();

    LOAD(kbase); STORE(0); __syncthreads();
    for (int kt = 0; kt < nslabs; kt++) {
        int cur = kt & 1;
        if (kt + 1 < nslabs) LOAD(kbase + (kt + 1) * TK);
        TF32_COMPUTE(cur);
        if (kt + 1 < nslabs) { STORE(cur ^ 1); __syncthreads(); }
    }

    float* dst = g_biaf4[split] + (long long)b * (MC * MC);
    #pragma unroll
    for (int mf = 0; mf < 4; mf++)
        #pragma unroll
        for (int nf = 0; nf < 4; nf++) {
            int r0 = mw + mf * 16 + lm;
            int cc = nw + nf * 8 + lk * 2;
            float2 v0 = { acc[mf][nf][0], acc[mf][nf][1] };
            float2 v1 = { acc[mf][nf][2], acc[mf][nf][3] };
            *(float2*)&dst[r0 * MC + cc]       = v0;
            *(float2*)&dst[(r0 + 8) * MC + cc] = v1;
        }
#undef LOAD
#undef STORE
}

// ----- spatial features + folded MLP, 4 key rows per thread ---------------
__global__ __launch_bounds__(128)
void pair_kernel(float* __restrict__ out,
                 const float* __restrict__ Ws1, const float* __restrict__ bs1,
                 const float* __restrict__ Wf1,
                 const float* __restrict__ Wf2, const float* __restrict__ bf2,
                 const float* __restrict__ bbilp) {
    __shared__ float sW1[8 * 64], sb1[64];
    __shared__ float sW2f[64 * 16], sb2f[16];
    __shared__ float sF0[16], sF2[16];
    __shared__ float sbf2, sbil;
    __shared__ float kb[4][4];
    __shared__ float srowk[4];

    int b = blockIdx.y;
    int i0 = blockIdx.x * 4;
    int j = threadIdx.x;

    for (int t = j; t < 512;  t += 128) sW1[t] = Ws1[t];
    for (int t = j; t < 1024; t += 128) sW2f[t] = g_W2f[t];
    if (j < 64) sb1[j] = bs1[j];
    if (j < 16) { sb2f[j] = g_b2f[j]; sF0[j] = Wf1[j]; sF2[j] = Wf2[j]; }
    if (j == 0) { sbf2 = bf2[0]; sbil = bbilp[0]; }
    if (j < 4)  srowk[j] = g_rowk[b * MC + i0 + j];
    if (j < 16) kb[j >> 2][j & 3] = g_kbox[(b * MC + i0 + (j >> 2)) * 4 + (j & 3)];
    __syncthreads();

    float vx1 = g_vbox[(b * MC + j) * 4 + 0];
    float vy1 = g_vbox[(b * MC + j) * 4 + 1];
    float vx2 = g_vbox[(b * MC + j) * 4 + 2];
    float vy2 = g_vbox[(b * MC + j) * 4 + 3];
    float vcx = (vx1 + vx2) * 0.5f, vcy = (vy1 + vy2) * 0.5f;
    float vh = vy2 - vy1, vw = vx2 - vx1;

    float sfa[4][8];
    #pragma unroll
    for (int s = 0; s < 4; s++) {
        float kx1 = kb[s][0], ky1 = kb[s][1], kx2 = kb[s][2], ky2 = kb[s][3];
        float kcx = (kx1 + kx2) * 0.5f, kcy = (ky1 + ky2) * 0.5f;
        float dx = vcx - kcx, dy = vcy - kcy;
        float dist  = sqrtf(dx * dx + dy * dy + EPSF);
        float angle = atan2f(dy, dx);
        float kh = ky2 - ky1, kw = kx2 - kx1;
        float h_ov = fmaxf(fminf(ky2, vy2) - fmaxf(ky1, vy1), 0.0f);
        float h_align = h_ov / (fminf(kh, vh) + EPSF);
        float v_ov = fmaxf(fminf(kx2, vx2) - fmaxf(kx1, vx1), 0.0f);
        float v_align = v_ov / (fminf(kw, vw) + EPSF);
        float area_ratio   = (vh * vw) / (kh * kw + EPSF);
        float aspect_ratio = (vw / (vh + EPSF)) / (kw / (kh + EPSF));
        sfa[s][0] = dx; sfa[s][1] = dy; sfa[s][2] = dist; sfa[s][3] = angle;
        sfa[s][4] = h_align; sfa[s][5] = v_align;
        sfa[s][6] = area_ratio; sfa[s][7] = aspect_ratio;
    }

    float rowvj = g_rowv[b * MC + j];
    long long bidx[4];
    float biafv[4];
    #pragma unroll
    for (int s = 0; s < 4; s++) {
        bidx[s] = (long long)b * (MC * MC) + (i0 + s) * MC + j;
        float v = srowk[s] + rowvj + sbil;
        #pragma unroll
        for (int sp = 0; sp < 4; sp++) v += g_biaf4[sp][bidx[s]];
        biafv[s] = v;
    }

    float f1[4][16];
    #pragma unroll
    for (int t = 0; t < 16; t++) {
        float f0 = sF0[t], bb = sb2f[t];
        #pragma unroll
        for (int s = 0; s < 4; s++) f1[s][t] = fmaf(biafv[s], f0, bb);
    }

    for (int u = 0; u < 64; u++) {
        float h[4];
        float hb = sb1[u];
        #pragma unroll
        for (int s = 0; s < 4; s++) h[s] = hb;
        #pragma unroll
        for (int f = 0; f < 8; f++) {
            float w = sW1[f * 64 + u];
            #pragma unroll
            for (int s = 0; s < 4; s++) h[s] = fmaf(sfa[s][f], w, h[s]);
        }
        #pragma unroll
        for (int s = 0; s < 4; s++) h[s] = fmaxf(h[s], 0.0f);
        #pragma unroll
        for (int t = 0; t < 16; t++) {
            float w2 = sW2f[u * 16 + t];
            #pragma unroll
            for (int s = 0; s < 4; s++) f1[s][t] = fmaf(h[s], w2, f1[s][t]);
        }
    }

    float sc[4];
    #pragma unroll
    for (int s = 0; s < 4; s++) sc[s] = sbf2;
    #pragma unroll
    for (int t = 0; t < 16; t++) {
        float w = sF2[t];
        #pragma unroll
        for (int s = 0; s < 4; s++)
            sc[s] = fmaf(fmaxf(f1[s][t], 0.0f), w, sc[s]);
    }
    #pragma unroll
    for (int s = 0; s < 4; s++) out[bidx[s]] = sc[s];
}

// ---------------- launch ----------------
extern "C" void kernel_launch(void* const* d_in, const int* in_sizes, int n_in,
                              void* d_out, int out_size) {
    (void)in_sizes; (void)n_in; (void)out_size;
    const float* seq    = (const float*)d_in[0];
    const float* logits = (const float*)d_in[1];
    const float* bboxes = (const float*)d_in[2];
    const int*   mask   = (const int*)  d_in[3];
    const float* Wk  = (const float*)d_in[4];
    const float* bk  = (const float*)d_in[5];
    const float* Wv  = (const float*)d_in[6];
    const float* bv  = (const float*)d_in[7];
    const float* Wbil= (const float*)d_in[8];
    const float* bbil= (const float*)d_in[9];
    const float* Ws1 = (const float*)d_in[10];
    const float* bs1 = (const float*)d_in[11];
    const float* Ws2 = (const float*)d_in[12];
    const float* bs2 = (const float*)d_in[13];
    const float* Wf1 = (const float*)d_in[14];
    const float* bf1 = (const float*)d_in[15];
    const float* Wf2 = (const float*)d_in[16];
    const float* bf2 = (const float*)d_in[17];
    float* out = (float*)d_out;

    float *pM;
    cudaGetSymbolAddress((void**)&pM, g_M);

    // fork a second stream so the weight chain (memset->nt->nn) runs
    // concurrently with the data chain (topk->setupA->setupB->growdot).
    cudaStream_t s1;
    cudaStreamCreateWithFlags(&s1, cudaStreamNonBlocking);
    cudaEvent_t e0, e1;
    cudaEventCreateWithFlags(&e0, cudaEventDisableTiming);
    cudaEventCreateWithFlags(&e1, cudaEventDisableTiming);

    cudaEventRecord(e0, 0);
    cudaStreamWaitEvent(s1, e0, 0);

    // --- weight chain on s1 ---
    cudaMemsetAsync(pM, 0, (size_t)HH * HH * sizeof(float), s1);
    nt_split<<<dim3(HH / 128, HH / 128, 4), 256, 0, s1>>>(Wbil, Wv);
    nn_atomic<<<dim3(HH / 128, HH / 128, 4), 256, 0, s1>>>(Wk, pM);
    cudaEventRecord(e1, s1);

    // --- data chain on the capture (default) stream ---
    topk_kernel<<<dim3(BB, 2), 512>>>(logits, mask, bboxes, out);
    setupA<<<99, 256>>>(bk, Wbil, bv);
    setupB<<<193, 256>>>(Wv, Wk, bv, Ws2, bs2, Wf1, bf1);
    growdot_kernel<<<dim3((BB * MC) / 8, 2), 256>>>(seq);

    // join: u needs both g_M (s1) and g_kidx (s0)
    cudaStreamWaitEvent(0, e1, 0);

    u_gemm_tf32<<<dim3(HH / 128, (BB * MC) / 128, 2), 256>>>(seq, pM);
    biaf_splitk<<<dim3(4, BB), 256>>>(seq);
    pair_kernel<<<dim3(MC / 4, BB), 128>>>(out, Ws1, bs1, Wf1, Wf2, bf2, bbil);

    cudaEventDestroy(e0);
    cudaEventDestroy(e1);
    cudaStreamDestroy(s1);
}

// round 15
// speedup vs baseline: 2.3953x; 1.0294x over previous
#include <cuda_runtime.h>
#include <math.h>
#include <stdint.h>

#define BB 32
#define SS 512
#define HH 768
#define MC 128
#define EPSF 1e-8f
#define TK 16

// ---------------- scratch (static device memory; no allocs) ----------------
__device__ int   g_kidx[BB*MC];
__device__ int   g_vidx[BB*MC];
__device__ float g_kbox[BB*MC*4];
__device__ float g_vbox[BB*MC*4];
__device__ float g_uA[BB*MC*HH];
__device__ float g_uB[BB*MC*HH];
__device__ float g_biaf4[4][BB*MC*MC];
__device__ float g_Wc2s[4][HH*HH]; // Wbil @ Wv^T, 4 K-split partials
__device__ float g_M[HH*HH];       // Wk @ Wc2
__device__ float g_s1[HH];         // bk @ Wbil
__device__ float g_r[HH];          // Wbil @ bv
__device__ float g_q[HH];          // Wv @ s1
__device__ float g_p[HH];          // Wk @ r
__device__ float g_c[1];           // s1 . bv
__device__ float g_rowk[BB*MC];
__device__ float g_rowv[BB*MC];
__device__ float g_W2f[64*16];
__device__ float g_b2f[16];

__device__ __forceinline__ unsigned int f2tf32(float x) {
    unsigned int r;
    asm("cvt.rna.tf32.f32 %0, %1;" : "=r"(r) : "f"(x));
    return r;
}
__device__ __forceinline__ float tf(float x) { return __uint_as_float(f2tf32(x)); }

#define TF32_COMPUTE(CUR) do { \
    _Pragma("unroll") \
    for (int ks = 0; ks < TK; ks += 8) { \
        uint32_t af[4][4]; \
        _Pragma("unroll") \
        for (int mf = 0; mf < 4; mf++) { \
            int mb = mw + mf * 16 + lm; \
            af[mf][0] = __float_as_uint(As[CUR][ks + lk][mb]); \
            af[mf][1] = __float_as_uint(As[CUR][ks + lk][mb + 8]); \
            af[mf][2] = __float_as_uint(As[CUR][ks + lk + 4][mb]); \
            af[mf][3] = __float_as_uint(As[CUR][ks + lk + 4][mb + 8]); \
        } \
        uint32_t bf[4][2]; \
        _Pragma("unroll") \
        for (int nf = 0; nf < 4; nf++) { \
            int nb = nw + nf * 8 + lm; \
            bf[nf][0] = __float_as_uint(Bs[CUR][ks + lk][nb]); \
            bf[nf][1] = __float_as_uint(Bs[CUR][ks + lk + 4][nb]); \
        } \
        _Pragma("unroll") \
        for (int mf = 0; mf < 4; mf++) \
            _Pragma("unroll") \
            for (int nf = 0; nf < 4; nf++) { \
                asm volatile( \
                    "mma.sync.aligned.m16n8k8.row.col.f32.tf32.tf32.f32 " \
                    "{%0,%1,%2,%3}, {%4,%5,%6,%7}, {%8,%9}, {%0,%1,%2,%3};" \
                    : "+f"(acc[mf][nf][0]), "+f"(acc[mf][nf][1]), \
                      "+f"(acc[mf][nf][2]), "+f"(acc[mf][nf][3]) \
                    : "r"(af[mf][0]), "r"(af[mf][1]), "r"(af[mf][2]), "r"(af[mf][3]), \
                      "r"(bf[nf][0]), "r"(bf[nf][1])); \
            } \
    } \
} while (0)

#define TF32_DECL_FRAG() \
    int wid = tid >> 5; \
    int lane = tid & 31; \
    int mw = (wid & 1) * 64; \
    int nw = (wid >> 1) * 32; \
    int lm = lane >> 2; \
    int lk = lane & 3; \
    float acc[4][4][4]; \
    _Pragma("unroll") \
    for (int mf = 0; mf < 4; mf++) \
        _Pragma("unroll") \
        for (int nf = 0; nf < 4; nf++) \
            _Pragma("unroll") \
            for (int e = 0; e < 4; e++) acc[mf][nf][e] = 0.f;

// -------- 1+2) conf (inline) + exact top-128 of 512 via bitonic sort ------
__global__ void topk_kernel(const float* __restrict__ logits,
                            const int* __restrict__ mask,
                            const float* __restrict__ bboxes,
                            float* __restrict__ out) {
    int b = blockIdx.x;
    int which = blockIdx.y;   // 0 = key, 1 = val
    __shared__ float sc[512];
    __shared__ int   si[512];
    int tid = threadIdx.x;

    {   // inline confidence
        int t = b * SS + tid;
        float l0 = logits[3*t+0], l1 = logits[3*t+1], l2 = logits[3*t+2];
        int pred = 0; float best = l0;
        if (l1 > best) { pred = 1; best = l1; }
        if (l2 > best) { pred = 2; best = l2; }
        float e0 = expf(l0 - best), e1 = expf(l1 - best), e2 = expf(l2 - best);
        float inv = 1.0f / (e0 + e1 + e2);
        bool valid = (mask[t] == 1);
        float conf;
        if (which == 0) conf = (pred == 1 && valid) ? e1 * inv : -INFINITY;
        else            conf = (pred == 2 && valid) ? e2 * inv : -INFINITY;
        sc[tid] = conf; si[tid] = tid;
    }

    for (int k = 2; k <= 512; k <<= 1) {
        for (int j = k >> 1; j > 0; j >>= 1) {
            __syncthreads();
            int ixj = tid ^ j;
            if (ixj > tid) {
                float c1 = sc[tid], c2 = sc[ixj];
                int   i1 = si[tid], i2 = si[ixj];
                bool b2 = (c2 > c1) || (c2 == c1 && i2 < i1);
                bool doswap = ((tid & k) == 0) ? b2 : !b2;
                if (doswap) {
                    sc[tid] = c2; si[tid] = i2;
                    sc[ixj] = c1; si[ixj] = i1;
                }
            }
        }
    }
    __syncthreads();

    if (tid < MC) {
        int   idx = si[tid];
        float cf  = sc[tid];
        int*   gi = (which == 0) ? g_kidx : g_vidx;
        float* gb = (which == 0) ? g_kbox : g_vbox;
        gi[b * MC + tid] = idx;
        const float* src = bboxes + ((long long)b * SS + idx) * 4;
        float* dst = gb + (b * MC + tid) * 4;
        dst[0] = src[0]; dst[1] = src[1]; dst[2] = src[2]; dst[3] = src[3];
        long long base = (long long)BB * MC * MC;            // 524288
        float vf = (cf != -INFINITY) ? 1.0f : 0.0f;
        out[base + (long long)which * (BB * MC) + b * MC + tid] = vf;
        out[base + 2LL * (BB * MC) + (long long)which * (BB * MC) + b * MC + tid] = (float)idx;
    }
}

// ----- setupA: s1 = bk @ Wbil (8-way ILP) ; r = Wbil @ bv (warp dot) -------
__global__ void setupA(const float* __restrict__ bk,
                       const float* __restrict__ Wbil,
                       const float* __restrict__ bv) {
    int bx = blockIdx.x, tid = threadIdx.x;
    if (bx < 3) {
        int j = bx * 256 + tid;
        float a0 = 0.f, a1 = 0.f, a2 = 0.f, a3 = 0.f;
        float a4 = 0.f, a5 = 0.f, a6 = 0.f, a7 = 0.f;
        for (int h = 0; h < HH; h += 8) {
            a0 = fmaf(bk[h+0], Wbil[(long long)(h+0) * HH + j], a0);
            a1 = fmaf(bk[h+1], Wbil[(long long)(h+1) * HH + j], a1);
            a2 = fmaf(bk[h+2], Wbil[(long long)(h+2) * HH + j], a2);
            a3 = fmaf(bk[h+3], Wbil[(long long)(h+3) * HH + j], a3);
            a4 = fmaf(bk[h+4], Wbil[(long long)(h+4) * HH + j], a4);
            a5 = fmaf(bk[h+5], Wbil[(long long)(h+5) * HH + j], a5);
            a6 = fmaf(bk[h+6], Wbil[(long long)(h+6) * HH + j], a6);
            a7 = fmaf(bk[h+7], Wbil[(long long)(h+7) * HH + j], a7);
        }
        g_s1[j] = ((a0 + a1) + (a2 + a3)) + ((a4 + a5) + (a6 + a7));
    } else {
        int row = (bx - 3) * 8 + (tid >> 5);
        int lane = tid & 31;
        const float* rp = Wbil + (long long)row * HH;
        float s = 0.f;
        #pragma unroll 4
        for (int cdx = lane; cdx < HH; cdx += 32) s = fmaf(rp[cdx], bv[cdx], s);
        #pragma unroll
        for (int o = 16; o; o >>= 1) s += __shfl_xor_sync(0xffffffffu, s, o);
        if (lane == 0) g_r[row] = s;
    }
}

// -------- setupB: q = Wv@s1 ; p = Wk@r ; c = s1.bv ; MLP fold --------------
__global__ void setupB(const float* __restrict__ Wv, const float* __restrict__ Wk,
                       const float* __restrict__ bv,
                       const float* __restrict__ Ws2, const float* __restrict__ bs2,
                       const float* __restrict__ Wf1, const float* __restrict__ bf1) {
    int bx = blockIdx.x, tid = threadIdx.x;
    if (bx < 192) {
        const float* A   = (bx < 96) ? Wv : Wk;
        const float* x   = (bx < 96) ? g_s1 : g_r;
        float* outv      = (bx < 96) ? g_q : g_p;
        int row = ((bx < 96) ? bx : bx - 96) * 8 + (tid >> 5);
        int lane = tid & 31;
        const float* rp = A + (long long)row * HH;
        float s = 0.f;
        #pragma unroll 4
        for (int cdx = lane; cdx < HH; cdx += 32) s = fmaf(rp[cdx], x[cdx], s);
        #pragma unroll
        for (int o = 16; o; o >>= 1) s += __shfl_xor_sync(0xffffffffu, s, o);
        if (lane == 0) outv[row] = s;
    } else {
        #pragma unroll
        for (int e = 0; e < 4; e++) {
            int o = tid * 4 + e;
            if (o < 1024) {
                int u = o >> 4, t = o & 15;
                float s = 0.f;
                #pragma unroll
                for (int s2 = 0; s2 < 32; s2++)
                    s = fmaf(Ws2[u * 32 + s2], Wf1[(s2 + 1) * 16 + t], s);
                g_W2f[o] = s;
            }
        }
        if (tid < 16) {
            float s = bf1[tid];
            #pragma unroll
            for (int s2 = 0; s2 < 32; s2++)
                s = fmaf(bs2[s2], Wf1[(s2 + 1) * 16 + tid], s);
            g_b2f[tid] = s;
        }
        __shared__ float red[256];
        float s = 0.f;
        for (int g = tid; g < HH; g += 256) s = fmaf(g_s1[g], bv[g], s);
        red[tid] = s; __syncthreads();
        for (int o = 128; o; o >>= 1) { if (tid < o) red[tid] += red[tid + o]; __syncthreads(); }
        if (tid == 0) g_c[0] = red[0];
    }
}

// ------ NT tf32 split-K x4, plain stores: Wc2_s = Wbil @ Wv^T --------------
__global__ __launch_bounds__(256)
void nt_split(const float* __restrict__ A, const float* __restrict__ B) {
    __shared__ __align__(16) float As[2][TK][136];
    __shared__ __align__(16) float Bs[2][TK][136];
    const int nslabs = 12;
    int tid = threadIdx.x;
    int m0 = blockIdx.y * 128, n0 = blockIdx.x * 128;
    int kbase = blockIdx.z * nslabs * TK;
    int ar0 = tid >> 2, ak = (tid & 3) * 4, ar1 = ar0 + 64;

    float4 a0v, a1v, b0v, b1v;
#define LOAD(K0) do { \
        a0v = *(const float4*)(A + (long long)(m0 + ar0) * HH + (K0) + ak); \
        a1v = *(const float4*)(A + (long long)(m0 + ar1) * HH + (K0) + ak); \
        b0v = *(const float4*)(B + (long long)(n0 + ar0) * HH + (K0) + ak); \
        b1v = *(const float4*)(B + (long long)(n0 + ar1) * HH + (K0) + ak); \
    } while (0)
#define STORE(BUF) do { \
        As[BUF][ak+0][ar0] = tf(a0v.x); As[BUF][ak+1][ar0] = tf(a0v.y); \
        As[BUF][ak+2][ar0] = tf(a0v.z); As[BUF][ak+3][ar0] = tf(a0v.w); \
        As[BUF][ak+0][ar1] = tf(a1v.x); As[BUF][ak+1][ar1] = tf(a1v.y); \
        As[BUF][ak+2][ar1] = tf(a1v.z); As[BUF][ak+3][ar1] = tf(a1v.w); \
        Bs[BUF][ak+0][ar0] = tf(b0v.x); Bs[BUF][ak+1][ar0] = tf(b0v.y); \
        Bs[BUF][ak+2][ar0] = tf(b0v.z); Bs[BUF][ak+3][ar0] = tf(b0v.w); \
        Bs[BUF][ak+0][ar1] = tf(b1v.x); Bs[BUF][ak+1][ar1] = tf(b1v.y); \
        Bs[BUF][ak+2][ar1] = tf(b1v.z); Bs[BUF][ak+3][ar1] = tf(b1v.w); \
    } while (0)

    TF32_DECL_FRAG();

    LOAD(kbase); STORE(0); __syncthreads();
    for (int kt = 0; kt < nslabs; kt++) {
        int cur = kt & 1;
        if (kt + 1 < nslabs) LOAD(kbase + (kt + 1) * TK);
        TF32_COMPUTE(cur);
        if (kt + 1 < nslabs) { STORE(cur ^ 1); __syncthreads(); }
    }
    float* C = g_Wc2s[blockIdx.z];
    #pragma unroll
    for (int mf = 0; mf < 4; mf++)
        #pragma unroll
        for (int nf = 0; nf < 4; nf++) {
            long long r0 = m0 + mw + mf * 16 + lm;
            long long cc = n0 + nw + nf * 8 + lk * 2;
            float2 v0 = { acc[mf][nf][0], acc[mf][nf][1] };
            float2 v1 = { acc[mf][nf][2], acc[mf][nf][3] };
            *(float2*)&C[r0 * HH + cc]       = v0;
            *(float2*)&C[(r0 + 8) * HH + cc] = v1;
        }
#undef LOAD
#undef STORE
}

// ------ NN tf32 split-K x4 atomic: M = Wk @ sum(Wc2_s) ---------------------
__global__ __launch_bounds__(256)
void nn_atomic(const float* __restrict__ A, float* __restrict__ C) {
    __shared__ __align__(16) float As[2][TK][136];
    __shared__ __align__(16) float Bs[2][TK][136];
    const int nslabs = 12;
    int tid = threadIdx.x;
    int m0 = blockIdx.y * 128, c0 = blockIdx.x * 128;
    int kbase = blockIdx.z * nslabs * TK;
    int ar0 = tid >> 2, ak = (tid & 3) * 4, ar1 = ar0 + 64;
    int bk0 = tid >> 5, bcc = (tid & 31) * 4, bk1 = bk0 + 8;

    float4 a0v, a1v, b0v, b1v;
#define LOAD(K0) do { \
        a0v = *(const float4*)(A + (long long)(m0 + ar0) * HH + (K0) + ak); \
        a1v = *(const float4*)(A + (long long)(m0 + ar1) * HH + (K0) + ak); \
        long long o0 = (long long)((K0) + bk0) * HH + c0 + bcc; \
        long long o1 = (long long)((K0) + bk1) * HH + c0 + bcc; \
        float4 t0 = *(const float4*)(g_Wc2s[0] + o0); \
        float4 t1 = *(const float4*)(g_Wc2s[1] + o0); \
        float4 t2 = *(const float4*)(g_Wc2s[2] + o0); \
        float4 t3 = *(const float4*)(g_Wc2s[3] + o0); \
        b0v.x = t0.x + t1.x + t2.x + t3.x; b0v.y = t0.y + t1.y + t2.y + t3.y; \
        b0v.z = t0.z + t1.z + t2.z + t3.z; b0v.w = t0.w + t1.w + t2.w + t3.w; \
        t0 = *(const float4*)(g_Wc2s[0] + o1); \
        t1 = *(const float4*)(g_Wc2s[1] + o1); \
        t2 = *(const float4*)(g_Wc2s[2] + o1); \
        t3 = *(const float4*)(g_Wc2s[3] + o1); \
        b1v.x = t0.x + t1.x + t2.x + t3.x; b1v.y = t0.y + t1.y + t2.y + t3.y; \
        b1v.z = t0.z + t1.z + t2.z + t3.z; b1v.w = t0.w + t1.w + t2.w + t3.w; \
    } while (0)
#define STORE(BUF) do { \
        As[BUF][ak+0][ar0] = tf(a0v.x); As[BUF][ak+1][ar0] = tf(a0v.y); \
        As[BUF][ak+2][ar0] = tf(a0v.z); As[BUF][ak+3][ar0] = tf(a0v.w); \
        As[BUF][ak+0][ar1] = tf(a1v.x); As[BUF][ak+1][ar1] = tf(a1v.y); \
        As[BUF][ak+2][ar1] = tf(a1v.z); As[BUF][ak+3][ar1] = tf(a1v.w); \
        float4 cb0, cb1; \
        cb0.x = tf(b0v.x); cb0.y = tf(b0v.y); cb0.z = tf(b0v.z); cb0.w = tf(b0v.w); \
        cb1.x = tf(b1v.x); cb1.y = tf(b1v.y); cb1.z = tf(b1v.z); cb1.w = tf(b1v.w); \
        *(float4*)&Bs[BUF][bk0][bcc] = cb0; \
        *(float4*)&Bs[BUF][bk1][bcc] = cb1; \
    } while (0)

    TF32_DECL_FRAG();

    LOAD(kbase); STORE(0); __syncthreads();
    for (int kt = 0; kt < nslabs; kt++) {
        int cur = kt & 1;
        if (kt + 1 < nslabs) LOAD(kbase + (kt + 1) * TK);
        TF32_COMPUTE(cur);
        if (kt + 1 < nslabs) { STORE(cur ^ 1); __syncthreads(); }
    }
    #pragma unroll
    for (int mf = 0; mf < 4; mf++)
        #pragma unroll
        for (int nf = 0; nf < 4; nf++) {
            long long r0 = m0 + mw + mf * 16 + lm;
            long long cc = c0 + nw + nf * 8 + lk * 2;
            atomicAdd(&C[r0 * HH + cc],           acc[mf][nf][0]);
            atomicAdd(&C[r0 * HH + cc + 1],       acc[mf][nf][1]);
            atomicAdd(&C[(r0 + 8) * HH + cc],     acc[mf][nf][2]);
            atomicAdd(&C[(r0 + 8) * HH + cc + 1], acc[mf][nf][3]);
        }
#undef LOAD
#undef STORE
}

// --- u = Gk(seq) @ M : tf32 mma, 128x128 tile, split-K x2 ------------------
__global__ __launch_bounds__(256)
void u_gemm_tf32(const float* __restrict__ A, const float* __restrict__ Bm) {
    __shared__ __align__(16) float As[2][TK][136];
    __shared__ __align__(16) float Bs[2][TK][136];
    __shared__ long long rowbase[128];
    const int nslabs = 24;     // 384 K per split

    int tid = threadIdx.x;
    int m0 = blockIdx.y * 128, c0 = blockIdx.x * 128;
    int kbase = blockIdx.z * nslabs * TK;
    float* C = blockIdx.z ? g_uB : g_uA;

    if (tid < 128) {
        int m = m0 + tid;
        rowbase[tid] = ((long long)(m >> 7) * SS + g_kidx[m]) * HH;
    }
    __syncthreads();

    int ar0 = tid >> 2, ak0 = (tid & 3) * 4, ar1 = ar0 + 64;
    int bk0 = tid >> 5, bc0 = (tid & 31) * 4, bk1 = bk0 + 8;
    long long ra0 = rowbase[ar0];
    long long ra1 = rowbase[ar1];

    float4 a0v, a1v, b0v, b1v;
#define LOAD_REGS(K0) do { \
        a0v = *(const float4*)(A + ra0 + (K0) + ak0); \
        a1v = *(const float4*)(A + ra1 + (K0) + ak0); \
        b0v = *(const float4*)(Bm + (long long)((K0) + bk0) * HH + c0 + bc0); \
        b1v = *(const float4*)(Bm + (long long)((K0) + bk1) * HH + c0 + bc0); \
    } while (0)
#define STORE_SMEM(BUF) do { \
        As[BUF][ak0+0][ar0] = tf(a0v.x); As[BUF][ak0+1][ar0] = tf(a0v.y); \
        As[BUF][ak0+2][ar0] = tf(a0v.z); As[BUF][ak0+3][ar0] = tf(a0v.w); \
        As[BUF][ak0+0][ar1] = tf(a1v.x); As[BUF][ak0+1][ar1] = tf(a1v.y); \
        As[BUF][ak0+2][ar1] = tf(a1v.z); As[BUF][ak0+3][ar1] = tf(a1v.w); \
        float4 cb0, cb1; \
        cb0.x = tf(b0v.x); cb0.y = tf(b0v.y); cb0.z = tf(b0v.z); cb0.w = tf(b0v.w); \
        cb1.x = tf(b1v.x); cb1.y = tf(b1v.y); cb1.z = tf(b1v.z); cb1.w = tf(b1v.w); \
        *(float4*)&Bs[BUF][bk0][bc0] = cb0; \
        *(float4*)&Bs[BUF][bk1][bc0] = cb1; \
    } while (0)

    TF32_DECL_FRAG();

    LOAD_REGS(kbase);
    STORE_SMEM(0);
    __syncthreads();

    for (int kt = 0; kt < nslabs; kt++) {
        int cur = kt & 1;
        if (kt + 1 < nslabs) LOAD_REGS(kbase + (kt + 1) * TK);
        TF32_COMPUTE(cur);
        if (kt + 1 < nslabs) { STORE_SMEM(cur ^ 1); __syncthreads(); }
    }

    #pragma unroll
    for (int mf = 0; mf < 4; mf++) {
        #pragma unroll
        for (int nf = 0; nf < 4; nf++) {
            long long r0 = m0 + mw + mf * 16 + lm;
            long long cc = c0 + nw + nf * 8 + lk * 2;
            float2 v0 = { acc[mf][nf][0], acc[mf][nf][1] };
            float2 v1 = { acc[mf][nf][2], acc[mf][nf][3] };
            *(float2*)&C[r0 * HH + cc]       = v0;
            *(float2*)&C[(r0 + 8) * HH + cc] = v1;
        }
    }
#undef LOAD_REGS
#undef STORE_SMEM
}

// -------- rowk = Gk.p ; rowv = Gv.q + c  (warp per row) --------------------
__global__ void growdot_kernel(const float* __restrict__ seq) {
    int r = blockIdx.x * 8 + (threadIdx.x >> 5);
    int lane = threadIdx.x & 31;
    int which = blockIdx.y;
    const int* gidx = which ? g_vidx : g_kidx;
    const float* vec = which ? g_q : g_p;
    const float* row = seq + ((long long)(r >> 7) * SS + gidx[r]) * HH;
    float s = 0.f;
    #pragma unroll 4
    for (int cdx = lane; cdx < HH; cdx += 32) s = fmaf(row[cdx], vec[cdx], s);
    #pragma unroll
    for (int o = 16; o; o >>= 1) s += __shfl_xor_sync(0xffffffffu, s, o);
    if (lane == 0) {
        if (which) g_rowv[r] = s + g_c[0];
        else       g_rowk[r] = s;
    }
}

// -- biaffine tf32: biaf4[s][b,i,j] = (uA+uB)[b,i,ks] . Gv_seq[b,j,ks] ------
__global__ __launch_bounds__(256)
void biaf_splitk(const float* __restrict__ seq) {
    __shared__ __align__(16) float As[2][TK][136];
    __shared__ __align__(16) float Bs[2][TK][136];
    __shared__ long long vrowbase[128];
    const int nslabs = 12;
    int b = blockIdx.y;
    int split = blockIdx.x;
    int kbase = split * nslabs * TK;
    int tid = threadIdx.x;

    const float* A0 = g_uA + (long long)b * MC * HH;
    const float* A1 = g_uB + (long long)b * MC * HH;

    if (tid < 128)
        vrowbase[tid] = ((long long)b * SS + g_vidx[b * MC + tid]) * HH;
    __syncthreads();

    int ar0 = tid >> 2, ak = (tid & 3) * 4, ar1 = ar0 + 64;
    long long vb0 = vrowbase[ar0];
    long long vb1 = vrowbase[ar1];

    float4 a0v, a1v, b0v, b1v;
#define LOAD(K0) do { \
        float4 x0 = *(const float4*)(A0 + (long long)ar0 * HH + (K0) + ak); \
        float4 x1 = *(const float4*)(A1 + (long long)ar0 * HH + (K0) + ak); \
        a0v.x = x0.x + x1.x; a0v.y = x0.y + x1.y; a0v.z = x0.z + x1.z; a0v.w = x0.w + x1.w; \
        x0 = *(const float4*)(A0 + (long long)ar1 * HH + (K0) + ak); \
        x1 = *(const float4*)(A1 + (long long)ar1 * HH + (K0) + ak); \
        a1v.x = x0.x + x1.x; a1v.y = x0.y + x1.y; a1v.z = x0.z + x1.z; a1v.w = x0.w + x1.w; \
        b0v = *(const float4*)(seq + vb0 + (K0) + ak); \
        b1v = *(const float4*)(seq + vb1 + (K0) + ak); \
    } while (0)
#define STORE(BUF) do { \
        As[BUF][ak+0][ar0] = tf(a0v.x); As[BUF][ak+1][ar0] = tf(a0v.y); \
        As[BUF][ak+2][ar0] = tf(a0v.z); As[BUF][ak+3][ar0] = tf(a0v.w); \
        As[BUF][ak+0][ar1] = tf(a1v.x); As[BUF][ak+1][ar1] = tf(a1v.y); \
        As[BUF][ak+2][ar1] = tf(a1v.z); As[BUF][ak+3][ar1] = tf(a1v.w); \
        Bs[BUF][ak+0][ar0] = tf(b0v.x); Bs[BUF][ak+1][ar0] = tf(b0v.y); \
        Bs[BUF][ak+2][ar0] = tf(b0v.z); Bs[BUF][ak+3][ar0] = tf(b0v.w); \
        Bs[BUF][ak+0][ar1] = tf(b1v.x); Bs[BUF][ak+1][ar1] = tf(b1v.y); \
        Bs[BUF][ak+2][ar1] = tf(b1v.z); Bs[BUF][ak+3][ar1] = tf(b1v.w); \
    } while (0)

    TF32_DECL_FRAG();

    LOAD(kbase); STORE(0); __syncthreads();
    for (int kt = 0; kt < nslabs; kt++) {
        int cur = kt & 1;
        if (kt + 1 < nslabs) LOAD(kbase + (kt + 1) * TK);
        TF32_COMPUTE(cur);
        if (kt + 1 < nslabs) { STORE(cur ^ 1); __syncthreads(); }
    }

    float* dst = g_biaf4[split] + (long long)b * (MC * MC);
    #pragma unroll
    for (int mf = 0; mf < 4; mf++)
        #pragma unroll
        for (int nf = 0; nf < 4; nf++) {
            int r0 = mw + mf * 16 + lm;
            int cc = nw + nf * 8 + lk * 2;
            float2 v0 = { acc[mf][nf][0], acc[mf][nf][1] };
            float2 v1 = { acc[mf][nf][2], acc[mf][nf][3] };
            *(float2*)&dst[r0 * MC + cc]       = v0;
            *(float2*)&dst[(r0 + 8) * MC + cc] = v1;
        }
#undef LOAD
#undef STORE
}

// ----- spatial features + folded MLP, 4 key rows per thread ---------------
__global__ __launch_bounds__(128)
void pair_kernel(float* __restrict__ out,
                 const float* __restrict__ Ws1, const float* __restrict__ bs1,
                 const float* __restrict__ Wf1,
                 const float* __restrict__ Wf2, const float* __restrict__ bf2,
                 const float* __restrict__ bbilp) {
    __shared__ float sW1[8 * 64], sb1[64];
    __shared__ float sW2f[64 * 16], sb2f[16];
    __shared__ float sF0[16], sF2[16];
    __shared__ float sbf2, sbil;
    __shared__ float kb[4][4];
    __shared__ float srowk[4];

    int b = blockIdx.y;
    int i0 = blockIdx.x * 4;
    int j = threadIdx.x;

    for (int t = j; t < 512;  t += 128) sW1[t] = Ws1[t];
    for (int t = j; t < 1024; t += 128) sW2f[t] = g_W2f[t];
    if (j < 64) sb1[j] = bs1[j];
    if (j < 16) { sb2f[j] = g_b2f[j]; sF0[j] = Wf1[j]; sF2[j] = Wf2[j]; }
    if (j == 0) { sbf2 = bf2[0]; sbil = bbilp[0]; }
    if (j < 4)  srowk[j] = g_rowk[b * MC + i0 + j];
    if (j < 16) kb[j >> 2][j & 3] = g_kbox[(b * MC + i0 + (j >> 2)) * 4 + (j & 3)];
    __syncthreads();

    float vx1 = g_vbox[(b * MC + j) * 4 + 0];
    float vy1 = g_vbox[(b * MC + j) * 4 + 1];
    float vx2 = g_vbox[(b * MC + j) * 4 + 2];
    float vy2 = g_vbox[(b * MC + j) * 4 + 3];
    float vcx = (vx1 + vx2) * 0.5f, vcy = (vy1 + vy2) * 0.5f;
    float vh = vy2 - vy1, vw = vx2 - vx1;

    float sfa[4][8];
    #pragma unroll
    for (int s = 0; s < 4; s++) {
        float kx1 = kb[s][0], ky1 = kb[s][1], kx2 = kb[s][2], ky2 = kb[s][3];
        float kcx = (kx1 + kx2) * 0.5f, kcy = (ky1 + ky2) * 0.5f;
        float dx = vcx - kcx, dy = vcy - kcy;
        float dist  = sqrtf(dx * dx + dy * dy + EPSF);
        float angle = atan2f(dy, dx);
        float kh = ky2 - ky1, kw = kx2 - kx1;
        float h_ov = fmaxf(fminf(ky2, vy2) - fmaxf(ky1, vy1), 0.0f);
        float h_align = h_ov / (fminf(kh, vh) + EPSF);
        float v_ov = fmaxf(fminf(kx2, vx2) - fmaxf(kx1, vx1), 0.0f);
        float v_align = v_ov / (fminf(kw, vw) + EPSF);
        float area_ratio   = (vh * vw) / (kh * kw + EPSF);
        float aspect_ratio = (vw / (vh + EPSF)) / (kw / (kh + EPSF));
        sfa[s][0] = dx; sfa[s][1] = dy; sfa[s][2] = dist; sfa[s][3] = angle;
        sfa[s][4] = h_align; sfa[s][5] = v_align;
        sfa[s][6] = area_ratio; sfa[s][7] = aspect_ratio;
    }

    float rowvj = g_rowv[b * MC + j];
    long long bidx[4];
    float biafv[4];
    #pragma unroll
    for (int s = 0; s < 4; s++) {
        bidx[s] = (long long)b * (MC * MC) + (i0 + s) * MC + j;
        float v = srowk[s] + rowvj + sbil;
        #pragma unroll
        for (int sp = 0; sp < 4; sp++) v += g_biaf4[sp][bidx[s]];
        biafv[s] = v;
    }

    float f1[4][16];
    #pragma unroll
    for (int t = 0; t < 16; t++) {
        float f0 = sF0[t], bb = sb2f[t];
        #pragma unroll
        for (int s = 0; s < 4; s++) f1[s][t] = fmaf(biafv[s], f0, bb);
    }

    for (int u = 0; u < 64; u++) {
        float h[4];
        float hb = sb1[u];
        #pragma unroll
        for (int s = 0; s < 4; s++) h[s] = hb;
        #pragma unroll
        for (int f = 0; f < 8; f++) {
            float w = sW1[f * 64 + u];
            #pragma unroll
            for (int s = 0; s < 4; s++) h[s] = fmaf(sfa[s][f], w, h[s]);
        }
        #pragma unroll
        for (int s = 0; s < 4; s++) h[s] = fmaxf(h[s], 0.0f);
        #pragma unroll
        for (int t = 0; t < 16; t++) {
            float w2 = sW2f[u * 16 + t];
            #pragma unroll
            for (int s = 0; s < 4; s++) f1[s][t] = fmaf(h[s], w2, f1[s][t]);
        }
    }

    float sc[4];
    #pragma unroll
    for (int s = 0; s < 4; s++) sc[s] = sbf2;
    #pragma unroll
    for (int t = 0; t < 16; t++) {
        float w = sF2[t];
        #pragma unroll
        for (int s = 0; s < 4; s++)
            sc[s] = fmaf(fmaxf(f1[s][t], 0.0f), w, sc[s]);
    }
    #pragma unroll
    for (int s = 0; s < 4; s++) out[bidx[s]] = sc[s];
}

// ---------------- launch ----------------
extern "C" void kernel_launch(void* const* d_in, const int* in_sizes, int n_in,
                              void* d_out, int out_size) {
    (void)in_sizes; (void)n_in; (void)out_size;
    const float* seq    = (const float*)d_in[0];
    const float* logits = (const float*)d_in[1];
    const float* bboxes = (const float*)d_in[2];
    const int*   mask   = (const int*)  d_in[3];
    const float* Wk  = (const float*)d_in[4];
    const float* bk  = (const float*)d_in[5];
    const float* Wv  = (const float*)d_in[6];
    const float* bv  = (const float*)d_in[7];
    const float* Wbil= (const float*)d_in[8];
    const float* bbil= (const float*)d_in[9];
    const float* Ws1 = (const float*)d_in[10];
    const float* bs1 = (const float*)d_in[11];
    const float* Ws2 = (const float*)d_in[12];
    const float* bs2 = (const float*)d_in[13];
    const float* Wf1 = (const float*)d_in[14];
    const float* bf1 = (const float*)d_in[15];
    const float* Wf2 = (const float*)d_in[16];
    const float* bf2 = (const float*)d_in[17];
    float* out = (float*)d_out;

    float *pM;
    cudaGetSymbolAddress((void**)&pM, g_M);

    // three-way fork:
    //  s1 = weight chain (memset -> nt -> nn)          [~35 us]
    //  s2 = setup chain (setupA -> setupB)             [~15 us, weights-only]
    //  s0 = topk                                       [~25 us]
    // joins: growdot needs s0(topk) + s2(setupB);
    //        u needs s0(topk) + s1(nn).
    cudaStream_t s1, s2;
    cudaStreamCreateWithFlags(&s1, cudaStreamNonBlocking);
    cudaStreamCreateWithFlags(&s2, cudaStreamNonBlocking);
    cudaEvent_t e0, e1, e2;
    cudaEventCreateWithFlags(&e0, cudaEventDisableTiming);
    cudaEventCreateWithFlags(&e1, cudaEventDisableTiming);
    cudaEventCreateWithFlags(&e2, cudaEventDisableTiming);

    cudaEventRecord(e0, 0);
    cudaStreamWaitEvent(s1, e0, 0);
    cudaStreamWaitEvent(s2, e0, 0);

    // --- weight chain on s1 ---
    cudaMemsetAsync(pM, 0, (size_t)HH * HH * sizeof(float), s1);
    nt_split<<<dim3(HH / 128, HH / 128, 4), 256, 0, s1>>>(Wbil, Wv);
    nn_atomic<<<dim3(HH / 128, HH / 128, 4), 256, 0, s1>>>(Wk, pM);
    cudaEventRecord(e1, s1);

    // --- setup chain on s2 (weights-only inputs) ---
    setupA<<<99, 256, 0, s2>>>(bk, Wbil, bv);
    setupB<<<193, 256, 0, s2>>>(Wv, Wk, bv, Ws2, bs2, Wf1, bf1);
    cudaEventRecord(e2, s2);

    // --- topk on default stream ---
    topk_kernel<<<dim3(BB, 2), 512>>>(logits, mask, bboxes, out);

    // growdot: needs topk (ordered on s0) + setup (e2)
    cudaStreamWaitEvent(0, e2, 0);
    growdot_kernel<<<dim3((BB * MC) / 8, 2), 256>>>(seq);

    // u: needs topk (ordered) + M (e1)
    cudaStreamWaitEvent(0, e1, 0);
    u_gemm_tf32<<<dim3(HH / 128, (BB * MC) / 128, 2), 256>>>(seq, pM);
    biaf_splitk<<<dim3(4, BB), 256>>>(seq);
    pair_kernel<<<dim3(MC / 4, BB), 128>>>(out, Ws1, bs1, Wf1, Wf2, bf2, bbil);

    cudaEventDestroy(e0);
    cudaEventDestroy(e1);
    cudaEventDestroy(e2);
    cudaStreamDestroy(s1);
    cudaStreamDestroy(s2);
}

// round 16
// speedup vs baseline: 2.5734x; 1.0744x over previous
#include <cuda_runtime.h>
#include <math.h>
#include <stdint.h>

#define BB 32
#define SS 512
#define HH 768
#define MC 128
#define EPSF 1e-8f
#define TK 16

// ---------------- scratch (static device memory; no allocs) ----------------
__device__ int   g_kidx[BB*MC];
__device__ int   g_vidx[BB*MC];
__device__ float g_kbox[BB*MC*4];
__device__ float g_vbox[BB*MC*4];
__device__ float g_uA[BB*MC*HH];
__device__ float g_uB[BB*MC*HH];
__device__ float g_biaf4[4][BB*MC*MC];
__device__ float g_Wc2s[4][HH*HH];
__device__ float g_M[HH*HH];
__device__ float g_s1[HH];
__device__ float g_r[HH];
__device__ float g_q[HH];
__device__ float g_p[HH];
__device__ float g_c[1];
__device__ float g_rowk[BB*MC];
__device__ float g_rowv[BB*MC];
__device__ float g_W2f[64*16];
__device__ float g_b2f[16];
__device__ float g_f1pre[(long long)BB*MC*MC*16];   // spatial-MLP partial

__device__ __forceinline__ unsigned int f2tf32(float x) {
    unsigned int r;
    asm("cvt.rna.tf32.f32 %0, %1;" : "=r"(r) : "f"(x));
    return r;
}
__device__ __forceinline__ float tf(float x) { return __uint_as_float(f2tf32(x)); }

#define TF32_COMPUTE(CUR) do { \
    _Pragma("unroll") \
    for (int ks = 0; ks < TK; ks += 8) { \
        uint32_t af[4][4]; \
        _Pragma("unroll") \
        for (int mf = 0; mf < 4; mf++) { \
            int mb = mw + mf * 16 + lm; \
            af[mf][0] = __float_as_uint(As[CUR][ks + lk][mb]); \
            af[mf][1] = __float_as_uint(As[CUR][ks + lk][mb + 8]); \
            af[mf][2] = __float_as_uint(As[CUR][ks + lk + 4][mb]); \
            af[mf][3] = __float_as_uint(As[CUR][ks + lk + 4][mb + 8]); \
        } \
        uint32_t bf[4][2]; \
        _Pragma("unroll") \
        for (int nf = 0; nf < 4; nf++) { \
            int nb = nw + nf * 8 + lm; \
            bf[nf][0] = __float_as_uint(Bs[CUR][ks + lk][nb]); \
            bf[nf][1] = __float_as_uint(Bs[CUR][ks + lk + 4][nb]); \
        } \
        _Pragma("unroll") \
        for (int mf = 0; mf < 4; mf++) \
            _Pragma("unroll") \
            for (int nf = 0; nf < 4; nf++) { \
                asm volatile( \
                    "mma.sync.aligned.m16n8k8.row.col.f32.tf32.tf32.f32 " \
                    "{%0,%1,%2,%3}, {%4,%5,%6,%7}, {%8,%9}, {%0,%1,%2,%3};" \
                    : "+f"(acc[mf][nf][0]), "+f"(acc[mf][nf][1]), \
                      "+f"(acc[mf][nf][2]), "+f"(acc[mf][nf][3]) \
                    : "r"(af[mf][0]), "r"(af[mf][1]), "r"(af[mf][2]), "r"(af[mf][3]), \
                      "r"(bf[nf][0]), "r"(bf[nf][1])); \
            } \
    } \
} while (0)

#define TF32_DECL_FRAG() \
    int wid = tid >> 5; \
    int lane = tid & 31; \
    int mw = (wid & 1) * 64; \
    int nw = (wid >> 1) * 32; \
    int lm = lane >> 2; \
    int lk = lane & 3; \
    float acc[4][4][4]; \
    _Pragma("unroll") \
    for (int mf = 0; mf < 4; mf++) \
        _Pragma("unroll") \
        for (int nf = 0; nf < 4; nf++) \
            _Pragma("unroll") \
            for (int e = 0; e < 4; e++) acc[mf][nf][e] = 0.f;

// -------- 1+2) conf (inline) + exact top-128 of 512 via bitonic sort ------
__global__ void topk_kernel(const float* __restrict__ logits,
                            const int* __restrict__ mask,
                            const float* __restrict__ bboxes,
                            float* __restrict__ out) {
    int b = blockIdx.x;
    int which = blockIdx.y;
    __shared__ float sc[512];
    __shared__ int   si[512];
    int tid = threadIdx.x;

    {
        int t = b * SS + tid;
        float l0 = logits[3*t+0], l1 = logits[3*t+1], l2 = logits[3*t+2];
        int pred = 0; float best = l0;
        if (l1 > best) { pred = 1; best = l1; }
        if (l2 > best) { pred = 2; best = l2; }
        float e0 = expf(l0 - best), e1 = expf(l1 - best), e2 = expf(l2 - best);
        float inv = 1.0f / (e0 + e1 + e2);
        bool valid = (mask[t] == 1);
        float conf;
        if (which == 0) conf = (pred == 1 && valid) ? e1 * inv : -INFINITY;
        else            conf = (pred == 2 && valid) ? e2 * inv : -INFINITY;
        sc[tid] = conf; si[tid] = tid;
    }

    for (int k = 2; k <= 512; k <<= 1) {
        for (int j = k >> 1; j > 0; j >>= 1) {
            __syncthreads();
            int ixj = tid ^ j;
            if (ixj > tid) {
                float c1 = sc[tid], c2 = sc[ixj];
                int   i1 = si[tid], i2 = si[ixj];
                bool b2 = (c2 > c1) || (c2 == c1 && i2 < i1);
                bool doswap = ((tid & k) == 0) ? b2 : !b2;
                if (doswap) {
                    sc[tid] = c2; si[tid] = i2;
                    sc[ixj] = c1; si[ixj] = i1;
                }
            }
        }
    }
    __syncthreads();

    if (tid < MC) {
        int   idx = si[tid];
        float cf  = sc[tid];
        int*   gi = (which == 0) ? g_kidx : g_vidx;
        float* gb = (which == 0) ? g_kbox : g_vbox;
        gi[b * MC + tid] = idx;
        const float* src = bboxes + ((long long)b * SS + idx) * 4;
        float* dst = gb + (b * MC + tid) * 4;
        dst[0] = src[0]; dst[1] = src[1]; dst[2] = src[2]; dst[3] = src[3];
        long long base = (long long)BB * MC * MC;
        float vf = (cf != -INFINITY) ? 1.0f : 0.0f;
        out[base + (long long)which * (BB * MC) + b * MC + tid] = vf;
        out[base + 2LL * (BB * MC) + (long long)which * (BB * MC) + b * MC + tid] = (float)idx;
    }
}

// ----- setupA: s1 = bk @ Wbil (8-way ILP) ; r = Wbil @ bv (warp dot) -------
__global__ void setupA(const float* __restrict__ bk,
                       const float* __restrict__ Wbil,
                       const float* __restrict__ bv) {
    int bx = blockIdx.x, tid = threadIdx.x;
    if (bx < 3) {
        int j = bx * 256 + tid;
        float a0 = 0.f, a1 = 0.f, a2 = 0.f, a3 = 0.f;
        float a4 = 0.f, a5 = 0.f, a6 = 0.f, a7 = 0.f;
        for (int h = 0; h < HH; h += 8) {
            a0 = fmaf(bk[h+0], Wbil[(long long)(h+0) * HH + j], a0);
            a1 = fmaf(bk[h+1], Wbil[(long long)(h+1) * HH + j], a1);
            a2 = fmaf(bk[h+2], Wbil[(long long)(h+2) * HH + j], a2);
            a3 = fmaf(bk[h+3], Wbil[(long long)(h+3) * HH + j], a3);
            a4 = fmaf(bk[h+4], Wbil[(long long)(h+4) * HH + j], a4);
            a5 = fmaf(bk[h+5], Wbil[(long long)(h+5) * HH + j], a5);
            a6 = fmaf(bk[h+6], Wbil[(long long)(h+6) * HH + j], a6);
            a7 = fmaf(bk[h+7], Wbil[(long long)(h+7) * HH + j], a7);
        }
        g_s1[j] = ((a0 + a1) + (a2 + a3)) + ((a4 + a5) + (a6 + a7));
    } else {
        int row = (bx - 3) * 8 + (tid >> 5);
        int lane = tid & 31;
        const float* rp = Wbil + (long long)row * HH;
        float s = 0.f;
        #pragma unroll 4
        for (int cdx = lane; cdx < HH; cdx += 32) s = fmaf(rp[cdx], bv[cdx], s);
        #pragma unroll
        for (int o = 16; o; o >>= 1) s += __shfl_xor_sync(0xffffffffu, s, o);
        if (lane == 0) g_r[row] = s;
    }
}

// -------- setupB: q = Wv@s1 ; p = Wk@r ; c = s1.bv ; MLP fold --------------
__global__ void setupB(const float* __restrict__ Wv, const float* __restrict__ Wk,
                       const float* __restrict__ bv,
                       const float* __restrict__ Ws2, const float* __restrict__ bs2,
                       const float* __restrict__ Wf1, const float* __restrict__ bf1) {
    int bx = blockIdx.x, tid = threadIdx.x;
    if (bx < 192) {
        const float* A   = (bx < 96) ? Wv : Wk;
        const float* x   = (bx < 96) ? g_s1 : g_r;
        float* outv      = (bx < 96) ? g_q : g_p;
        int row = ((bx < 96) ? bx : bx - 96) * 8 + (tid >> 5);
        int lane = tid & 31;
        const float* rp = A + (long long)row * HH;
        float s = 0.f;
        #pragma unroll 4
        for (int cdx = lane; cdx < HH; cdx += 32) s = fmaf(rp[cdx], x[cdx], s);
        #pragma unroll
        for (int o = 16; o; o >>= 1) s += __shfl_xor_sync(0xffffffffu, s, o);
        if (lane == 0) outv[row] = s;
    } else {
        #pragma unroll
        for (int e = 0; e < 4; e++) {
            int o = tid * 4 + e;
            if (o < 1024) {
                int u = o >> 4, t = o & 15;
                float s = 0.f;
                #pragma unroll
                for (int s2 = 0; s2 < 32; s2++)
                    s = fmaf(Ws2[u * 32 + s2], Wf1[(s2 + 1) * 16 + t], s);
                g_W2f[o] = s;
            }
        }
        if (tid < 16) {
            float s = bf1[tid];
            #pragma unroll
            for (int s2 = 0; s2 < 32; s2++)
                s = fmaf(bs2[s2], Wf1[(s2 + 1) * 16 + tid], s);
            g_b2f[tid] = s;
        }
        __shared__ float red[256];
        float s = 0.f;
        for (int g = tid; g < HH; g += 256) s = fmaf(g_s1[g], bv[g], s);
        red[tid] = s; __syncthreads();
        for (int o = 128; o; o >>= 1) { if (tid < o) red[tid] += red[tid + o]; __syncthreads(); }
        if (tid == 0) g_c[0] = red[0];
    }
}

// ------ NT tf32 split-K x4, plain stores: Wc2_s = Wbil @ Wv^T --------------
__global__ __launch_bounds__(256)
void nt_split(const float* __restrict__ A, const float* __restrict__ B) {
    __shared__ __align__(16) float As[2][TK][136];
    __shared__ __align__(16) float Bs[2][TK][136];
    const int nslabs = 12;
    int tid = threadIdx.x;
    int m0 = blockIdx.y * 128, n0 = blockIdx.x * 128;
    int kbase = blockIdx.z * nslabs * TK;
    int ar0 = tid >> 2, ak = (tid & 3) * 4, ar1 = ar0 + 64;

    float4 a0v, a1v, b0v, b1v;
#define LOAD(K0) do { \
        a0v = *(const float4*)(A + (long long)(m0 + ar0) * HH + (K0) + ak); \
        a1v = *(const float4*)(A + (long long)(m0 + ar1) * HH + (K0) + ak); \
        b0v = *(const float4*)(B + (long long)(n0 + ar0) * HH + (K0) + ak); \
        b1v = *(const float4*)(B + (long long)(n0 + ar1) * HH + (K0) + ak); \
    } while (0)
#define STORE(BUF) do { \
        As[BUF][ak+0][ar0] = tf(a0v.x); As[BUF][ak+1][ar0] = tf(a0v.y); \
        As[BUF][ak+2][ar0] = tf(a0v.z); As[BUF][ak+3][ar0] = tf(a0v.w); \
        As[BUF][ak+0][ar1] = tf(a1v.x); As[BUF][ak+1][ar1] = tf(a1v.y); \
        As[BUF][ak+2][ar1] = tf(a1v.z); As[BUF][ak+3][ar1] = tf(a1v.w); \
        Bs[BUF][ak+0][ar0] = tf(b0v.x); Bs[BUF][ak+1][ar0] = tf(b0v.y); \
        Bs[BUF][ak+2][ar0] = tf(b0v.z); Bs[BUF][ak+3][ar0] = tf(b0v.w); \
        Bs[BUF][ak+0][ar1] = tf(b1v.x); Bs[BUF][ak+1][ar1] = tf(b1v.y); \
        Bs[BUF][ak+2][ar1] = tf(b1v.z); Bs[BUF][ak+3][ar1] = tf(b1v.w); \
    } while (0)

    TF32_DECL_FRAG();

    LOAD(kbase); STORE(0); __syncthreads();
    for (int kt = 0; kt < nslabs; kt++) {
        int cur = kt & 1;
        if (kt + 1 < nslabs) LOAD(kbase + (kt + 1) * TK);
        TF32_COMPUTE(cur);
        if (kt + 1 < nslabs) { STORE(cur ^ 1); __syncthreads(); }
    }
    float* C = g_Wc2s[blockIdx.z];
    #pragma unroll
    for (int mf = 0; mf < 4; mf++)
        #pragma unroll
        for (int nf = 0; nf < 4; nf++) {
            long long r0 = m0 + mw + mf * 16 + lm;
            long long cc = n0 + nw + nf * 8 + lk * 2;
            float2 v0 = { acc[mf][nf][0], acc[mf][nf][1] };
            float2 v1 = { acc[mf][nf][2], acc[mf][nf][3] };
            *(float2*)&C[r0 * HH + cc]       = v0;
            *(float2*)&C[(r0 + 8) * HH + cc] = v1;
        }
#undef LOAD
#undef STORE
}

// ------ NN tf32 split-K x4 atomic: M = Wk @ sum(Wc2_s) ---------------------
__global__ __launch_bounds__(256)
void nn_atomic(const float* __restrict__ A, float* __restrict__ C) {
    __shared__ __align__(16) float As[2][TK][136];
    __shared__ __align__(16) float Bs[2][TK][136];
    const int nslabs = 12;
    int tid = threadIdx.x;
    int m0 = blockIdx.y * 128, c0 = blockIdx.x * 128;
    int kbase = blockIdx.z * nslabs * TK;
    int ar0 = tid >> 2, ak = (tid & 3) * 4, ar1 = ar0 + 64;
    int bk0 = tid >> 5, bcc = (tid & 31) * 4, bk1 = bk0 + 8;

    float4 a0v, a1v, b0v, b1v;
#define LOAD(K0) do { \
        a0v = *(const float4*)(A + (long long)(m0 + ar0) * HH + (K0) + ak); \
        a1v = *(const float4*)(A + (long long)(m0 + ar1) * HH + (K0) + ak); \
        long long o0 = (long long)((K0) + bk0) * HH + c0 + bcc; \
        long long o1 = (long long)((K0) + bk1) * HH + c0 + bcc; \
        float4 t0 = *(const float4*)(g_Wc2s[0] + o0); \
        float4 t1 = *(const float4*)(g_Wc2s[1] + o0); \
        float4 t2 = *(const float4*)(g_Wc2s[2] + o0); \
        float4 t3 = *(const float4*)(g_Wc2s[3] + o0); \
        b0v.x = t0.x + t1.x + t2.x + t3.x; b0v.y = t0.y + t1.y + t2.y + t3.y; \
        b0v.z = t0.z + t1.z + t2.z + t3.z; b0v.w = t0.w + t1.w + t2.w + t3.w; \
        t0 = *(const float4*)(g_Wc2s[0] + o1); \
        t1 = *(const float4*)(g_Wc2s[1] + o1); \
        t2 = *(const float4*)(g_Wc2s[2] + o1); \
        t3 = *(const float4*)(g_Wc2s[3] + o1); \
        b1v.x = t0.x + t1.x + t2.x + t3.x; b1v.y = t0.y + t1.y + t2.y + t3.y; \
        b1v.z = t0.z + t1.z + t2.z + t3.z; b1v.w = t0.w + t1.w + t2.w + t3.w; \
    } while (0)
#define STORE(BUF) do { \
        As[BUF][ak+0][ar0] = tf(a0v.x); As[BUF][ak+1][ar0] = tf(a0v.y); \
        As[BUF][ak+2][ar0] = tf(a0v.z); As[BUF][ak+3][ar0] = tf(a0v.w); \
        As[BUF][ak+0][ar1] = tf(a1v.x); As[BUF][ak+1][ar1] = tf(a1v.y); \
        As[BUF][ak+2][ar1] = tf(a1v.z); As[BUF][ak+3][ar1] = tf(a1v.w); \
        float4 cb0, cb1; \
        cb0.x = tf(b0v.x); cb0.y = tf(b0v.y); cb0.z = tf(b0v.z); cb0.w = tf(b0v.w); \
        cb1.x = tf(b1v.x); cb1.y = tf(b1v.y); cb1.z = tf(b1v.z); cb1.w = tf(b1v.w); \
        *(float4*)&Bs[BUF][bk0][bcc] = cb0; \
        *(float4*)&Bs[BUF][bk1][bcc] = cb1; \
    } while (0)

    TF32_DECL_FRAG();

    LOAD(kbase); STORE(0); __syncthreads();
    for (int kt = 0; kt < nslabs; kt++) {
        int cur = kt & 1;
        if (kt + 1 < nslabs) LOAD(kbase + (kt + 1) * TK);
        TF32_COMPUTE(cur);
        if (kt + 1 < nslabs) { STORE(cur ^ 1); __syncthreads(); }
    }
    #pragma unroll
    for (int mf = 0; mf < 4; mf++)
        #pragma unroll
        for (int nf = 0; nf < 4; nf++) {
            long long r0 = m0 + mw + mf * 16 + lm;
            long long cc = c0 + nw + nf * 8 + lk * 2;
            atomicAdd(&C[r0 * HH + cc],           acc[mf][nf][0]);
            atomicAdd(&C[r0 * HH + cc + 1],       acc[mf][nf][1]);
            atomicAdd(&C[(r0 + 8) * HH + cc],     acc[mf][nf][2]);
            atomicAdd(&C[(r0 + 8) * HH + cc + 1], acc[mf][nf][3]);
        }
#undef LOAD
#undef STORE
}

// --- u = Gk(seq) @ M : tf32 mma, 128x128 tile, split-K x2 ------------------
__global__ __launch_bounds__(256)
void u_gemm_tf32(const float* __restrict__ A, const float* __restrict__ Bm) {
    __shared__ __align__(16) float As[2][TK][136];
    __shared__ __align__(16) float Bs[2][TK][136];
    __shared__ long long rowbase[128];
    const int nslabs = 24;

    int tid = threadIdx.x;
    int m0 = blockIdx.y * 128, c0 = blockIdx.x * 128;
    int kbase = blockIdx.z * nslabs * TK;
    float* C = blockIdx.z ? g_uB : g_uA;

    if (tid < 128) {
        int m = m0 + tid;
        rowbase[tid] = ((long long)(m >> 7) * SS + g_kidx[m]) * HH;
    }
    __syncthreads();

    int ar0 = tid >> 2, ak0 = (tid & 3) * 4, ar1 = ar0 + 64;
    int bk0 = tid >> 5, bc0 = (tid & 31) * 4, bk1 = bk0 + 8;
    long long ra0 = rowbase[ar0];
    long long ra1 = rowbase[ar1];

    float4 a0v, a1v, b0v, b1v;
#define LOAD_REGS(K0) do { \
        a0v = *(const float4*)(A + ra0 + (K0) + ak0); \
        a1v = *(const float4*)(A + ra1 + (K0) + ak0); \
        b0v = *(const float4*)(Bm + (long long)((K0) + bk0) * HH + c0 + bc0); \
        b1v = *(const float4*)(Bm + (long long)((K0) + bk1) * HH + c0 + bc0); \
    } while (0)
#define STORE_SMEM(BUF) do { \
        As[BUF][ak0+0][ar0] = tf(a0v.x); As[BUF][ak0+1][ar0] = tf(a0v.y); \
        As[BUF][ak0+2][ar0] = tf(a0v.z); As[BUF][ak0+3][ar0] = tf(a0v.w); \
        As[BUF][ak0+0][ar1] = tf(a1v.x); As[BUF][ak0+1][ar1] = tf(a1v.y); \
        As[BUF][ak0+2][ar1] = tf(a1v.z); As[BUF][ak0+3][ar1] = tf(a1v.w); \
        float4 cb0, cb1; \
        cb0.x = tf(b0v.x); cb0.y = tf(b0v.y); cb0.z = tf(b0v.z); cb0.w = tf(b0v.w); \
        cb1.x = tf(b1v.x); cb1.y = tf(b1v.y); cb1.z = tf(b1v.z); cb1.w = tf(b1v.w); \
        *(float4*)&Bs[BUF][bk0][bc0] = cb0; \
        *(float4*)&Bs[BUF][bk1][bc0] = cb1; \
    } while (0)

    TF32_DECL_FRAG();

    LOAD_REGS(kbase);
    STORE_SMEM(0);
    __syncthreads();

    for (int kt = 0; kt < nslabs; kt++) {
        int cur = kt & 1;
        if (kt + 1 < nslabs) LOAD_REGS(kbase + (kt + 1) * TK);
        TF32_COMPUTE(cur);
        if (kt + 1 < nslabs) { STORE_SMEM(cur ^ 1); __syncthreads(); }
    }

    #pragma unroll
    for (int mf = 0; mf < 4; mf++) {
        #pragma unroll
        for (int nf = 0; nf < 4; nf++) {
            long long r0 = m0 + mw + mf * 16 + lm;
            long long cc = c0 + nw + nf * 8 + lk * 2;
            float2 v0 = { acc[mf][nf][0], acc[mf][nf][1] };
            float2 v1 = { acc[mf][nf][2], acc[mf][nf][3] };
            *(float2*)&C[r0 * HH + cc]       = v0;
            *(float2*)&C[(r0 + 8) * HH + cc] = v1;
        }
    }
#undef LOAD_REGS
#undef STORE_SMEM
}

// -------- rowk = Gk.p ; rowv = Gv.q + c  (warp per row) --------------------
__global__ void growdot_kernel(const float* __restrict__ seq) {
    int r = blockIdx.x * 8 + (threadIdx.x >> 5);
    int lane = threadIdx.x & 31;
    int which = blockIdx.y;
    const int* gidx = which ? g_vidx : g_kidx;
    const float* vec = which ? g_q : g_p;
    const float* row = seq + ((long long)(r >> 7) * SS + gidx[r]) * HH;
    float s = 0.f;
    #pragma unroll 4
    for (int cdx = lane; cdx < HH; cdx += 32) s = fmaf(row[cdx], vec[cdx], s);
    #pragma unroll
    for (int o = 16; o; o >>= 1) s += __shfl_xor_sync(0xffffffffu, s, o);
    if (lane == 0) {
        if (which) g_rowv[r] = s + g_c[0];
        else       g_rowk[r] = s;
    }
}

// -- biaffine tf32: biaf4[s][b,i,j] = (uA+uB)[b,i,ks] . Gv_seq[b,j,ks] ------
__global__ __launch_bounds__(256)
void biaf_splitk(const float* __restrict__ seq) {
    __shared__ __align__(16) float As[2][TK][136];
    __shared__ __align__(16) float Bs[2][TK][136];
    __shared__ long long vrowbase[128];
    const int nslabs = 12;
    int b = blockIdx.y;
    int split = blockIdx.x;
    int kbase = split * nslabs * TK;
    int tid = threadIdx.x;

    const float* A0 = g_uA + (long long)b * MC * HH;
    const float* A1 = g_uB + (long long)b * MC * HH;

    if (tid < 128)
        vrowbase[tid] = ((long long)b * SS + g_vidx[b * MC + tid]) * HH;
    __syncthreads();

    int ar0 = tid >> 2, ak = (tid & 3) * 4, ar1 = ar0 + 64;
    long long vb0 = vrowbase[ar0];
    long long vb1 = vrowbase[ar1];

    float4 a0v, a1v, b0v, b1v;
#define LOAD(K0) do { \
        float4 x0 = *(const float4*)(A0 + (long long)ar0 * HH + (K0) + ak); \
        float4 x1 = *(const float4*)(A1 + (long long)ar0 * HH + (K0) + ak); \
        a0v.x = x0.x + x1.x; a0v.y = x0.y + x1.y; a0v.z = x0.z + x1.z; a0v.w = x0.w + x1.w; \
        x0 = *(const float4*)(A0 + (long long)ar1 * HH + (K0) + ak); \
        x1 = *(const float4*)(A1 + (long long)ar1 * HH + (K0) + ak); \
        a1v.x = x0.x + x1.x; a1v.y = x0.y + x1.y; a1v.z = x0.z + x1.z; a1v.w = x0.w + x1.w; \
        b0v = *(const float4*)(seq + vb0 + (K0) + ak); \
        b1v = *(const float4*)(seq + vb1 + (K0) + ak); \
    } while (0)
#define STORE(BUF) do { \
        As[BUF][ak+0][ar0] = tf(a0v.x); As[BUF][ak+1][ar0] = tf(a0v.y); \
        As[BUF][ak+2][ar0] = tf(a0v.z); As[BUF][ak+3][ar0] = tf(a0v.w); \
        As[BUF][ak+0][ar1] = tf(a1v.x); As[BUF][ak+1][ar1] = tf(a1v.y); \
        As[BUF][ak+2][ar1] = tf(a1v.z); As[BUF][ak+3][ar1] = tf(a1v.w); \
        Bs[BUF][ak+0][ar0] = tf(b0v.x); Bs[BUF][ak+1][ar0] = tf(b0v.y); \
        Bs[BUF][ak+2][ar0] = tf(b0v.z); Bs[BUF][ak+3][ar0] = tf(b0v.w); \
        Bs[BUF][ak+0][ar1] = tf(b1v.x); Bs[BUF][ak+1][ar1] = tf(b1v.y); \
        Bs[BUF][ak+2][ar1] = tf(b1v.z); Bs[BUF][ak+3][ar1] = tf(b1v.w); \
    } while (0)

    TF32_DECL_FRAG();

    LOAD(kbase); STORE(0); __syncthreads();
    for (int kt = 0; kt < nslabs; kt++) {
        int cur = kt & 1;
        if (kt + 1 < nslabs) LOAD(kbase + (kt + 1) * TK);
        TF32_COMPUTE(cur);
        if (kt + 1 < nslabs) { STORE(cur ^ 1); __syncthreads(); }
    }

    float* dst = g_biaf4[split] + (long long)b * (MC * MC);
    #pragma unroll
    for (int mf = 0; mf < 4; mf++)
        #pragma unroll
        for (int nf = 0; nf < 4; nf++) {
            int r0 = mw + mf * 16 + lm;
            int cc = nw + nf * 8 + lk * 2;
            float2 v0 = { acc[mf][nf][0], acc[mf][nf][1] };
            float2 v1 = { acc[mf][nf][2], acc[mf][nf][3] };
            *(float2*)&dst[r0 * MC + cc]       = v0;
            *(float2*)&dst[(r0 + 8) * MC + cc] = v1;
        }
#undef LOAD
#undef STORE
}

// ----- pair_pre: spatial MLP only (biaf-independent), 4 key rows/thread ----
__global__ __launch_bounds__(128)
void pair_pre(const float* __restrict__ Ws1, const float* __restrict__ bs1) {
    __shared__ float sW1[8 * 64], sb1[64];
    __shared__ float sW2f[64 * 16], sb2f[16];
    __shared__ float kb[4][4];

    int b = blockIdx.y;
    int i0 = blockIdx.x * 4;
    int j = threadIdx.x;

    for (int t = j; t < 512;  t += 128) sW1[t] = Ws1[t];
    for (int t = j; t < 1024; t += 128) sW2f[t] = g_W2f[t];
    if (j < 64) sb1[j] = bs1[j];
    if (j < 16) sb2f[j] = g_b2f[j];
    if (j < 16) kb[j >> 2][j & 3] = g_kbox[(b * MC + i0 + (j >> 2)) * 4 + (j & 3)];
    __syncthreads();

    float vx1 = g_vbox[(b * MC + j) * 4 + 0];
    float vy1 = g_vbox[(b * MC + j) * 4 + 1];
    float vx2 = g_vbox[(b * MC + j) * 4 + 2];
    float vy2 = g_vbox[(b * MC + j) * 4 + 3];
    float vcx = (vx1 + vx2) * 0.5f, vcy = (vy1 + vy2) * 0.5f;
    float vh = vy2 - vy1, vw = vx2 - vx1;

    float sfa[4][8];
    #pragma unroll
    for (int s = 0; s < 4; s++) {
        float kx1 = kb[s][0], ky1 = kb[s][1], kx2 = kb[s][2], ky2 = kb[s][3];
        float kcx = (kx1 + kx2) * 0.5f, kcy = (ky1 + ky2) * 0.5f;
        float dx = vcx - kcx, dy = vcy - kcy;
        float dist  = sqrtf(dx * dx + dy * dy + EPSF);
        float angle = atan2f(dy, dx);
        float kh = ky2 - ky1, kw = kx2 - kx1;
        float h_ov = fmaxf(fminf(ky2, vy2) - fmaxf(ky1, vy1), 0.0f);
        float h_align = h_ov / (fminf(kh, vh) + EPSF);
        float v_ov = fmaxf(fminf(kx2, vx2) - fmaxf(kx1, vx1), 0.0f);
        float v_align = v_ov / (fminf(kw, vw) + EPSF);
        float area_ratio   = (vh * vw) / (kh * kw + EPSF);
        float aspect_ratio = (vw / (vh + EPSF)) / (kw / (kh + EPSF));
        sfa[s][0] = dx; sfa[s][1] = dy; sfa[s][2] = dist; sfa[s][3] = angle;
        sfa[s][4] = h_align; sfa[s][5] = v_align;
        sfa[s][6] = area_ratio; sfa[s][7] = aspect_ratio;
    }

    float f1[4][16];
    #pragma unroll
    for (int t = 0; t < 16; t++) {
        float bb = sb2f[t];
        #pragma unroll
        for (int s = 0; s < 4; s++) f1[s][t] = bb;
    }

    for (int u = 0; u < 64; u++) {
        float h[4];
        float hb = sb1[u];
        #pragma unroll
        for (int s = 0; s < 4; s++) h[s] = hb;
        #pragma unroll
        for (int f = 0; f < 8; f++) {
            float w = sW1[f * 64 + u];
            #pragma unroll
            for (int s = 0; s < 4; s++) h[s] = fmaf(sfa[s][f], w, h[s]);
        }
        #pragma unroll
        for (int s = 0; s < 4; s++) h[s] = fmaxf(h[s], 0.0f);
        #pragma unroll
        for (int t = 0; t < 16; t++) {
            float w2 = sW2f[u * 16 + t];
            #pragma unroll
            for (int s = 0; s < 4; s++) f1[s][t] = fmaf(h[s], w2, f1[s][t]);
        }
    }

    #pragma unroll
    for (int s = 0; s < 4; s++) {
        long long bidx = (long long)b * (MC * MC) + (i0 + s) * MC + j;
        float* dst = g_f1pre + bidx * 16;
        *(float4*)(dst)      = *(float4*)&f1[s][0];
        *(float4*)(dst + 4)  = *(float4*)&f1[s][4];
        *(float4*)(dst + 8)  = *(float4*)&f1[s][8];
        *(float4*)(dst + 12) = *(float4*)&f1[s][12];
    }
}

// ----- pair_final: combine biaffine + spatial partial, 2 rows/block -------
__global__ __launch_bounds__(256)
void pair_final(float* __restrict__ out,
                const float* __restrict__ Wf1,
                const float* __restrict__ Wf2, const float* __restrict__ bf2,
                const float* __restrict__ bbilp) {
    __shared__ float sF0[16], sF2[16];
    __shared__ float sbf2, sbil;
    __shared__ float srowk[2];

    int t = threadIdx.x;
    int b = blockIdx.y;
    int i0 = blockIdx.x * 2;
    int i = i0 + (t >> 7);
    int j = t & 127;

    if (t < 16) { sF0[t] = Wf1[t]; sF2[t] = Wf2[t]; }
    if (t == 0) { sbf2 = bf2[0]; sbil = bbilp[0]; }
    if (t < 2)  srowk[t] = g_rowk[b * MC + i0 + t];
    __syncthreads();

    long long bidx = (long long)b * (MC * MC) + i * MC + j;
    float biafv = srowk[t >> 7] + g_rowv[b * MC + j] + sbil
                + g_biaf4[0][bidx] + g_biaf4[1][bidx]
                + g_biaf4[2][bidx] + g_biaf4[3][bidx];

    const float* src = g_f1pre + bidx * 16;
    float4 f0 = *(const float4*)(src);
    float4 f1 = *(const float4*)(src + 4);
    float4 f2 = *(const float4*)(src + 8);
    float4 f3 = *(const float4*)(src + 12);
    float fv[16] = { f0.x, f0.y, f0.z, f0.w, f1.x, f1.y, f1.z, f1.w,
                     f2.x, f2.y, f2.z, f2.w, f3.x, f3.y, f3.z, f3.w };

    float score = sbf2;
    #pragma unroll
    for (int k = 0; k < 16; k++)
        score = fmaf(fmaxf(fmaf(biafv, sF0[k], fv[k]), 0.0f), sF2[k], score);

    out[bidx] = score;
}

// ---------------- launch ----------------
extern "C" void kernel_launch(void* const* d_in, const int* in_sizes, int n_in,
                              void* d_out, int out_size) {
    (void)in_sizes; (void)n_in; (void)out_size;
    const float* seq    = (const float*)d_in[0];
    const float* logits = (const float*)d_in[1];
    const float* bboxes = (const float*)d_in[2];
    const int*   mask   = (const int*)  d_in[3];
    const float* Wk  = (const float*)d_in[4];
    const float* bk  = (const float*)d_in[5];
    const float* Wv  = (const float*)d_in[6];
    const float* bv  = (const float*)d_in[7];
    const float* Wbil= (const float*)d_in[8];
    const float* bbil= (const float*)d_in[9];
    const float* Ws1 = (const float*)d_in[10];
    const float* bs1 = (const float*)d_in[11];
    const float* Ws2 = (const float*)d_in[12];
    const float* bs2 = (const float*)d_in[13];
    const float* Wf1 = (const float*)d_in[14];
    const float* bf1 = (const float*)d_in[15];
    const float* Wf2 = (const float*)d_in[16];
    const float* bf2 = (const float*)d_in[17];
    float* out = (float*)d_out;

    float *pM;
    cudaGetSymbolAddress((void**)&pM, g_M);

    // fork:
    //  s1 = weight chain (memset -> nt -> nn)
    //  s2 = setup chain (setupA -> setupB), then after topk: growdot, pair_pre
    //  s0 = topk, then (after e1) u -> biaf, then (after e4) pair_final
    cudaStream_t s1, s2;
    cudaStreamCreateWithFlags(&s1, cudaStreamNonBlocking);
    cudaStreamCreateWithFlags(&s2, cudaStreamNonBlocking);
    cudaEvent_t e0, e1, e3, e4;
    cudaEventCreateWithFlags(&e0, cudaEventDisableTiming);
    cudaEventCreateWithFlags(&e1, cudaEventDisableTiming);
    cudaEventCreateWithFlags(&e3, cudaEventDisableTiming);
    cudaEventCreateWithFlags(&e4, cudaEventDisableTiming);

    cudaEventRecord(e0, 0);
    cudaStreamWaitEvent(s1, e0, 0);
    cudaStreamWaitEvent(s2, e0, 0);

    // --- weight chain on s1 ---
    cudaMemsetAsync(pM, 0, (size_t)HH * HH * sizeof(float), s1);
    nt_split<<<dim3(HH / 128, HH / 128, 4), 256, 0, s1>>>(Wbil, Wv);
    nn_atomic<<<dim3(HH / 128, HH / 128, 4), 256, 0, s1>>>(Wk, pM);
    cudaEventRecord(e1, s1);

    // --- setup chain on s2 ---
    setupA<<<99, 256, 0, s2>>>(bk, Wbil, bv);
    setupB<<<193, 256, 0, s2>>>(Wv, Wk, bv, Ws2, bs2, Wf1, bf1);

    // --- topk on default stream ---
    topk_kernel<<<dim3(BB, 2), 512>>>(logits, mask, bboxes, out);
    cudaEventRecord(e3, 0);

    // --- s2 continues after topk: growdot + spatial pair MLP ---
    cudaStreamWaitEvent(s2, e3, 0);
    growdot_kernel<<<dim3((BB * MC) / 8, 2), 256, 0, s2>>>(seq);
    pair_pre<<<dim3(MC / 4, BB), 128, 0, s2>>>(Ws1, bs1);
    cudaEventRecord(e4, s2);

    // --- s0 tail: u -> biaf -> pair_final ---
    cudaStreamWaitEvent(0, e1, 0);
    u_gemm_tf32<<<dim3(HH / 128, (BB * MC) / 128, 2), 256>>>(seq, pM);
    biaf_splitk<<<dim3(4, BB), 256>>>(seq);
    cudaStreamWaitEvent(0, e4, 0);
    pair_final<<<dim3(MC / 2, BB), 256>>>(out, Wf1, Wf2, bf2, bbil);

    cudaEventDestroy(e0);
    cudaEventDestroy(e1);
    cudaEventDestroy(e3);
    cudaEventDestroy(e4);
    cudaStreamDestroy(s1);
    cudaStreamDestroy(s2);
}